// round 8
// baseline (speedup 1.0000x reference)
#include <cuda_runtime.h>
#include <cuda_bf16.h>
#include <cstdint>
#include <cstddef>

#define BATCH 32
#define CH    512
#define NPIX  1024
#define NG    32
#define CPG   16
#define EPS   1e-6f

// ---------------------------------------------------------------------------
// Scratch: activations single bf16 plane; weights split hi/lo.
// ---------------------------------------------------------------------------
#define SZ_CN ((size_t)BATCH * NPIX * CH)
#define SZ_NN ((size_t)BATCH * NPIX * NPIX)

__device__ __nv_bfloat16 g_Hh[SZ_CN];     // H^T [b][n][c]
__device__ __nv_bfloat16 g_Qh[SZ_CN];     // Q   [b][n][co]
__device__ __nv_bfloat16 g_Kh[SZ_CN];     // K   [b][n][co]
__device__ __nv_bfloat16 g_Vh[SZ_CN];     // V   [b][co][n]
__device__ float         g_S [SZ_NN];     // logits fp32
__device__ __nv_bfloat16 g_Sp[SZ_NN];     // probs bf16
__device__ __nv_bfloat16 g_Oh[SZ_CN];     // O^T [b][q][co]
__device__ __nv_bfloat16 g_Wh[4 * (size_t)CH * CH], g_Wl[4 * (size_t)CH * CH];

// ---------------------------------------------------------------------------
// Helpers
// ---------------------------------------------------------------------------
__device__ __forceinline__ uint32_t smem_u32(const void* p) {
    return (uint32_t)__cvta_generic_to_shared(p);
}
__device__ __forceinline__ void ldsm4(uint32_t r[4], uint32_t a) {
    asm volatile("ldmatrix.sync.aligned.m8n8.x4.shared.b16 {%0,%1,%2,%3}, [%4];"
        : "=r"(r[0]), "=r"(r[1]), "=r"(r[2]), "=r"(r[3]) : "r"(a));
}
__device__ __forceinline__ void mma16816(float d[4], const uint32_t a[4], const uint32_t* b) {
    asm volatile(
        "mma.sync.aligned.m16n8k16.row.col.f32.bf16.bf16.f32 "
        "{%0,%1,%2,%3}, {%4,%5,%6,%7}, {%8,%9}, {%0,%1,%2,%3};"
        : "+f"(d[0]), "+f"(d[1]), "+f"(d[2]), "+f"(d[3])
        : "r"(a[0]), "r"(a[1]), "r"(a[2]), "r"(a[3]), "r"(b[0]), "r"(b[1]));
}
__device__ __forceinline__ void cp16(uint32_t s, const void* g) {
    asm volatile("cp.async.cg.shared.global [%0], [%1], 16;" :: "r"(s), "l"(g));
}
__device__ __forceinline__ void cp_commit() {
    asm volatile("cp.async.commit_group;" ::: "memory");
}
template<int n>
__device__ __forceinline__ void cp_wait() {
    asm volatile("cp.async.wait_group %0;" :: "n"(n) : "memory");
}
__device__ __forceinline__ void splitf(float x, __nv_bfloat16& h, __nv_bfloat16& l) {
    h = __float2bfloat16(x);
    l = __float2bfloat16(x - __bfloat162float(h));
}

// ---------------------------------------------------------------------------
// Weight pack: 4 x [512][512] fp32 -> hi/lo planes
// ---------------------------------------------------------------------------
__global__ __launch_bounds__(256) void pack_w_kernel(
    const float* __restrict__ a0, const float* __restrict__ a1,
    const float* __restrict__ a2, const float* __restrict__ a3,
    __nv_bfloat16* __restrict__ oh, __nv_bfloat16* __restrict__ ol)
{
    int i = blockIdx.x * 256 + threadIdx.x;
    int t = i >> 18;
    int j = i & 262143;
    const float* src = (t == 0) ? a0 : (t == 1) ? a1 : (t == 2) ? a2 : a3;
    __nv_bfloat16 h, l;
    splitf(src[j], h, l);
    oh[i] = h; ol[i] = l;
}

// ---------------------------------------------------------------------------
// GroupNorm -> transposed single bf16 plane H^T[b][n][c]
// ---------------------------------------------------------------------------
__global__ __launch_bounds__(256) void gn_kernel(
    const float* __restrict__ x, const float* __restrict__ w,
    const float* __restrict__ b, __nv_bfloat16* __restrict__ Hh)
{
    const int bg = blockIdx.x;
    const int batch = bg >> 5;
    const int g = bg & 31;
    const int tid = threadIdx.x;
    const float* xp = x + ((size_t)batch * CH + (size_t)g * CPG) * NPIX;

    float s = 0.f, ss = 0.f;
    for (int i = tid; i < CPG * NPIX; i += 256) {
        float v = xp[i];
        s += v; ss += v * v;
    }
    __shared__ float sh_s[256], sh_ss[256];
    sh_s[tid] = s; sh_ss[tid] = ss;
    __syncthreads();
    for (int st = 128; st > 0; st >>= 1) {
        if (tid < st) { sh_s[tid] += sh_s[tid + st]; sh_ss[tid] += sh_ss[tid + st]; }
        __syncthreads();
    }
    const float mean = sh_s[0] * (1.0f / (CPG * NPIX));
    const float var  = sh_ss[0] * (1.0f / (CPG * NPIX)) - mean * mean;
    const float inv  = rsqrtf(var + EPS);

    __shared__ float st[512][17];

    for (int half = 0; half < 2; half++) {
        for (int i = tid; i < CPG * 512; i += 256) {
            int c16 = i >> 9;
            int nl  = i & 511;
            int c   = g * CPG + c16;
            float v = (xp[c16 * NPIX + half * 512 + nl] - mean) * inv;
            st[nl][c16] = v * w[c] + b[c];
        }
        __syncthreads();
        size_t dst = ((size_t)batch * NPIX + half * 512) * CH + g * CPG;
        for (int i = tid; i < CPG * 512; i += 256) {
            int nl = i >> 4;
            int c16 = i & 15;
            Hh[dst + (size_t)nl * CH + c16] = __float2bfloat16(st[nl][c16]);
        }
        __syncthreads();
    }
}

// ---------------------------------------------------------------------------
// Row softmax over fp32 logits -> single bf16 prob plane
// ---------------------------------------------------------------------------
__global__ __launch_bounds__(256) void softmax_kernel(
    const float* __restrict__ S, __nv_bfloat16* __restrict__ Sp)
{
    const float* p = S + (size_t)blockIdx.x * NPIX;
    __nv_bfloat16* po = Sp + (size_t)blockIdx.x * NPIX;
    const int t = threadIdx.x;

    float v[4];
    float mx = -1e30f;
    #pragma unroll
    for (int i = 0; i < 4; i++) { v[i] = p[t + i * 256]; mx = fmaxf(mx, v[i]); }
    __shared__ float red[256];
    red[t] = mx;
    __syncthreads();
    for (int st = 128; st > 0; st >>= 1) {
        if (t < st) red[t] = fmaxf(red[t], red[t + st]);
        __syncthreads();
    }
    mx = red[0];
    __syncthreads();
    float sum = 0.f;
    #pragma unroll
    for (int i = 0; i < 4; i++) { v[i] = __expf(v[i] - mx); sum += v[i]; }
    red[t] = sum;
    __syncthreads();
    for (int st = 128; st > 0; st >>= 1) {
        if (t < st) red[t] += red[t + st];
        __syncthreads();
    }
    const float inv = 1.0f / red[0];
    #pragma unroll
    for (int i = 0; i < 4; i++) po[t + i * 256] = __float2bfloat16(v[i] * inv);
}

// ---------------------------------------------------------------------------
// Tensor-core GEMM:
//   C[m][n] = alpha * sum_k A(m,k)*B(n,k) + bias_row[m] + bias_col[n] (+resid)
// PA/PB planes per operand. Terms: a0*b0 (+a0*b1 if PB==2) (+a1*b0 if PA==2).
// Block 128x128, K-chunk 64 (fewer barrier-alignment stalls), 2-stage
// cp.async double buffer, 8 warps, 2 CTAs/SM.
// ---------------------------------------------------------------------------
#define KCHUNK   64
#define ROWS_H   72               // 64 halves + 8 pad (144B stride, 16B aligned)
#define TILE_B   (128 * ROWS_H * 2)   // 18432 B per plane

template<int PA, int PB, bool OUTF32>
__global__ __launch_bounds__(256, 2) void mma_gemm(
    const __nv_bfloat16* __restrict__ Ah, const __nv_bfloat16* __restrict__ Al,
    const __nv_bfloat16* __restrict__ Bh, const __nv_bfloat16* __restrict__ Bl,
    void* __restrict__ C0,
    int N, int K,
    size_t sA, size_t sB, size_t sC,
    const float* __restrict__ bias_row, const float* __restrict__ bias_col,
    const float* __restrict__ resid, size_t sR, float alpha)
{
    constexpr int NTILES = PA + PB;
    constexpr int STAGE = NTILES * TILE_B;

    extern __shared__ __align__(1024) char smem[];
    const uint32_t sb = smem_u32(smem);

    const int tid  = threadIdx.x;
    const int lane = tid & 31;
    const int warp = tid >> 5;
    const int wm = (warp >> 2) * 64;
    const int wn = (warp & 3) * 32;
    const int m0 = blockIdx.y * 128;
    const int n0 = blockIdx.x * 128;
    const int bz = blockIdx.z;

    const __nv_bfloat16* gA[2];
    gA[0] = Ah + (size_t)bz * sA;
    gA[1] = (PA == 2) ? (Al + (size_t)bz * sA) : nullptr;
    const __nv_bfloat16* gB[2];
    gB[0] = Bh + (size_t)bz * sB;
    gB[1] = (PB == 2) ? (Bl + (size_t)bz * sB) : nullptr;

    auto issue = [&](int c) {
        const int stg = c & 1;
        const int k0 = c * KCHUNK;
        const uint32_t sbase = sb + stg * STAGE;
        #pragma unroll
        for (int i = 0; i < 4; i++) {
            const int idx = tid + i * 256;       // 0..1023
            const int r = idx >> 3;              // 0..127
            const int seg = idx & 7;             // 0..7 (16B each = 8 halves)
            const uint32_t soff = r * (ROWS_H * 2) + seg * 16;
            const size_t ga = (size_t)(m0 + r) * K + k0 + seg * 8;
            const size_t gb = (size_t)(n0 + r) * K + k0 + seg * 8;
            #pragma unroll
            for (int t = 0; t < PA; t++)
                cp16(sbase + t * TILE_B + soff, gA[t] + ga);
            #pragma unroll
            for (int t = 0; t < PB; t++)
                cp16(sbase + (PA + t) * TILE_B + soff, gB[t] + gb);
        }
        cp_commit();
    };

    float acc[4][4][4] = {};

    const int nc = K / KCHUNK;
    issue(0);

    const int ar = lane & 15;
    const int ac0 = (lane >> 4) * 8;
    const int br = (lane & 7) + (lane >> 4) * 8;
    const int bc0 = ((lane >> 3) & 1) * 8;

    for (int c = 0; c < nc; c++) {
        cp_wait<0>();
        __syncthreads();
        if (c + 1 < nc) issue(c + 1);

        const int stg = c & 1;
        const __nv_bfloat16* TA0 = (const __nv_bfloat16*)(smem + stg * STAGE);
        const __nv_bfloat16* TA1 = (const __nv_bfloat16*)(smem + stg * STAGE + TILE_B);
        const __nv_bfloat16* TB0 = (const __nv_bfloat16*)(smem + stg * STAGE + PA * TILE_B);
        const __nv_bfloat16* TB1 = (const __nv_bfloat16*)(smem + stg * STAGE + (PA + 1) * TILE_B);

        #pragma unroll
        for (int kk = 0; kk < KCHUNK; kk += 16) {
            uint32_t a0[4][4], a1[4][4];
            uint32_t b0[8], b1[8];
            #pragma unroll
            for (int i = 0; i < 4; i++) {
                ldsm4(a0[i], smem_u32(TA0 + (wm + i * 16 + ar) * ROWS_H + kk + ac0));
                if (PA == 2)
                    ldsm4(a1[i], smem_u32(TA1 + (wm + i * 16 + ar) * ROWS_H + kk + ac0));
            }
            #pragma unroll
            for (int jj = 0; jj < 2; jj++) {
                ldsm4(&b0[4 * jj], smem_u32(TB0 + (wn + jj * 16 + br) * ROWS_H + kk + bc0));
                if (PB == 2)
                    ldsm4(&b1[4 * jj], smem_u32(TB1 + (wn + jj * 16 + br) * ROWS_H + kk + bc0));
            }
            #pragma unroll
            for (int i = 0; i < 4; i++)
                #pragma unroll
                for (int j = 0; j < 4; j++)
                    mma16816(acc[i][j], a0[i], &b0[2 * j]);
            if (PB == 2) {
                #pragma unroll
                for (int i = 0; i < 4; i++)
                    #pragma unroll
                    for (int j = 0; j < 4; j++)
                        mma16816(acc[i][j], a0[i], &b1[2 * j]);
            }
            if (PA == 2) {
                #pragma unroll
                for (int i = 0; i < 4; i++)
                    #pragma unroll
                    for (int j = 0; j < 4; j++)
                        mma16816(acc[i][j], a1[i], &b0[2 * j]);
            }
        }
    }

    // ---- epilogue ----
    const int g  = lane >> 2;
    const int t2 = (lane & 3) * 2;
    #pragma unroll
    for (int i = 0; i < 4; i++) {
        const int m = m0 + wm + i * 16 + g;
        const float br0 = bias_row ? bias_row[m] : 0.f;
        const float br1 = bias_row ? bias_row[m + 8] : 0.f;
        #pragma unroll
        for (int j = 0; j < 4; j++) {
            const int n = n0 + wn + j * 8 + t2;
            float bc0v = 0.f, bc1v = 0.f;
            if (bias_col) { bc0v = bias_col[n]; bc1v = bias_col[n + 1]; }
            float v0 = acc[i][j][0] * alpha + br0 + bc0v;
            float v1 = acc[i][j][1] * alpha + br0 + bc1v;
            float v2 = acc[i][j][2] * alpha + br1 + bc0v;
            float v3 = acc[i][j][3] * alpha + br1 + bc1v;
            if (resid) {
                const float* rp = resid + (size_t)bz * sR;
                v0 += rp[(size_t)m * N + n];
                v1 += rp[(size_t)m * N + n + 1];
                v2 += rp[(size_t)(m + 8) * N + n];
                v3 += rp[(size_t)(m + 8) * N + n + 1];
            }
            if (OUTF32) {
                float* C = (float*)C0 + (size_t)bz * sC;
                float2 o0; o0.x = v0; o0.y = v1;
                float2 o1; o1.x = v2; o1.y = v3;
                *(float2*)&C[(size_t)m * N + n] = o0;
                *(float2*)&C[(size_t)(m + 8) * N + n] = o1;
            } else {
                __nv_bfloat16* Ch = (__nv_bfloat16*)C0 + (size_t)bz * sC;
                __nv_bfloat162 hh01, hh23;
                hh01.x = __float2bfloat16(v0); hh01.y = __float2bfloat16(v1);
                hh23.x = __float2bfloat16(v2); hh23.y = __float2bfloat16(v3);
                *(__nv_bfloat162*)&Ch[(size_t)m * N + n] = hh01;
                *(__nv_bfloat162*)&Ch[(size_t)(m + 8) * N + n] = hh23;
            }
        }
    }
}

// ---------------------------------------------------------------------------
// Launch
// ---------------------------------------------------------------------------
extern "C" void kernel_launch(void* const* d_in, const int* in_sizes, int n_in,
                              void* d_out, int out_size)
{
    (void)in_sizes; (void)n_in; (void)out_size;
    const float* x    = (const float*)d_in[0];
    const float* gn_w = (const float*)d_in[1];
    const float* gn_b = (const float*)d_in[2];
    const float* wq   = (const float*)d_in[3];
    const float* bq   = (const float*)d_in[4];
    const float* wk   = (const float*)d_in[5];
    const float* bk   = (const float*)d_in[6];
    const float* wv   = (const float*)d_in[7];
    const float* bv   = (const float*)d_in[8];
    const float* wp   = (const float*)d_in[9];
    const float* bp   = (const float*)d_in[10];
    float* out = (float*)d_out;

    __nv_bfloat16 *Hh, *Qh, *Kh, *Vh, *Oh, *Wh, *Wl, *Sp;
    float* S;
    cudaGetSymbolAddress((void**)&Hh, g_Hh);
    cudaGetSymbolAddress((void**)&Qh, g_Qh);
    cudaGetSymbolAddress((void**)&Kh, g_Kh);
    cudaGetSymbolAddress((void**)&Vh, g_Vh);
    cudaGetSymbolAddress((void**)&Oh, g_Oh);
    cudaGetSymbolAddress((void**)&Wh, g_Wh); cudaGetSymbolAddress((void**)&Wl, g_Wl);
    cudaGetSymbolAddress((void**)&S,  g_S);  cudaGetSymbolAddress((void**)&Sp, g_Sp);

    const int SM3 = 2 * 3 * TILE_B;  // 110592 B (3-plane)
    const int SM2 = 2 * 2 * TILE_B;  // 73728 B (2-plane)
    static bool attr_done = false;
    if (!attr_done) {
        cudaFuncSetAttribute((const void*)mma_gemm<1, 2, false>, cudaFuncAttributeMaxDynamicSharedMemorySize, SM3);
        cudaFuncSetAttribute((const void*)mma_gemm<2, 1, false>, cudaFuncAttributeMaxDynamicSharedMemorySize, SM3);
        cudaFuncSetAttribute((const void*)mma_gemm<2, 1, true>,  cudaFuncAttributeMaxDynamicSharedMemorySize, SM3);
        cudaFuncSetAttribute((const void*)mma_gemm<1, 1, true>,  cudaFuncAttributeMaxDynamicSharedMemorySize, SM2);
        cudaFuncSetAttribute((const void*)mma_gemm<1, 1, false>, cudaFuncAttributeMaxDynamicSharedMemorySize, SM2);
        attr_done = true;
    }

    const size_t WSZ = (size_t)CH * CH;
    const size_t sCN = (size_t)CH * NPIX;
    const size_t sNN = (size_t)NPIX * NPIX;
    const float scale = 0.044194173824159223f; // 512^-0.5

    // 0) pack weights into hi/lo planes
    pack_w_kernel<<<4096, 256>>>(wq, wk, wv, wp, Wh, Wl);

    // 1) GroupNorm -> H^T bf16 [b][n][c]
    gn_kernel<<<BATCH * NG, 256>>>(x, gn_w, gn_b, Hh);

    // 2) Q[n][co] = H^T[n][c] . Wq[co][c] + bq  (2-term)
    {
        dim3 grid(CH / 128, NPIX / 128, BATCH);
        mma_gemm<1, 2, false><<<grid, 256, SM3>>>(Hh, nullptr, Wh, Wl, Qh,
            CH, CH, sCN, 0, sCN, nullptr, bq, nullptr, 0, 1.f);
        mma_gemm<1, 2, false><<<grid, 256, SM3>>>(Hh, nullptr, Wh + WSZ, Wl + WSZ, Kh,
            CH, CH, sCN, 0, sCN, nullptr, bk, nullptr, 0, 1.f);
    }
    // 3) V[co][n] = Wv[co][c] . H^T[n][c] + bv  (2-term)
    {
        dim3 grid(NPIX / 128, CH / 128, BATCH);
        mma_gemm<2, 1, false><<<grid, 256, SM3>>>(Wh + 2 * WSZ, Wl + 2 * WSZ, Hh, nullptr, Vh,
            NPIX, CH, 0, sCN, sCN, bv, nullptr, nullptr, 0, 1.f);
    }
    // 4) S[q][k] = scale * Q[q][c] . K[k][c]  (1-term) fp32
    {
        dim3 grid(NPIX / 128, NPIX / 128, BATCH);
        mma_gemm<1, 1, true><<<grid, 256, SM2>>>(Qh, nullptr, Kh, nullptr, S,
            NPIX, CH, sCN, sCN, sNN, nullptr, nullptr, nullptr, 0, scale);
    }
    // 5) softmax -> bf16 probs
    softmax_kernel<<<BATCH * NPIX, 256>>>(S, Sp);

    // 6) O^T[q][co] = P[q][k] . V[co][k]  (1-term)
    {
        dim3 grid(CH / 128, NPIX / 128, BATCH);
        mma_gemm<1, 1, false><<<grid, 256, SM2>>>(Sp, nullptr, Vh, nullptr, Oh,
            CH, NPIX, sNN, sCN, sCN, nullptr, nullptr, nullptr, 0, 1.f);
    }
    // 7) out[co][n] = Wp[co][c] . O^T[n][c] + bp + x  (2-term)
    {
        dim3 grid(NPIX / 128, CH / 128, BATCH);
        mma_gemm<2, 1, true><<<grid, 256, SM3>>>(Wh + 3 * WSZ, Wl + 3 * WSZ, Oh, nullptr, out,
            NPIX, CH, 0, sCN, sCN, bp, nullptr, x, sCN, 1.f);
    }
}

// round 9
// speedup vs baseline: 1.4871x; 1.4871x over previous
#include <cuda_runtime.h>
#include <cuda_bf16.h>
#include <cstdint>
#include <cstddef>

#define BATCH 32
#define CH    512
#define NPIX  1024
#define NG    32
#define CPG   16
#define EPS   1e-6f

#define SZ_CN ((size_t)BATCH * NPIX * CH)
#define SZ_NN ((size_t)BATCH * NPIX * NPIX)
#define WSZ   ((size_t)CH * CH)

// ---------------------------------------------------------------------------
// Scratch
// ---------------------------------------------------------------------------
__device__ __nv_bfloat16 g_Hn[SZ_CN];    // H [b][n][c]   (c contiguous)
__device__ __nv_bfloat16 g_Hc[SZ_CN];    // H [b][c][n]   (n contiguous)
__device__ __nv_bfloat16 g_U [SZ_CN];    // U = H.T^T [b][n][c1]
__device__ __nv_bfloat16 g_G [SZ_CN];    // G = P.H  [b][q][c]
__device__ float         g_S [SZ_NN];    // logits fp32
__device__ __nv_bfloat16 g_P [SZ_NN];    // probs bf16
// weights
__device__ __nv_bfloat16 g_WqTh[WSZ], g_WqTl[WSZ];  // Wq^T [c][co] hi/lo
__device__ __nv_bfloat16 g_WkTh[WSZ], g_WkTl[WSZ];
__device__ __nv_bfloat16 g_WvTh[WSZ], g_WvTl[WSZ];
__device__ __nv_bfloat16 g_Wph [WSZ], g_Wpl [WSZ];  // Wp natural [co][c]
__device__ float g_Traw [WSZ];
__device__ float g_W2raw[WSZ];
__device__ __nv_bfloat16 g_Th[WSZ], g_Tl[WSZ];      // T = scale*Wq^T.Wk split
__device__ __nv_bfloat16 g_W2h[WSZ], g_W2l[WSZ];    // W2 = Wp.Wv split
__device__ float g_vv[2 * CH + 1];                  // v1, v2, bq.bk
__device__ float g_cvec[CH];                        // Wp.bv + bp
__device__ float g_rq[(size_t)BATCH * NPIX];
__device__ float g_rk[(size_t)BATCH * NPIX];

// ---------------------------------------------------------------------------
// Helpers
// ---------------------------------------------------------------------------
__device__ __forceinline__ uint32_t smem_u32(const void* p) {
    return (uint32_t)__cvta_generic_to_shared(p);
}
__device__ __forceinline__ void ldsm4(uint32_t r[4], uint32_t a) {
    asm volatile("ldmatrix.sync.aligned.m8n8.x4.shared.b16 {%0,%1,%2,%3}, [%4];"
        : "=r"(r[0]), "=r"(r[1]), "=r"(r[2]), "=r"(r[3]) : "r"(a));
}
__device__ __forceinline__ void mma16816(float d[4], const uint32_t a[4], const uint32_t* b) {
    asm volatile(
        "mma.sync.aligned.m16n8k16.row.col.f32.bf16.bf16.f32 "
        "{%0,%1,%2,%3}, {%4,%5,%6,%7}, {%8,%9}, {%0,%1,%2,%3};"
        : "+f"(d[0]), "+f"(d[1]), "+f"(d[2]), "+f"(d[3])
        : "r"(a[0]), "r"(a[1]), "r"(a[2]), "r"(a[3]), "r"(b[0]), "r"(b[1]));
}
__device__ __forceinline__ void cp16(uint32_t s, const void* g) {
    asm volatile("cp.async.cg.shared.global [%0], [%1], 16;" :: "r"(s), "l"(g));
}
__device__ __forceinline__ void cp_commit() {
    asm volatile("cp.async.commit_group;" ::: "memory");
}
template<int n>
__device__ __forceinline__ void cp_wait() {
    asm volatile("cp.async.wait_group %0;" :: "n"(n) : "memory");
}
__device__ __forceinline__ void splitf(float x, __nv_bfloat16& h, __nv_bfloat16& l) {
    h = __float2bfloat16(x);
    l = __float2bfloat16(x - __bfloat162float(h));
}

// ---------------------------------------------------------------------------
// Pack: Wq,Wk,Wv transposed hi/lo; Wp natural hi/lo
// ---------------------------------------------------------------------------
__global__ __launch_bounds__(256) void pack_weights_kernel(
    const float* __restrict__ wq, const float* __restrict__ wk,
    const float* __restrict__ wv, const float* __restrict__ wp)
{
    int i = blockIdx.x * 256 + threadIdx.x;     // 0 .. 4*WSZ-1
    int t = i >> 18;
    int j = i & (int)(WSZ - 1);
    __nv_bfloat16 h, l;
    if (t < 3) {
        int c = j >> 9, co = j & 511;           // out[c][co] = W[co][c]
        const float* src = (t == 0) ? wq : (t == 1) ? wk : wv;
        splitf(src[co * CH + c], h, l);
        if (t == 0) { g_WqTh[j] = h; g_WqTl[j] = l; }
        else if (t == 1) { g_WkTh[j] = h; g_WkTl[j] = l; }
        else { g_WvTh[j] = h; g_WvTl[j] = l; }
    } else {
        splitf(wp[j], h, l);
        g_Wph[j] = h; g_Wpl[j] = l;
    }
}

// split fp32 T/W2 -> bf16 hi/lo planes
__global__ __launch_bounds__(256) void split_tw_kernel()
{
    int i = blockIdx.x * 256 + threadIdx.x;     // 0 .. 2*WSZ-1
    __nv_bfloat16 h, l;
    if (i < (int)WSZ) {
        splitf(g_Traw[i], h, l);
        g_Th[i] = h; g_Tl[i] = l;
    } else {
        int j = i - WSZ;
        splitf(g_W2raw[j], h, l);
        g_W2h[j] = h; g_W2l[j] = l;
    }
}

// v1 = Wk^T.bq, v2 = Wq^T.bk, vv[1024] = bq.bk ; cvec = Wp.bv + bp
__global__ __launch_bounds__(256) void vecs_kernel(
    const float* __restrict__ wq, const float* __restrict__ wk,
    const float* __restrict__ bq, const float* __restrict__ bk,
    const float* __restrict__ wp, const float* __restrict__ bv,
    const float* __restrict__ bp)
{
    int gid = blockIdx.x * 256 + threadIdx.x;   // grid 6*256 = 1536
    if (gid < CH) {
        float s = 0.f;
        for (int co = 0; co < CH; co++) s += wk[co * CH + gid] * bq[co];
        g_vv[gid] = s;
    } else if (gid < 2 * CH) {
        int c = gid - CH;
        float s = 0.f;
        for (int co = 0; co < CH; co++) s += wq[co * CH + c] * bk[co];
        g_vv[gid] = s;
        if (c == 0) {
            float sc = 0.f;
            for (int co = 0; co < CH; co++) sc += bq[co] * bk[co];
            g_vv[2 * CH] = sc;
        }
    } else if (gid < 3 * CH) {
        int co = gid - 2 * CH;
        float s = bp[co];
        for (int cm = 0; cm < CH; cm++) s += wp[co * CH + cm] * bv[cm];
        g_cvec[co] = s;
    }
}

// rq[b][n] = scale*(v2.h + bqbk), rk[b][n] = scale*(v1.h); one warp per row
__global__ __launch_bounds__(256) void rqk_kernel(float scale)
{
    const int row = blockIdx.x * 8 + (threadIdx.x >> 5);   // 0..32767
    const int lane = threadIdx.x & 31;
    const __nv_bfloat16* h = g_Hn + (size_t)row * CH;
    float d1 = 0.f, d2 = 0.f;
    for (int j = 0; j < 16; j++) {
        int c = lane + j * 32;
        float hv = __bfloat162float(h[c]);
        d1 += g_vv[c] * hv;
        d2 += g_vv[CH + c] * hv;
    }
    #pragma unroll
    for (int o = 16; o > 0; o >>= 1) {
        d1 += __shfl_xor_sync(0xFFFFFFFF, d1, o);
        d2 += __shfl_xor_sync(0xFFFFFFFF, d2, o);
    }
    if (lane == 0) {
        g_rq[row] = scale * (d2 + g_vv[2 * CH]);
        g_rk[row] = scale * d1;
    }
}

// ---------------------------------------------------------------------------
// GroupNorm -> both layouts: Hn [b][n][c], Hc [b][c][n]
// ---------------------------------------------------------------------------
__global__ __launch_bounds__(256) void gn_kernel(
    const float* __restrict__ x, const float* __restrict__ w,
    const float* __restrict__ b)
{
    const int bg = blockIdx.x;
    const int batch = bg >> 5;
    const int g = bg & 31;
    const int tid = threadIdx.x;
    const float* xp = x + ((size_t)batch * CH + (size_t)g * CPG) * NPIX;

    float s = 0.f, ss = 0.f;
    for (int i = tid; i < CPG * NPIX; i += 256) {
        float v = xp[i];
        s += v; ss += v * v;
    }
    __shared__ float sh_s[256], sh_ss[256];
    sh_s[tid] = s; sh_ss[tid] = ss;
    __syncthreads();
    for (int st = 128; st > 0; st >>= 1) {
        if (tid < st) { sh_s[tid] += sh_s[tid + st]; sh_ss[tid] += sh_ss[tid + st]; }
        __syncthreads();
    }
    const float mean = sh_s[0] * (1.0f / (CPG * NPIX));
    const float var  = sh_ss[0] * (1.0f / (CPG * NPIX)) - mean * mean;
    const float inv  = rsqrtf(var + EPS);

    __shared__ float st[512][17];

    for (int half = 0; half < 2; half++) {
        for (int i = tid; i < CPG * 512; i += 256) {
            int c16 = i >> 9;
            int nl  = i & 511;
            int c   = g * CPG + c16;
            float v = (xp[c16 * NPIX + half * 512 + nl] - mean) * inv;
            v = v * w[c] + b[c];
            st[nl][c16] = v;
            g_Hc[((size_t)batch * CH + c) * NPIX + half * 512 + nl] = __float2bfloat16(v);
        }
        __syncthreads();
        size_t dst = ((size_t)batch * NPIX + half * 512) * CH + g * CPG;
        for (int i = tid; i < CPG * 512; i += 256) {
            int nl = i >> 4;
            int c16 = i & 15;
            g_Hn[dst + (size_t)nl * CH + c16] = __float2bfloat16(st[nl][c16]);
        }
        __syncthreads();
    }
}

// ---------------------------------------------------------------------------
// Row softmax fp32 -> bf16 probs
// ---------------------------------------------------------------------------
__global__ __launch_bounds__(256) void softmax_kernel(
    const float* __restrict__ S, __nv_bfloat16* __restrict__ Sp)
{
    const float* p = S + (size_t)blockIdx.x * NPIX;
    __nv_bfloat16* po = Sp + (size_t)blockIdx.x * NPIX;
    const int t = threadIdx.x;

    float v[4];
    float mx = -1e30f;
    #pragma unroll
    for (int i = 0; i < 4; i++) { v[i] = p[t + i * 256]; mx = fmaxf(mx, v[i]); }
    __shared__ float red[256];
    red[t] = mx;
    __syncthreads();
    for (int st = 128; st > 0; st >>= 1) {
        if (t < st) red[t] = fmaxf(red[t], red[t + st]);
        __syncthreads();
    }
    mx = red[0];
    __syncthreads();
    float sum = 0.f;
    #pragma unroll
    for (int i = 0; i < 4; i++) { v[i] = __expf(v[i] - mx); sum += v[i]; }
    red[t] = sum;
    __syncthreads();
    for (int st = 128; st > 0; st >>= 1) {
        if (t < st) red[t] += red[t + st];
        __syncthreads();
    }
    const float inv = 1.0f / red[0];
    #pragma unroll
    for (int i = 0; i < 4; i++) po[t + i * 256] = __float2bfloat16(v[i] * inv);
}

// ---------------------------------------------------------------------------
// Tensor-core GEMM (round-7 proven config):
//   C[m][n] = alpha*sum_k A(m,k)B(n,k) + bias_row[m] + bias_col[n] (+resid)
// PA/PB planes; terms a0b0 (+a0b1 if PB==2) (+a1b0 if PA==2).
// bias strides brs/bcs: per-batch offset (0 = shared).
// Block 128x128, k-chunk 32, 2-stage cp.async, 8 warps, 2 CTAs/SM.
// ---------------------------------------------------------------------------
#define TILE_B   10240
#define ROWS_H   40

template<int PA, int PB, bool OUTF32>
__global__ __launch_bounds__(256, 2) void mma_gemm(
    const __nv_bfloat16* __restrict__ Ah, const __nv_bfloat16* __restrict__ Al,
    const __nv_bfloat16* __restrict__ Bh, const __nv_bfloat16* __restrict__ Bl,
    void* __restrict__ C0,
    int N, int K,
    size_t sA, size_t sB, size_t sC,
    const float* __restrict__ bias_row, size_t brs,
    const float* __restrict__ bias_col, size_t bcs,
    const float* __restrict__ resid, size_t sR, float alpha)
{
    constexpr int NTILES = PA + PB;
    constexpr int STAGE = NTILES * TILE_B;

    extern __shared__ __align__(1024) char smem[];
    const uint32_t sb = smem_u32(smem);

    const int tid  = threadIdx.x;
    const int lane = tid & 31;
    const int warp = tid >> 5;
    const int wm = (warp >> 2) * 64;
    const int wn = (warp & 3) * 32;
    const int m0 = blockIdx.y * 128;
    const int n0 = blockIdx.x * 128;
    const int bz = blockIdx.z;

    const __nv_bfloat16* gA[2];
    gA[0] = Ah + (size_t)bz * sA;
    gA[1] = (PA == 2) ? (Al + (size_t)bz * sA) : nullptr;
    const __nv_bfloat16* gB[2];
    gB[0] = Bh + (size_t)bz * sB;
    gB[1] = (PB == 2) ? (Bl + (size_t)bz * sB) : nullptr;

    auto issue = [&](int c) {
        const int stg = c & 1;
        const int k0 = c * 32;
        const uint32_t sbase = sb + stg * STAGE;
        #pragma unroll
        for (int i = 0; i < 2; i++) {
            const int idx = tid + i * 256;
            const int r = idx >> 2;
            const int seg = idx & 3;
            const uint32_t soff = r * (ROWS_H * 2) + seg * 16;
            const size_t ga = (size_t)(m0 + r) * K + k0 + seg * 8;
            const size_t gb = (size_t)(n0 + r) * K + k0 + seg * 8;
            #pragma unroll
            for (int t = 0; t < PA; t++)
                cp16(sbase + t * TILE_B + soff, gA[t] + ga);
            #pragma unroll
            for (int t = 0; t < PB; t++)
                cp16(sbase + (PA + t) * TILE_B + soff, gB[t] + gb);
        }
        cp_commit();
    };

    float acc[4][4][4] = {};

    const int nc = K >> 5;
    issue(0);

    const int ar = lane & 15;
    const int ac0 = (lane >> 4) * 8;
    const int br = (lane & 7) + (lane >> 4) * 8;
    const int bc0 = ((lane >> 3) & 1) * 8;

    for (int c = 0; c < nc; c++) {
        cp_wait<0>();
        __syncthreads();
        if (c + 1 < nc) issue(c + 1);

        const int stg = c & 1;
        const __nv_bfloat16* TA0 = (const __nv_bfloat16*)(smem + stg * STAGE);
        const __nv_bfloat16* TA1 = (const __nv_bfloat16*)(smem + stg * STAGE + TILE_B);
        const __nv_bfloat16* TB0 = (const __nv_bfloat16*)(smem + stg * STAGE + PA * TILE_B);
        const __nv_bfloat16* TB1 = (const __nv_bfloat16*)(smem + stg * STAGE + (PA + 1) * TILE_B);

        #pragma unroll
        for (int kk = 0; kk < 32; kk += 16) {
            uint32_t a0[4][4], a1[4][4];
            uint32_t b0[8], b1[8];
            #pragma unroll
            for (int i = 0; i < 4; i++) {
                ldsm4(a0[i], smem_u32(TA0 + (wm + i * 16 + ar) * ROWS_H + kk + ac0));
                if (PA == 2)
                    ldsm4(a1[i], smem_u32(TA1 + (wm + i * 16 + ar) * ROWS_H + kk + ac0));
            }
            #pragma unroll
            for (int jj = 0; jj < 2; jj++) {
                ldsm4(&b0[4 * jj], smem_u32(TB0 + (wn + jj * 16 + br) * ROWS_H + kk + bc0));
                if (PB == 2)
                    ldsm4(&b1[4 * jj], smem_u32(TB1 + (wn + jj * 16 + br) * ROWS_H + kk + bc0));
            }
            #pragma unroll
            for (int i = 0; i < 4; i++)
                #pragma unroll
                for (int j = 0; j < 4; j++)
                    mma16816(acc[i][j], a0[i], &b0[2 * j]);
            if (PB == 2) {
                #pragma unroll
                for (int i = 0; i < 4; i++)
                    #pragma unroll
                    for (int j = 0; j < 4; j++)
                        mma16816(acc[i][j], a0[i], &b1[2 * j]);
            }
            if (PA == 2) {
                #pragma unroll
                for (int i = 0; i < 4; i++)
                    #pragma unroll
                    for (int j = 0; j < 4; j++)
                        mma16816(acc[i][j], a1[i], &b0[2 * j]);
            }
        }
    }

    // ---- epilogue ----
    const float* brp = bias_row ? bias_row + (size_t)bz * brs : nullptr;
    const float* bcp = bias_col ? bias_col + (size_t)bz * bcs : nullptr;
    const int g  = lane >> 2;
    const int t2 = (lane & 3) * 2;
    #pragma unroll
    for (int i = 0; i < 4; i++) {
        const int m = m0 + wm + i * 16 + g;
        const float br0 = brp ? brp[m] : 0.f;
        const float br1 = brp ? brp[m + 8] : 0.f;
        #pragma unroll
        for (int j = 0; j < 4; j++) {
            const int n = n0 + wn + j * 8 + t2;
            float bc0v = 0.f, bc1v = 0.f;
            if (bcp) { bc0v = bcp[n]; bc1v = bcp[n + 1]; }
            float v0 = acc[i][j][0] * alpha + br0 + bc0v;
            float v1 = acc[i][j][1] * alpha + br0 + bc1v;
            float v2 = acc[i][j][2] * alpha + br1 + bc0v;
            float v3 = acc[i][j][3] * alpha + br1 + bc1v;
            if (resid) {
                const float* rp = resid + (size_t)bz * sR;
                v0 += rp[(size_t)m * N + n];
                v1 += rp[(size_t)m * N + n + 1];
                v2 += rp[(size_t)(m + 8) * N + n];
                v3 += rp[(size_t)(m + 8) * N + n + 1];
            }
            if (OUTF32) {
                float* C = (float*)C0 + (size_t)bz * sC;
                float2 o0; o0.x = v0; o0.y = v1;
                float2 o1; o1.x = v2; o1.y = v3;
                *(float2*)&C[(size_t)m * N + n] = o0;
                *(float2*)&C[(size_t)(m + 8) * N + n] = o1;
            } else {
                __nv_bfloat16* Ch = (__nv_bfloat16*)C0 + (size_t)bz * sC;
                __nv_bfloat162 hh01, hh23;
                hh01.x = __float2bfloat16(v0); hh01.y = __float2bfloat16(v1);
                hh23.x = __float2bfloat16(v2); hh23.y = __float2bfloat16(v3);
                *(__nv_bfloat162*)&Ch[(size_t)m * N + n] = hh01;
                *(__nv_bfloat162*)&Ch[(size_t)(m + 8) * N + n] = hh23;
            }
        }
    }
}

// ---------------------------------------------------------------------------
// Launch
// ---------------------------------------------------------------------------
extern "C" void kernel_launch(void* const* d_in, const int* in_sizes, int n_in,
                              void* d_out, int out_size)
{
    (void)in_sizes; (void)n_in; (void)out_size;
    const float* x    = (const float*)d_in[0];
    const float* gn_w = (const float*)d_in[1];
    const float* gn_b = (const float*)d_in[2];
    const float* wq   = (const float*)d_in[3];
    const float* bq   = (const float*)d_in[4];
    const float* wk   = (const float*)d_in[5];
    const float* bk   = (const float*)d_in[6];
    const float* wv   = (const float*)d_in[7];
    const float* bv   = (const float*)d_in[8];
    const float* wp   = (const float*)d_in[9];
    const float* bp   = (const float*)d_in[10];
    float* out = (float*)d_out;

    __nv_bfloat16 *Hn, *Hc, *U, *G, *P;
    __nv_bfloat16 *WqTh, *WqTl, *WkTh, *WkTl, *WvTh, *WvTl, *Wph, *Wpl;
    __nv_bfloat16 *Th, *Tl, *W2h, *W2l;
    float *S, *Traw, *W2raw, *rq, *rk, *cvec;
    cudaGetSymbolAddress((void**)&Hn, g_Hn);
    cudaGetSymbolAddress((void**)&Hc, g_Hc);
    cudaGetSymbolAddress((void**)&U,  g_U);
    cudaGetSymbolAddress((void**)&G,  g_G);
    cudaGetSymbolAddress((void**)&P,  g_P);
    cudaGetSymbolAddress((void**)&S,  g_S);
    cudaGetSymbolAddress((void**)&WqTh, g_WqTh); cudaGetSymbolAddress((void**)&WqTl, g_WqTl);
    cudaGetSymbolAddress((void**)&WkTh, g_WkTh); cudaGetSymbolAddress((void**)&WkTl, g_WkTl);
    cudaGetSymbolAddress((void**)&WvTh, g_WvTh); cudaGetSymbolAddress((void**)&WvTl, g_WvTl);
    cudaGetSymbolAddress((void**)&Wph, g_Wph);   cudaGetSymbolAddress((void**)&Wpl, g_Wpl);
    cudaGetSymbolAddress((void**)&Th, g_Th);     cudaGetSymbolAddress((void**)&Tl, g_Tl);
    cudaGetSymbolAddress((void**)&W2h, g_W2h);   cudaGetSymbolAddress((void**)&W2l, g_W2l);
    cudaGetSymbolAddress((void**)&Traw, g_Traw); cudaGetSymbolAddress((void**)&W2raw, g_W2raw);
    cudaGetSymbolAddress((void**)&rq, g_rq);     cudaGetSymbolAddress((void**)&rk, g_rk);
    cudaGetSymbolAddress((void**)&cvec, g_cvec);

    const int SM2 = 2 * 2 * TILE_B;  // 40960
    const int SM3 = 2 * 3 * TILE_B;  // 61440
    const int SM4 = 2 * 4 * TILE_B;  // 81920
    static bool attr_done = false;
    if (!attr_done) {
        cudaFuncSetAttribute((const void*)mma_gemm<2, 2, true>,  cudaFuncAttributeMaxDynamicSharedMemorySize, SM4);
        cudaFuncSetAttribute((const void*)mma_gemm<1, 2, false>, cudaFuncAttributeMaxDynamicSharedMemorySize, SM3);
        cudaFuncSetAttribute((const void*)mma_gemm<2, 1, true>,  cudaFuncAttributeMaxDynamicSharedMemorySize, SM3);
        cudaFuncSetAttribute((const void*)mma_gemm<1, 1, true>,  cudaFuncAttributeMaxDynamicSharedMemorySize, SM2);
        cudaFuncSetAttribute((const void*)mma_gemm<1, 1, false>, cudaFuncAttributeMaxDynamicSharedMemorySize, SM2);
        attr_done = true;
    }

    const size_t sCN = (size_t)CH * NPIX;
    const size_t sNN = (size_t)NPIX * NPIX;
    const float scale = 0.044194173824159223f; // 512^-0.5

    // 0) pack weights (transposed q,k,v hi/lo; natural p hi/lo)
    pack_weights_kernel<<<4096, 256>>>(wq, wk, wv, wp);
    // bias precomputes
    vecs_kernel<<<6, 256>>>(wq, wk, bq, bk, wp, bv, bp);

    // 1) T = scale * Wq^T.Wk : C[c1][c2] = sum_co WqT(c1,co)*WkT(c2,co), 3-term
    {
        dim3 grid(4, 4, 1);
        mma_gemm<2, 2, true><<<grid, 256, SM4>>>(WqTh, WqTl, WkTh, WkTl, Traw,
            CH, CH, 0, 0, 0, nullptr, 0, nullptr, 0, nullptr, 0, scale);
    }
    // 2) W2 = Wp.Wv : C[co][c] = sum_cm Wp(co,cm)*WvT(c,cm), 3-term
    {
        dim3 grid(4, 4, 1);
        mma_gemm<2, 2, true><<<grid, 256, SM4>>>(Wph, Wpl, WvTh, WvTl, W2raw,
            CH, CH, 0, 0, 0, nullptr, 0, nullptr, 0, nullptr, 0, 1.f);
    }
    split_tw_kernel<<<2048, 256>>>();

    // 3) GroupNorm -> Hn [b][n][c], Hc [b][c][n]
    gn_kernel<<<BATCH * NG, 256>>>(x, gn_w, gn_b);

    // bias corrections rq/rk (zero when bq=bk=0, but computed generally)
    rqk_kernel<<<4096, 256>>>(scale);

    // 4) U[b][n][c1] = sum_c2 Hn(n,c2) * T(c1,c2)   (2-term via T hi/lo)
    {
        dim3 grid(CH / 128, NPIX / 128, BATCH);   // (4,8,32)
        mma_gemm<1, 2, false><<<grid, 256, SM3>>>(Hn, nullptr, Th, Tl, U,
            CH, CH, sCN, 0, sCN, nullptr, 0, nullptr, 0, nullptr, 0, 1.f);
    }
    // 5) S[b][q][k] = sum_c1 Hn(q,c1) * U(k,c1) + rq[q] + rk[k]   fp32
    {
        dim3 grid(NPIX / 128, NPIX / 128, BATCH); // (8,8,32)
        mma_gemm<1, 1, true><<<grid, 256, SM2>>>(Hn, nullptr, U, nullptr, S,
            NPIX, CH, sCN, sCN, sNN, rq, NPIX, rk, NPIX, nullptr, 0, 1.f);
    }
    // 6) softmax -> P bf16
    softmax_kernel<<<BATCH * NPIX, 256>>>(S, P);

    // 7) G[b][q][c] = sum_k P(q,k) * Hc(c,k)
    {
        dim3 grid(CH / 128, NPIX / 128, BATCH);   // (4,8,32)
        mma_gemm<1, 1, false><<<grid, 256, SM2>>>(P, nullptr, Hc, nullptr, G,
            CH, NPIX, sNN, sCN, sCN, nullptr, 0, nullptr, 0, nullptr, 0, 1.f);
    }
    // 8) out[b][co][n] = sum_c W2(co,c) * G(n,c) + cvec[co] + x
    {
        dim3 grid(NPIX / 128, CH / 128, BATCH);   // (8,4,32)
        mma_gemm<2, 1, true><<<grid, 256, SM3>>>(W2h, W2l, G, nullptr, out,
            NPIX, CH, 0, sCN, sCN, cvec, 0, nullptr, 0, x, sCN, 1.f);
    }
}

// round 10
// speedup vs baseline: 1.5862x; 1.0666x over previous
#include <cuda_runtime.h>
#include <cuda_bf16.h>
#include <cstdint>
#include <cstddef>

#define BATCH 32
#define CH    512
#define NPIX  1024
#define NG    32
#define CPG   16
#define EPS   1e-6f

#define SZ_CN ((size_t)BATCH * NPIX * CH)
#define SZ_NN ((size_t)BATCH * NPIX * NPIX)
#define WSZ   ((size_t)CH * CH)

// ---------------------------------------------------------------------------
// Scratch
// ---------------------------------------------------------------------------
__device__ __nv_bfloat16 g_Hn[SZ_CN];    // H [b][n][c]
__device__ __nv_bfloat16 g_Hc[SZ_CN];    // H [b][c][n]
__device__ __nv_bfloat16 g_U [SZ_CN];    // U = H.T^T [b][n][c1]
__device__ __nv_bfloat16 g_G [SZ_CN];    // G = P.H  [b][q][c]
__device__ float         g_S [SZ_NN];    // logits fp32
__device__ __nv_bfloat16 g_P [SZ_NN];    // probs bf16
// packed weights, unified layout: [0]=WqT, [1]=Wp(nat), [2]=WkT, [3]=WvT
__device__ __nv_bfloat16 g_Wah[4 * WSZ], g_Wal[4 * WSZ];
__device__ float g_TW[2 * WSZ];                     // Traw | W2raw
__device__ __nv_bfloat16 g_Th[WSZ], g_Tl[WSZ];      // T = scale*Wq^T.Wk split
__device__ __nv_bfloat16 g_W2h[WSZ], g_W2l[WSZ];    // W2 = Wp.Wv split
__device__ float g_vv[2 * CH + 1];
__device__ float g_cvec[CH];
__device__ float g_rq[(size_t)BATCH * NPIX];
__device__ float g_rk[(size_t)BATCH * NPIX];

// ---------------------------------------------------------------------------
// Helpers
// ---------------------------------------------------------------------------
__device__ __forceinline__ uint32_t smem_u32(const void* p) {
    return (uint32_t)__cvta_generic_to_shared(p);
}
__device__ __forceinline__ void ldsm4(uint32_t r[4], uint32_t a) {
    asm volatile("ldmatrix.sync.aligned.m8n8.x4.shared.b16 {%0,%1,%2,%3}, [%4];"
        : "=r"(r[0]), "=r"(r[1]), "=r"(r[2]), "=r"(r[3]) : "r"(a));
}
__device__ __forceinline__ void mma16816(float d[4], const uint32_t a[4], const uint32_t* b) {
    asm volatile(
        "mma.sync.aligned.m16n8k16.row.col.f32.bf16.bf16.f32 "
        "{%0,%1,%2,%3}, {%4,%5,%6,%7}, {%8,%9}, {%0,%1,%2,%3};"
        : "+f"(d[0]), "+f"(d[1]), "+f"(d[2]), "+f"(d[3])
        : "r"(a[0]), "r"(a[1]), "r"(a[2]), "r"(a[3]), "r"(b[0]), "r"(b[1]));
}
__device__ __forceinline__ void cp16(uint32_t s, const void* g) {
    asm volatile("cp.async.cg.shared.global [%0], [%1], 16;" :: "r"(s), "l"(g));
}
__device__ __forceinline__ void cp_commit() {
    asm volatile("cp.async.commit_group;" ::: "memory");
}
template<int n>
__device__ __forceinline__ void cp_wait() {
    asm volatile("cp.async.wait_group %0;" :: "n"(n) : "memory");
}
__device__ __forceinline__ void splitf(float x, __nv_bfloat16& h, __nv_bfloat16& l) {
    h = __float2bfloat16(x);
    l = __float2bfloat16(x - __bfloat162float(h));
}

// ---------------------------------------------------------------------------
// Pack into unified layout: [0]=WqT, [1]=Wp natural, [2]=WkT, [3]=WvT
// ---------------------------------------------------------------------------
__global__ __launch_bounds__(256) void pack_weights_kernel(
    const float* __restrict__ wq, const float* __restrict__ wk,
    const float* __restrict__ wv, const float* __restrict__ wp)
{
    int i = blockIdx.x * 256 + threadIdx.x;     // 0 .. 4*WSZ-1
    int t = i >> 18;
    int j = i & (int)(WSZ - 1);
    float v;
    if (t == 1) {
        v = wp[j];                              // natural
    } else {
        int c = j >> 9, co = j & 511;           // transposed: out[c][co] = W[co][c]
        const float* src = (t == 0) ? wq : (t == 2) ? wk : wv;
        v = src[co * CH + c];
    }
    __nv_bfloat16 h, l;
    splitf(v, h, l);
    g_Wah[i] = h; g_Wal[i] = l;
}

// split fp32 TW -> bf16 hi/lo planes; T gets alpha=scale folded in
__global__ __launch_bounds__(256) void split_tw_kernel(float scale)
{
    int i = blockIdx.x * 256 + threadIdx.x;     // 0 .. 2*WSZ-1
    __nv_bfloat16 h, l;
    if (i < (int)WSZ) {
        splitf(g_TW[i] * scale, h, l);
        g_Th[i] = h; g_Tl[i] = l;
    } else {
        int j = i - (int)WSZ;
        splitf(g_TW[i], h, l);
        g_W2h[j] = h; g_W2l[j] = l;
    }
}

// v1 = Wk^T.bq, v2 = Wq^T.bk, vv[1024] = bq.bk ; cvec = Wp.bv + bp
__global__ __launch_bounds__(256) void vecs_kernel(
    const float* __restrict__ wq, const float* __restrict__ wk,
    const float* __restrict__ bq, const float* __restrict__ bk,
    const float* __restrict__ wp, const float* __restrict__ bv,
    const float* __restrict__ bp)
{
    int gid = blockIdx.x * 256 + threadIdx.x;
    if (gid < CH) {
        float s = 0.f;
        for (int co = 0; co < CH; co++) s += wk[co * CH + gid] * bq[co];
        g_vv[gid] = s;
    } else if (gid < 2 * CH) {
        int c = gid - CH;
        float s = 0.f;
        for (int co = 0; co < CH; co++) s += wq[co * CH + c] * bk[co];
        g_vv[gid] = s;
        if (c == 0) {
            float sc = 0.f;
            for (int co = 0; co < CH; co++) sc += bq[co] * bk[co];
            g_vv[2 * CH] = sc;
        }
    } else if (gid < 3 * CH) {
        int co = gid - 2 * CH;
        float s = bp[co];
        for (int cm = 0; cm < CH; cm++) s += wp[co * CH + cm] * bv[cm];
        g_cvec[co] = s;
    }
}

// rq[b][n] = scale*(v2.h + bqbk), rk[b][n] = scale*(v1.h)
__global__ __launch_bounds__(256) void rqk_kernel(float scale)
{
    const int row = blockIdx.x * 8 + (threadIdx.x >> 5);
    const int lane = threadIdx.x & 31;
    const __nv_bfloat16* h = g_Hn + (size_t)row * CH;
    float d1 = 0.f, d2 = 0.f;
    for (int j = 0; j < 16; j++) {
        int c = lane + j * 32;
        float hv = __bfloat162float(h[c]);
        d1 += g_vv[c] * hv;
        d2 += g_vv[CH + c] * hv;
    }
    #pragma unroll
    for (int o = 16; o > 0; o >>= 1) {
        d1 += __shfl_xor_sync(0xFFFFFFFF, d1, o);
        d2 += __shfl_xor_sync(0xFFFFFFFF, d2, o);
    }
    if (lane == 0) {
        g_rq[row] = scale * (d2 + g_vv[2 * CH]);
        g_rk[row] = scale * d1;
    }
}

// ---------------------------------------------------------------------------
// GroupNorm -> Hn [b][n][c], Hc [b][c][n]
// ---------------------------------------------------------------------------
__global__ __launch_bounds__(256) void gn_kernel(
    const float* __restrict__ x, const float* __restrict__ w,
    const float* __restrict__ b)
{
    const int bg = blockIdx.x;
    const int batch = bg >> 5;
    const int g = bg & 31;
    const int tid = threadIdx.x;
    const float* xp = x + ((size_t)batch * CH + (size_t)g * CPG) * NPIX;

    float s = 0.f, ss = 0.f;
    for (int i = tid; i < CPG * NPIX; i += 256) {
        float v = xp[i];
        s += v; ss += v * v;
    }
    __shared__ float sh_s[256], sh_ss[256];
    sh_s[tid] = s; sh_ss[tid] = ss;
    __syncthreads();
    for (int st = 128; st > 0; st >>= 1) {
        if (tid < st) { sh_s[tid] += sh_s[tid + st]; sh_ss[tid] += sh_ss[tid + st]; }
        __syncthreads();
    }
    const float mean = sh_s[0] * (1.0f / (CPG * NPIX));
    const float var  = sh_ss[0] * (1.0f / (CPG * NPIX)) - mean * mean;
    const float inv  = rsqrtf(var + EPS);

    __shared__ float st[512][17];

    for (int half = 0; half < 2; half++) {
        for (int i = tid; i < CPG * 512; i += 256) {
            int c16 = i >> 9;
            int nl  = i & 511;
            int c   = g * CPG + c16;
            float v = (xp[c16 * NPIX + half * 512 + nl] - mean) * inv;
            v = v * w[c] + b[c];
            st[nl][c16] = v;
            g_Hc[((size_t)batch * CH + c) * NPIX + half * 512 + nl] = __float2bfloat16(v);
        }
        __syncthreads();
        size_t dst = ((size_t)batch * NPIX + half * 512) * CH + g * CPG;
        for (int i = tid; i < CPG * 512; i += 256) {
            int nl = i >> 4;
            int c16 = i & 15;
            g_Hn[dst + (size_t)nl * CH + c16] = __float2bfloat16(st[nl][c16]);
        }
        __syncthreads();
    }
}

// ---------------------------------------------------------------------------
// Vectorized row softmax fp32 -> bf16 probs (float4 in, 4xbf16 out)
// ---------------------------------------------------------------------------
__global__ __launch_bounds__(256) void softmax_kernel(
    const float* __restrict__ S, __nv_bfloat16* __restrict__ Sp)
{
    const float4* p4 = (const float4*)(S + (size_t)blockIdx.x * NPIX);
    uint2* po = (uint2*)(Sp + (size_t)blockIdx.x * NPIX);
    const int t = threadIdx.x;
    const int lane = t & 31;
    const int wid = t >> 5;

    float4 v = p4[t];
    float mx = fmaxf(fmaxf(v.x, v.y), fmaxf(v.z, v.w));
    #pragma unroll
    for (int o = 16; o > 0; o >>= 1)
        mx = fmaxf(mx, __shfl_xor_sync(0xFFFFFFFF, mx, o));
    __shared__ float red[8];
    if (lane == 0) red[wid] = mx;
    __syncthreads();
    mx = red[0];
    #pragma unroll
    for (int i = 1; i < 8; i++) mx = fmaxf(mx, red[i]);
    __syncthreads();

    v.x = __expf(v.x - mx); v.y = __expf(v.y - mx);
    v.z = __expf(v.z - mx); v.w = __expf(v.w - mx);
    float sum = v.x + v.y + v.z + v.w;
    #pragma unroll
    for (int o = 16; o > 0; o >>= 1)
        sum += __shfl_xor_sync(0xFFFFFFFF, sum, o);
    if (lane == 0) red[wid] = sum;
    __syncthreads();
    sum = 0.f;
    #pragma unroll
    for (int i = 0; i < 8; i++) sum += red[i];
    const float inv = 1.0f / sum;

    __nv_bfloat162 lo, hi;
    lo.x = __float2bfloat16(v.x * inv); lo.y = __float2bfloat16(v.y * inv);
    hi.x = __float2bfloat16(v.z * inv); hi.y = __float2bfloat16(v.w * inv);
    uint2 o;
    o.x = *reinterpret_cast<uint32_t*>(&lo);
    o.y = *reinterpret_cast<uint32_t*>(&hi);
    po[t] = o;
}

// ---------------------------------------------------------------------------
// Config A GEMM (proven, round-7):
//   C[m][n] = alpha*sum_k A(m,k)B(n,k) + bias_row[m] + bias_col[n] (+resid)
// Block 128x128, 8 warps (64x32 warp tiles), k-chunk 32, 2 CTAs/SM.
// ---------------------------------------------------------------------------
#define TILE_B   10240
#define ROWS_H   40

template<int PA, int PB, bool OUTF32>
__global__ __launch_bounds__(256, 2) void mma_gemm(
    const __nv_bfloat16* __restrict__ Ah, const __nv_bfloat16* __restrict__ Al,
    const __nv_bfloat16* __restrict__ Bh, const __nv_bfloat16* __restrict__ Bl,
    void* __restrict__ C0,
    int N, int K,
    size_t sA, size_t sB, size_t sC,
    const float* __restrict__ bias_row, size_t brs,
    const float* __restrict__ bias_col, size_t bcs,
    const float* __restrict__ resid, size_t sR, float alpha)
{
    constexpr int NTILES = PA + PB;
    constexpr int STAGE = NTILES * TILE_B;

    extern __shared__ __align__(1024) char smem[];
    const uint32_t sb = smem_u32(smem);

    const int tid  = threadIdx.x;
    const int lane = tid & 31;
    const int warp = tid >> 5;
    const int wm = (warp >> 2) * 64;
    const int wn = (warp & 3) * 32;
    const int m0 = blockIdx.y * 128;
    const int n0 = blockIdx.x * 128;
    const int bz = blockIdx.z;

    const __nv_bfloat16* gA[2];
    gA[0] = Ah + (size_t)bz * sA;
    gA[1] = (PA == 2) ? (Al + (size_t)bz * sA) : nullptr;
    const __nv_bfloat16* gB[2];
    gB[0] = Bh + (size_t)bz * sB;
    gB[1] = (PB == 2) ? (Bl + (size_t)bz * sB) : nullptr;

    auto issue = [&](int c) {
        const int stg = c & 1;
        const int k0 = c * 32;
        const uint32_t sbase = sb + stg * STAGE;
        #pragma unroll
        for (int i = 0; i < 2; i++) {
            const int idx = tid + i * 256;
            const int r = idx >> 2;
            const int seg = idx & 3;
            const uint32_t soff = r * (ROWS_H * 2) + seg * 16;
            const size_t ga = (size_t)(m0 + r) * K + k0 + seg * 8;
            const size_t gb = (size_t)(n0 + r) * K + k0 + seg * 8;
            #pragma unroll
            for (int t = 0; t < PA; t++)
                cp16(sbase + t * TILE_B + soff, gA[t] + ga);
            #pragma unroll
            for (int t = 0; t < PB; t++)
                cp16(sbase + (PA + t) * TILE_B + soff, gB[t] + gb);
        }
        cp_commit();
    };

    float acc[4][4][4] = {};

    const int nc = K >> 5;
    issue(0);

    const int ar = lane & 15;
    const int ac0 = (lane >> 4) * 8;
    const int br = (lane & 7) + (lane >> 4) * 8;
    const int bc0 = ((lane >> 3) & 1) * 8;

    for (int c = 0; c < nc; c++) {
        cp_wait<0>();
        __syncthreads();
        if (c + 1 < nc) issue(c + 1);

        const int stg = c & 1;
        const __nv_bfloat16* TA0 = (const __nv_bfloat16*)(smem + stg * STAGE);
        const __nv_bfloat16* TA1 = (const __nv_bfloat16*)(smem + stg * STAGE + TILE_B);
        const __nv_bfloat16* TB0 = (const __nv_bfloat16*)(smem + stg * STAGE + PA * TILE_B);
        const __nv_bfloat16* TB1 = (const __nv_bfloat16*)(smem + stg * STAGE + (PA + 1) * TILE_B);

        #pragma unroll
        for (int kk = 0; kk < 32; kk += 16) {
            uint32_t a0[4][4], a1[4][4];
            uint32_t b0[8], b1[8];
            #pragma unroll
            for (int i = 0; i < 4; i++) {
                ldsm4(a0[i], smem_u32(TA0 + (wm + i * 16 + ar) * ROWS_H + kk + ac0));
                if (PA == 2)
                    ldsm4(a1[i], smem_u32(TA1 + (wm + i * 16 + ar) * ROWS_H + kk + ac0));
            }
            #pragma unroll
            for (int jj = 0; jj < 2; jj++) {
                ldsm4(&b0[4 * jj], smem_u32(TB0 + (wn + jj * 16 + br) * ROWS_H + kk + bc0));
                if (PB == 2)
                    ldsm4(&b1[4 * jj], smem_u32(TB1 + (wn + jj * 16 + br) * ROWS_H + kk + bc0));
            }
            #pragma unroll
            for (int i = 0; i < 4; i++)
                #pragma unroll
                for (int j = 0; j < 4; j++)
                    mma16816(acc[i][j], a0[i], &b0[2 * j]);
            if (PB == 2) {
                #pragma unroll
                for (int i = 0; i < 4; i++)
                    #pragma unroll
                    for (int j = 0; j < 4; j++)
                        mma16816(acc[i][j], a0[i], &b1[2 * j]);
            }
            if (PA == 2) {
                #pragma unroll
                for (int i = 0; i < 4; i++)
                    #pragma unroll
                    for (int j = 0; j < 4; j++)
                        mma16816(acc[i][j], a1[i], &b0[2 * j]);
            }
        }
    }

    const float* brp = bias_row ? bias_row + (size_t)bz * brs : nullptr;
    const float* bcp = bias_col ? bias_col + (size_t)bz * bcs : nullptr;
    const int g  = lane >> 2;
    const int t2 = (lane & 3) * 2;
    #pragma unroll
    for (int i = 0; i < 4; i++) {
        const int m = m0 + wm + i * 16 + g;
        const float br0 = brp ? brp[m] : 0.f;
        const float br1 = brp ? brp[m + 8] : 0.f;
        #pragma unroll
        for (int j = 0; j < 4; j++) {
            const int n = n0 + wn + j * 8 + t2;
            float bc0v = 0.f, bc1v = 0.f;
            if (bcp) { bc0v = bcp[n]; bc1v = bcp[n + 1]; }
            float v0 = acc[i][j][0] * alpha + br0 + bc0v;
            float v1 = acc[i][j][1] * alpha + br0 + bc1v;
            float v2 = acc[i][j][2] * alpha + br1 + bc0v;
            float v3 = acc[i][j][3] * alpha + br1 + bc1v;
            if (resid) {
                const float* rp = resid + (size_t)bz * sR;
                v0 += rp[(size_t)m * N + n];
                v1 += rp[(size_t)m * N + n + 1];
                v2 += rp[(size_t)(m + 8) * N + n];
                v3 += rp[(size_t)(m + 8) * N + n + 1];
            }
            if (OUTF32) {
                float* C = (float*)C0 + (size_t)bz * sC;
                float2 o0; o0.x = v0; o0.y = v1;
                float2 o1; o1.x = v2; o1.y = v3;
                *(float2*)&C[(size_t)m * N + n] = o0;
                *(float2*)&C[(size_t)(m + 8) * N + n] = o1;
            } else {
                __nv_bfloat16* Ch = (__nv_bfloat16*)C0 + (size_t)bz * sC;
                __nv_bfloat162 hh01, hh23;
                hh01.x = __float2bfloat16(v0); hh01.y = __float2bfloat16(v1);
                hh23.x = __float2bfloat16(v2); hh23.y = __float2bfloat16(v3);
                *(__nv_bfloat162*)&Ch[(size_t)m * N + n] = hh01;
                *(__nv_bfloat162*)&Ch[(size_t)(m + 8) * N + n] = hh23;
            }
        }
    }
}

// ---------------------------------------------------------------------------
// Config B GEMM (1-term, LDSM-traffic-optimized): 4 warps (64x64 tiles),
// 128 threads, block 128x128, k-chunk 32, 2 CTAs/SM.
//   C[m][n] = alpha*sum_k A(m,k)B(n,k) + bias_row[m] + bias_col[n]
// ---------------------------------------------------------------------------
template<bool OUTF32>
__global__ __launch_bounds__(128, 2) void mma_gemm_b(
    const __nv_bfloat16* __restrict__ Ah, const __nv_bfloat16* __restrict__ Bh,
    void* __restrict__ C0,
    int N, int K,
    size_t sA, size_t sB, size_t sC,
    const float* __restrict__ bias_row, size_t brs,
    const float* __restrict__ bias_col, size_t bcs,
    float alpha)
{
    constexpr int STAGE = 2 * TILE_B;

    extern __shared__ __align__(1024) char smem[];
    const uint32_t sb = smem_u32(smem);

    const int tid  = threadIdx.x;
    const int lane = tid & 31;
    const int warp = tid >> 5;            // 0..3
    const int wm = (warp >> 1) * 64;
    const int wn = (warp & 1) * 64;
    const int m0 = blockIdx.y * 128;
    const int n0 = blockIdx.x * 128;
    const int bz = blockIdx.z;

    const __nv_bfloat16* gA = Ah + (size_t)bz * sA;
    const __nv_bfloat16* gB = Bh + (size_t)bz * sB;

    auto issue = [&](int c) {
        const int stg = c & 1;
        const int k0 = c * 32;
        const uint32_t sbase = sb + stg * STAGE;
        #pragma unroll
        for (int i = 0; i < 4; i++) {
            const int idx = tid + i * 128;       // 0..511
            const int r = idx >> 2;
            const int seg = idx & 3;
            const uint32_t soff = r * (ROWS_H * 2) + seg * 16;
            cp16(sbase + soff, gA + (size_t)(m0 + r) * K + k0 + seg * 8);
            cp16(sbase + TILE_B + soff, gB + (size_t)(n0 + r) * K + k0 + seg * 8);
        }
        cp_commit();
    };

    float acc[4][8][4] = {};

    const int nc = K >> 5;
    issue(0);

    const int ar = lane & 15;
    const int ac0 = (lane >> 4) * 8;
    const int br = (lane & 7) + (lane >> 4) * 8;
    const int bc0 = ((lane >> 3) & 1) * 8;

    for (int c = 0; c < nc; c++) {
        cp_wait<0>();
        __syncthreads();
        if (c + 1 < nc) issue(c + 1);

        const int stg = c & 1;
        const __nv_bfloat16* TA = (const __nv_bfloat16*)(smem + stg * STAGE);
        const __nv_bfloat16* TB = (const __nv_bfloat16*)(smem + stg * STAGE + TILE_B);

        #pragma unroll
        for (int kk = 0; kk < 32; kk += 16) {
            uint32_t a0[4][4];
            uint32_t b0[16];
            #pragma unroll
            for (int i = 0; i < 4; i++)
                ldsm4(a0[i], smem_u32(TA + (wm + i * 16 + ar) * ROWS_H + kk + ac0));
            #pragma unroll
            for (int jj = 0; jj < 4; jj++)
                ldsm4(&b0[4 * jj], smem_u32(TB + (wn + jj * 16 + br) * ROWS_H + kk + bc0));
            #pragma unroll
            for (int i = 0; i < 4; i++)
                #pragma unroll
                for (int j = 0; j < 8; j++)
                    mma16816(acc[i][j], a0[i], &b0[2 * j]);
        }
    }

    const float* brp = bias_row ? bias_row + (size_t)bz * brs : nullptr;
    const float* bcp = bias_col ? bias_col + (size_t)bz * bcs : nullptr;
    const int g  = lane >> 2;
    const int t2 = (lane & 3) * 2;
    #pragma unroll
    for (int i = 0; i < 4; i++) {
        const int m = m0 + wm + i * 16 + g;
        const float br0 = brp ? brp[m] : 0.f;
        const float br1 = brp ? brp[m + 8] : 0.f;
        #pragma unroll
        for (int j = 0; j < 8; j++) {
            const int n = n0 + wn + j * 8 + t2;
            float bc0v = 0.f, bc1v = 0.f;
            if (bcp) { bc0v = bcp[n]; bc1v = bcp[n + 1]; }
            float v0 = acc[i][j][0] * alpha + br0 + bc0v;
            float v1 = acc[i][j][1] * alpha + br0 + bc1v;
            float v2 = acc[i][j][2] * alpha + br1 + bc0v;
            float v3 = acc[i][j][3] * alpha + br1 + bc1v;
            if (OUTF32) {
                float* C = (float*)C0 + (size_t)bz * sC;
                float2 o0; o0.x = v0; o0.y = v1;
                float2 o1; o1.x = v2; o1.y = v3;
                *(float2*)&C[(size_t)m * N + n] = o0;
                *(float2*)&C[(size_t)(m + 8) * N + n] = o1;
            } else {
                __nv_bfloat16* Ch = (__nv_bfloat16*)C0 + (size_t)bz * sC;
                __nv_bfloat162 hh01, hh23;
                hh01.x = __float2bfloat16(v0); hh01.y = __float2bfloat16(v1);
                hh23.x = __float2bfloat16(v2); hh23.y = __float2bfloat16(v3);
                *(__nv_bfloat162*)&Ch[(size_t)m * N + n] = hh01;
                *(__nv_bfloat162*)&Ch[(size_t)(m + 8) * N + n] = hh23;
            }
        }
    }
}

// ---------------------------------------------------------------------------
// Launch
// ---------------------------------------------------------------------------
extern "C" void kernel_launch(void* const* d_in, const int* in_sizes, int n_in,
                              void* d_out, int out_size)
{
    (void)in_sizes; (void)n_in; (void)out_size;
    const float* x    = (const float*)d_in[0];
    const float* gn_w = (const float*)d_in[1];
    const float* gn_b = (const float*)d_in[2];
    const float* wq   = (const float*)d_in[3];
    const float* bq   = (const float*)d_in[4];
    const float* wk   = (const float*)d_in[5];
    const float* bk   = (const float*)d_in[6];
    const float* wv   = (const float*)d_in[7];
    const float* bv   = (const float*)d_in[8];
    const float* wp   = (const float*)d_in[9];
    const float* bp   = (const float*)d_in[10];
    float* out = (float*)d_out;

    __nv_bfloat16 *Hn, *Hc, *U, *G, *P, *Wah, *Wal, *Th, *Tl, *W2h, *W2l;
    float *S, *TW, *rq, *rk, *cvec;
    cudaGetSymbolAddress((void**)&Hn, g_Hn);
    cudaGetSymbolAddress((void**)&Hc, g_Hc);
    cudaGetSymbolAddress((void**)&U,  g_U);
    cudaGetSymbolAddress((void**)&G,  g_G);
    cudaGetSymbolAddress((void**)&P,  g_P);
    cudaGetSymbolAddress((void**)&S,  g_S);
    cudaGetSymbolAddress((void**)&Wah, g_Wah); cudaGetSymbolAddress((void**)&Wal, g_Wal);
    cudaGetSymbolAddress((void**)&Th, g_Th);   cudaGetSymbolAddress((void**)&Tl, g_Tl);
    cudaGetSymbolAddress((void**)&W2h, g_W2h); cudaGetSymbolAddress((void**)&W2l, g_W2l);
    cudaGetSymbolAddress((void**)&TW, g_TW);
    cudaGetSymbolAddress((void**)&rq, g_rq);   cudaGetSymbolAddress((void**)&rk, g_rk);
    cudaGetSymbolAddress((void**)&cvec, g_cvec);

    const int SMB = 2 * 2 * TILE_B;  // 40960 (config B, 1-term)
    const int SM3 = 2 * 3 * TILE_B;  // 61440
    const int SM4 = 2 * 4 * TILE_B;  // 81920
    static bool attr_done = false;
    if (!attr_done) {
        cudaFuncSetAttribute((const void*)mma_gemm<2, 2, true>,  cudaFuncAttributeMaxDynamicSharedMemorySize, SM4);
        cudaFuncSetAttribute((const void*)mma_gemm<1, 2, false>, cudaFuncAttributeMaxDynamicSharedMemorySize, SM3);
        cudaFuncSetAttribute((const void*)mma_gemm<2, 1, true>,  cudaFuncAttributeMaxDynamicSharedMemorySize, SM3);
        cudaFuncSetAttribute((const void*)mma_gemm_b<true>,  cudaFuncAttributeMaxDynamicSharedMemorySize, SMB);
        cudaFuncSetAttribute((const void*)mma_gemm_b<false>, cudaFuncAttributeMaxDynamicSharedMemorySize, SMB);
        attr_done = true;
    }

    const size_t sCN = (size_t)CH * NPIX;
    const size_t sNN = (size_t)NPIX * NPIX;
    const float scale = 0.044194173824159223f; // 512^-0.5

    // 0) pack weights + bias precomputes
    pack_weights_kernel<<<4096, 256>>>(wq, wk, wv, wp);
    vecs_kernel<<<6, 256>>>(wq, wk, bq, bk, wp, bv, bp);

    // 1) T | W2 in ONE launch: z=0: WqT.WkT^T ; z=1: Wp.WvT^T  (3-term each)
    {
        dim3 grid(4, 4, 2);
        mma_gemm<2, 2, true><<<grid, 256, SM4>>>(Wah, Wal, Wah + 2 * WSZ, Wal + 2 * WSZ, TW,
            CH, CH, WSZ, WSZ, WSZ, nullptr, 0, nullptr, 0, nullptr, 0, 1.f);
    }
    split_tw_kernel<<<2048, 256>>>(scale);

    // 2) GroupNorm -> Hn, Hc
    gn_kernel<<<BATCH * NG, 256>>>(x, gn_w, gn_b);
    rqk_kernel<<<4096, 256>>>(scale);

    // 3) U[b][n][c1] = sum_c2 Hn(n,c2)*T(c1,c2)  (2-term)
    {
        dim3 grid(CH / 128, NPIX / 128, BATCH);
        mma_gemm<1, 2, false><<<grid, 256, SM3>>>(Hn, nullptr, Th, Tl, U,
            CH, CH, sCN, 0, sCN, nullptr, 0, nullptr, 0, nullptr, 0, 1.f);
    }
    // 4) S[b][q][k] = sum_c1 Hn(q,c1)*U(k,c1) + rq[q] + rk[k]   (config B)
    {
        dim3 grid(NPIX / 128, NPIX / 128, BATCH);
        mma_gemm_b<true><<<grid, 128, SMB>>>(Hn, U, S,
            NPIX, CH, sCN, sCN, sNN, rq, NPIX, rk, NPIX, 1.f);
    }
    // 5) softmax -> P bf16
    softmax_kernel<<<BATCH * NPIX, 256>>>(S, P);

    // 6) G[b][q][c] = sum_k P(q,k)*Hc(c,k)   (config B)
    {
        dim3 grid(CH / 128, NPIX / 128, BATCH);
        mma_gemm_b<false><<<grid, 128, SMB>>>(P, Hc, G,
            CH, NPIX, sNN, sCN, sCN, nullptr, 0, nullptr, 0, 1.f);
    }
    // 7) out[b][co][n] = sum_c W2(co,c)*G(n,c) + cvec[co] + x
    {
        dim3 grid(NPIX / 128, CH / 128, BATCH);
        mma_gemm<2, 1, true><<<grid, 256, SM3>>>(W2h, W2l, G, nullptr, out,
            NPIX, CH, 0, sCN, sCN, cvec, 0, nullptr, 0, x, sCN, 1.f);
    }
}

// round 11
// speedup vs baseline: 1.7309x; 1.0913x over previous
#include <cuda_runtime.h>
#include <cuda_bf16.h>
#include <cstdint>
#include <cstddef>

#define BATCH 32
#define CH    512
#define NPIX  1024
#define NG    32
#define CPG   16
#define EPS   1e-6f

#define SZ_CN ((size_t)BATCH * NPIX * CH)
#define SZ_NN ((size_t)BATCH * NPIX * NPIX)
#define WSZ   ((size_t)CH * CH)

// ---------------------------------------------------------------------------
// Scratch
// ---------------------------------------------------------------------------
__device__ __nv_bfloat16 g_Hn[SZ_CN];    // H [b][n][c]
__device__ __nv_bfloat16 g_Hc[SZ_CN];    // H [b][c][n]
__device__ __nv_bfloat16 g_U [SZ_CN];    // U = H.T^T [b][n][c1]
__device__ __nv_bfloat16 g_G [SZ_CN];    // G = P.H  [b][q][c]
__device__ float         g_S [SZ_NN];    // logits fp32
__device__ __nv_bfloat16 g_P [SZ_NN];    // probs bf16
// packed weights, unified layout: [0]=WqT, [1]=Wp(nat), [2]=WkT, [3]=WvT
__device__ __nv_bfloat16 g_Wah[4 * WSZ], g_Wal[4 * WSZ];
__device__ float g_TW[2 * WSZ];                     // Traw | W2raw
__device__ __nv_bfloat16 g_Th[WSZ], g_Tl[WSZ];      // T = scale*Wq^T.Wk split
__device__ __nv_bfloat16 g_W2h[WSZ], g_W2l[WSZ];    // W2 = Wp.Wv split
__device__ float g_vv[2 * CH + 1];
__device__ float g_cvec[CH];
__device__ float g_rq[(size_t)BATCH * NPIX];
__device__ float g_rk[(size_t)BATCH * NPIX];

// ---------------------------------------------------------------------------
// Helpers
// ---------------------------------------------------------------------------
__device__ __forceinline__ uint32_t smem_u32(const void* p) {
    return (uint32_t)__cvta_generic_to_shared(p);
}
__device__ __forceinline__ void ldsm4(uint32_t r[4], uint32_t a) {
    asm volatile("ldmatrix.sync.aligned.m8n8.x4.shared.b16 {%0,%1,%2,%3}, [%4];"
        : "=r"(r[0]), "=r"(r[1]), "=r"(r[2]), "=r"(r[3]) : "r"(a));
}
__device__ __forceinline__ void mma16816(float d[4], const uint32_t a[4], const uint32_t* b) {
    asm volatile(
        "mma.sync.aligned.m16n8k16.row.col.f32.bf16.bf16.f32 "
        "{%0,%1,%2,%3}, {%4,%5,%6,%7}, {%8,%9}, {%0,%1,%2,%3};"
        : "+f"(d[0]), "+f"(d[1]), "+f"(d[2]), "+f"(d[3])
        : "r"(a[0]), "r"(a[1]), "r"(a[2]), "r"(a[3]), "r"(b[0]), "r"(b[1]));
}
__device__ __forceinline__ void cp16(uint32_t s, const void* g) {
    asm volatile("cp.async.cg.shared.global [%0], [%1], 16;" :: "r"(s), "l"(g));
}
__device__ __forceinline__ void cp_commit() {
    asm volatile("cp.async.commit_group;" ::: "memory");
}
template<int n>
__device__ __forceinline__ void cp_wait() {
    asm volatile("cp.async.wait_group %0;" :: "n"(n) : "memory");
}
__device__ __forceinline__ void splitf(float x, __nv_bfloat16& h, __nv_bfloat16& l) {
    h = __float2bfloat16(x);
    l = __float2bfloat16(x - __bfloat162float(h));
}

// ---------------------------------------------------------------------------
// Pack into unified layout: [0]=WqT, [1]=Wp natural, [2]=WkT, [3]=WvT
// ---------------------------------------------------------------------------
__global__ __launch_bounds__(256) void pack_weights_kernel(
    const float* __restrict__ wq, const float* __restrict__ wk,
    const float* __restrict__ wv, const float* __restrict__ wp)
{
    int i = blockIdx.x * 256 + threadIdx.x;
    int t = i >> 18;
    int j = i & (int)(WSZ - 1);
    float v;
    if (t == 1) {
        v = wp[j];
    } else {
        int c = j >> 9, co = j & 511;
        const float* src = (t == 0) ? wq : (t == 2) ? wk : wv;
        v = src[co * CH + c];
    }
    __nv_bfloat16 h, l;
    splitf(v, h, l);
    g_Wah[i] = h; g_Wal[i] = l;
}

// split fp32 TW -> bf16 hi/lo planes; T gets alpha=scale folded in
__global__ __launch_bounds__(256) void split_tw_kernel(float scale)
{
    int i = blockIdx.x * 256 + threadIdx.x;
    __nv_bfloat16 h, l;
    if (i < (int)WSZ) {
        splitf(g_TW[i] * scale, h, l);
        g_Th[i] = h; g_Tl[i] = l;
    } else {
        int j = i - (int)WSZ;
        splitf(g_TW[i], h, l);
        g_W2h[j] = h; g_W2l[j] = l;
    }
}

// warp-per-output: v1 = Wk^T.bq, v2 = Wq^T.bk, bq.bk ; cvec = Wp.bv + bp
// grid: 192 blocks x 256 = 1536 warps
__global__ __launch_bounds__(256) void vecs_kernel(
    const float* __restrict__ wq, const float* __restrict__ wk,
    const float* __restrict__ bq, const float* __restrict__ bk,
    const float* __restrict__ wp, const float* __restrict__ bv,
    const float* __restrict__ bp)
{
    const int gw = (blockIdx.x * 256 + threadIdx.x) >> 5;   // 0..1535
    const int lane = threadIdx.x & 31;
    float s = 0.f;
    if (gw < CH) {
        const int c = gw;
        #pragma unroll
        for (int j = 0; j < 16; j++) {
            int co = lane + j * 32;
            s += wk[co * CH + c] * bq[co];
        }
        #pragma unroll
        for (int o = 16; o > 0; o >>= 1) s += __shfl_xor_sync(0xFFFFFFFF, s, o);
        if (lane == 0) g_vv[c] = s;
        if (gw == 0) {
            float sc = 0.f;
            #pragma unroll
            for (int j = 0; j < 16; j++) {
                int co = lane + j * 32;
                sc += bq[co] * bk[co];
            }
            #pragma unroll
            for (int o = 16; o > 0; o >>= 1) sc += __shfl_xor_sync(0xFFFFFFFF, sc, o);
            if (lane == 0) g_vv[2 * CH] = sc;
        }
    } else if (gw < 2 * CH) {
        const int c = gw - CH;
        #pragma unroll
        for (int j = 0; j < 16; j++) {
            int co = lane + j * 32;
            s += wq[co * CH + c] * bk[co];
        }
        #pragma unroll
        for (int o = 16; o > 0; o >>= 1) s += __shfl_xor_sync(0xFFFFFFFF, s, o);
        if (lane == 0) g_vv[CH + c] = s;
    } else {
        const int co = gw - 2 * CH;
        #pragma unroll
        for (int j = 0; j < 16; j++) {
            int cm = lane + j * 32;
            s += wp[co * CH + cm] * bv[cm];
        }
        #pragma unroll
        for (int o = 16; o > 0; o >>= 1) s += __shfl_xor_sync(0xFFFFFFFF, s, o);
        if (lane == 0) g_cvec[co] = s + bp[co];
    }
}

// rq[b][n] = scale*(v2.h + bqbk), rk[b][n] = scale*(v1.h)
__global__ __launch_bounds__(256) void rqk_kernel(float scale)
{
    const int row = blockIdx.x * 8 + (threadIdx.x >> 5);
    const int lane = threadIdx.x & 31;
    const __nv_bfloat16* h = g_Hn + (size_t)row * CH;
    float d1 = 0.f, d2 = 0.f;
    #pragma unroll
    for (int j = 0; j < 16; j++) {
        int c = lane + j * 32;
        float hv = __bfloat162float(h[c]);
        d1 += g_vv[c] * hv;
        d2 += g_vv[CH + c] * hv;
    }
    #pragma unroll
    for (int o = 16; o > 0; o >>= 1) {
        d1 += __shfl_xor_sync(0xFFFFFFFF, d1, o);
        d2 += __shfl_xor_sync(0xFFFFFFFF, d2, o);
    }
    if (lane == 0) {
        g_rq[row] = scale * (d2 + g_vv[2 * CH]);
        g_rk[row] = scale * d1;
    }
}

// ---------------------------------------------------------------------------
// GroupNorm -> Hn [b][n][c], Hc [b][c][n]
// ---------------------------------------------------------------------------
__global__ __launch_bounds__(256) void gn_kernel(
    const float* __restrict__ x, const float* __restrict__ w,
    const float* __restrict__ b)
{
    const int bg = blockIdx.x;
    const int batch = bg >> 5;
    const int g = bg & 31;
    const int tid = threadIdx.x;
    const float* xp = x + ((size_t)batch * CH + (size_t)g * CPG) * NPIX;

    float s = 0.f, ss = 0.f;
    for (int i = tid; i < CPG * NPIX; i += 256) {
        float v = xp[i];
        s += v; ss += v * v;
    }
    __shared__ float sh_s[256], sh_ss[256];
    sh_s[tid] = s; sh_ss[tid] = ss;
    __syncthreads();
    for (int st = 128; st > 0; st >>= 1) {
        if (tid < st) { sh_s[tid] += sh_s[tid + st]; sh_ss[tid] += sh_ss[tid + st]; }
        __syncthreads();
    }
    const float mean = sh_s[0] * (1.0f / (CPG * NPIX));
    const float var  = sh_ss[0] * (1.0f / (CPG * NPIX)) - mean * mean;
    const float inv  = rsqrtf(var + EPS);

    __shared__ float st[512][17];

    for (int half = 0; half < 2; half++) {
        for (int i = tid; i < CPG * 512; i += 256) {
            int c16 = i >> 9;
            int nl  = i & 511;
            int c   = g * CPG + c16;
            float v = (xp[c16 * NPIX + half * 512 + nl] - mean) * inv;
            v = v * w[c] + b[c];
            st[nl][c16] = v;
            g_Hc[((size_t)batch * CH + c) * NPIX + half * 512 + nl] = __float2bfloat16(v);
        }
        __syncthreads();
        size_t dst = ((size_t)batch * NPIX + half * 512) * CH + g * CPG;
        for (int i = tid; i < CPG * 512; i += 256) {
            int nl = i >> 4;
            int c16 = i & 15;
            g_Hn[dst + (size_t)nl * CH + c16] = __float2bfloat16(st[nl][c16]);
        }
        __syncthreads();
    }
}

// ---------------------------------------------------------------------------
// Vectorized row softmax fp32 -> bf16 probs
// ---------------------------------------------------------------------------
__global__ __launch_bounds__(256) void softmax_kernel(
    const float* __restrict__ S, __nv_bfloat16* __restrict__ Sp)
{
    const float4* p4 = (const float4*)(S + (size_t)blockIdx.x * NPIX);
    uint2* po = (uint2*)(Sp + (size_t)blockIdx.x * NPIX);
    const int t = threadIdx.x;
    const int lane = t & 31;
    const int wid = t >> 5;

    float4 v = p4[t];
    float mx = fmaxf(fmaxf(v.x, v.y), fmaxf(v.z, v.w));
    #pragma unroll
    for (int o = 16; o > 0; o >>= 1)
        mx = fmaxf(mx, __shfl_xor_sync(0xFFFFFFFF, mx, o));
    __shared__ float red[8];
    if (lane == 0) red[wid] = mx;
    __syncthreads();
    mx = red[0];
    #pragma unroll
    for (int i = 1; i < 8; i++) mx = fmaxf(mx, red[i]);
    __syncthreads();

    v.x = __expf(v.x - mx); v.y = __expf(v.y - mx);
    v.z = __expf(v.z - mx); v.w = __expf(v.w - mx);
    float sum = v.x + v.y + v.z + v.w;
    #pragma unroll
    for (int o = 16; o > 0; o >>= 1)
        sum += __shfl_xor_sync(0xFFFFFFFF, sum, o);
    if (lane == 0) red[wid] = sum;
    __syncthreads();
    sum = 0.f;
    #pragma unroll
    for (int i = 0; i < 8; i++) sum += red[i];
    const float inv = 1.0f / sum;

    __nv_bfloat162 lo, hi;
    lo.x = __float2bfloat16(v.x * inv); lo.y = __float2bfloat16(v.y * inv);
    hi.x = __float2bfloat16(v.z * inv); hi.y = __float2bfloat16(v.w * inv);
    uint2 o;
    o.x = *reinterpret_cast<uint32_t*>(&lo);
    o.y = *reinterpret_cast<uint32_t*>(&hi);
    po[t] = o;
}

#define TILE_B   10240
#define ROWS_H   40

// ---------------------------------------------------------------------------
// Config A GEMM (8 warps, 64x32 tiles) — used only for tiny T/W2 precompute.
// ---------------------------------------------------------------------------
template<int PA, int PB, bool OUTF32>
__global__ __launch_bounds__(256, 2) void mma_gemm(
    const __nv_bfloat16* __restrict__ Ah, const __nv_bfloat16* __restrict__ Al,
    const __nv_bfloat16* __restrict__ Bh, const __nv_bfloat16* __restrict__ Bl,
    void* __restrict__ C0,
    int N, int K,
    size_t sA, size_t sB, size_t sC,
    float alpha)
{
    constexpr int NTILES = PA + PB;
    constexpr int STAGE = NTILES * TILE_B;

    extern __shared__ __align__(1024) char smem[];
    const uint32_t sb = smem_u32(smem);

    const int tid  = threadIdx.x;
    const int lane = tid & 31;
    const int warp = tid >> 5;
    const int wm = (warp >> 2) * 64;
    const int wn = (warp & 3) * 32;
    const int m0 = blockIdx.y * 128;
    const int n0 = blockIdx.x * 128;
    const int bz = blockIdx.z;

    const __nv_bfloat16* gA[2];
    gA[0] = Ah + (size_t)bz * sA;
    gA[1] = (PA == 2) ? (Al + (size_t)bz * sA) : nullptr;
    const __nv_bfloat16* gB[2];
    gB[0] = Bh + (size_t)bz * sB;
    gB[1] = (PB == 2) ? (Bl + (size_t)bz * sB) : nullptr;

    auto issue = [&](int c) {
        const int stg = c & 1;
        const int k0 = c * 32;
        const uint32_t sbase = sb + stg * STAGE;
        #pragma unroll
        for (int i = 0; i < 2; i++) {
            const int idx = tid + i * 256;
            const int r = idx >> 2;
            const int seg = idx & 3;
            const uint32_t soff = r * (ROWS_H * 2) + seg * 16;
            const size_t ga = (size_t)(m0 + r) * K + k0 + seg * 8;
            const size_t gb = (size_t)(n0 + r) * K + k0 + seg * 8;
            #pragma unroll
            for (int t = 0; t < PA; t++)
                cp16(sbase + t * TILE_B + soff, gA[t] + ga);
            #pragma unroll
            for (int t = 0; t < PB; t++)
                cp16(sbase + (PA + t) * TILE_B + soff, gB[t] + gb);
        }
        cp_commit();
    };

    float acc[4][4][4] = {};

    const int nc = K >> 5;
    issue(0);

    const int ar = lane & 15;
    const int ac0 = (lane >> 4) * 8;
    const int br = (lane & 7) + (lane >> 4) * 8;
    const int bc0 = ((lane >> 3) & 1) * 8;

    for (int c = 0; c < nc; c++) {
        cp_wait<0>();
        __syncthreads();
        if (c + 1 < nc) issue(c + 1);

        const int stg = c & 1;
        const __nv_bfloat16* TA0 = (const __nv_bfloat16*)(smem + stg * STAGE);
        const __nv_bfloat16* TA1 = (const __nv_bfloat16*)(smem + stg * STAGE + TILE_B);
        const __nv_bfloat16* TB0 = (const __nv_bfloat16*)(smem + stg * STAGE + PA * TILE_B);
        const __nv_bfloat16* TB1 = (const __nv_bfloat16*)(smem + stg * STAGE + (PA + 1) * TILE_B);

        #pragma unroll
        for (int kk = 0; kk < 32; kk += 16) {
            uint32_t a0[4][4], a1[4][4];
            uint32_t b0[8], b1[8];
            #pragma unroll
            for (int i = 0; i < 4; i++) {
                ldsm4(a0[i], smem_u32(TA0 + (wm + i * 16 + ar) * ROWS_H + kk + ac0));
                if (PA == 2)
                    ldsm4(a1[i], smem_u32(TA1 + (wm + i * 16 + ar) * ROWS_H + kk + ac0));
            }
            #pragma unroll
            for (int jj = 0; jj < 2; jj++) {
                ldsm4(&b0[4 * jj], smem_u32(TB0 + (wn + jj * 16 + br) * ROWS_H + kk + bc0));
                if (PB == 2)
                    ldsm4(&b1[4 * jj], smem_u32(TB1 + (wn + jj * 16 + br) * ROWS_H + kk + bc0));
            }
            #pragma unroll
            for (int i = 0; i < 4; i++)
                #pragma unroll
                for (int j = 0; j < 4; j++)
                    mma16816(acc[i][j], a0[i], &b0[2 * j]);
            if (PB == 2) {
                #pragma unroll
                for (int i = 0; i < 4; i++)
                    #pragma unroll
                    for (int j = 0; j < 4; j++)
                        mma16816(acc[i][j], a0[i], &b1[2 * j]);
            }
            if (PA == 2) {
                #pragma unroll
                for (int i = 0; i < 4; i++)
                    #pragma unroll
                    for (int j = 0; j < 4; j++)
                        mma16816(acc[i][j], a1[i], &b0[2 * j]);
            }
        }
    }

    const int g  = lane >> 2;
    const int t2 = (lane & 3) * 2;
    #pragma unroll
    for (int i = 0; i < 4; i++) {
        const int m = m0 + wm + i * 16 + g;
        #pragma unroll
        for (int j = 0; j < 4; j++) {
            const int n = n0 + wn + j * 8 + t2;
            float v0 = acc[i][j][0] * alpha;
            float v1 = acc[i][j][1] * alpha;
            float v2 = acc[i][j][2] * alpha;
            float v3 = acc[i][j][3] * alpha;
            if (OUTF32) {
                float* C = (float*)C0 + (size_t)bz * sC;
                float2 o0; o0.x = v0; o0.y = v1;
                float2 o1; o1.x = v2; o1.y = v3;
                *(float2*)&C[(size_t)m * N + n] = o0;
                *(float2*)&C[(size_t)(m + 8) * N + n] = o1;
            } else {
                __nv_bfloat16* Ch = (__nv_bfloat16*)C0 + (size_t)bz * sC;
                __nv_bfloat162 hh01, hh23;
                hh01.x = __float2bfloat16(v0); hh01.y = __float2bfloat16(v1);
                hh23.x = __float2bfloat16(v2); hh23.y = __float2bfloat16(v3);
                *(__nv_bfloat162*)&Ch[(size_t)m * N + n] = hh01;
                *(__nv_bfloat162*)&Ch[(size_t)(m + 8) * N + n] = hh23;
            }
        }
    }
}

// ---------------------------------------------------------------------------
// Config C GEMM (wide tiles, LDSM-optimized): 4 warps (64x64 warp tiles),
// 128 threads, block 128x128, k-chunk 32, 2 CTAs/SM. PA/PB planes (<=2).
// Terms: a0b0 (+a0b1 if PB==2) (+a1b0 if PA==2).
//   C[m][n] = alpha*sum_k A(m,k)B(n,k) + bias_row[m] + bias_col[n] (+resid)
// ---------------------------------------------------------------------------
template<int PA, int PB, bool OUTF32>
__global__ __launch_bounds__(128, 2) void mma_gemm_c(
    const __nv_bfloat16* __restrict__ Ah, const __nv_bfloat16* __restrict__ Al,
    const __nv_bfloat16* __restrict__ Bh, const __nv_bfloat16* __restrict__ Bl,
    void* __restrict__ C0,
    int N, int K,
    size_t sA, size_t sB, size_t sC,
    const float* __restrict__ bias_row, size_t brs,
    const float* __restrict__ bias_col, size_t bcs,
    const float* __restrict__ resid, size_t sR, float alpha)
{
    constexpr int NTILES = PA + PB;
    constexpr int STAGE = NTILES * TILE_B;

    extern __shared__ __align__(1024) char smem[];
    const uint32_t sb = smem_u32(smem);

    const int tid  = threadIdx.x;
    const int lane = tid & 31;
    const int warp = tid >> 5;            // 0..3
    const int wm = (warp >> 1) * 64;
    const int wn = (warp & 1) * 64;
    const int m0 = blockIdx.y * 128;
    const int n0 = blockIdx.x * 128;
    const int bz = blockIdx.z;

    const __nv_bfloat16* gA[2];
    gA[0] = Ah + (size_t)bz * sA;
    gA[1] = (PA == 2) ? (Al + (size_t)bz * sA) : nullptr;
    const __nv_bfloat16* gB[2];
    gB[0] = Bh + (size_t)bz * sB;
    gB[1] = (PB == 2) ? (Bl + (size_t)bz * sB) : nullptr;

    auto issue = [&](int c) {
        const int stg = c & 1;
        const int k0 = c * 32;
        const uint32_t sbase = sb + stg * STAGE;
        #pragma unroll
        for (int i = 0; i < 4; i++) {
            const int idx = tid + i * 128;       // 0..511
            const int r = idx >> 2;
            const int seg = idx & 3;
            const uint32_t soff = r * (ROWS_H * 2) + seg * 16;
            const size_t ga = (size_t)(m0 + r) * K + k0 + seg * 8;
            const size_t gb = (size_t)(n0 + r) * K + k0 + seg * 8;
            #pragma unroll
            for (int t = 0; t < PA; t++)
                cp16(sbase + t * TILE_B + soff, gA[t] + ga);
            #pragma unroll
            for (int t = 0; t < PB; t++)
                cp16(sbase + (PA + t) * TILE_B + soff, gB[t] + gb);
        }
        cp_commit();
    };

    float acc[4][8][4] = {};

    const int nc = K >> 5;
    issue(0);

    const int ar = lane & 15;
    const int ac0 = (lane >> 4) * 8;
    const int br = (lane & 7) + (lane >> 4) * 8;
    const int bc0 = ((lane >> 3) & 1) * 8;

    for (int c = 0; c < nc; c++) {
        cp_wait<0>();
        __syncthreads();
        if (c + 1 < nc) issue(c + 1);

        const int stg = c & 1;
        const __nv_bfloat16* TA0 = (const __nv_bfloat16*)(smem + stg * STAGE);
        const __nv_bfloat16* TA1 = (const __nv_bfloat16*)(smem + stg * STAGE + TILE_B);
        const __nv_bfloat16* TB0 = (const __nv_bfloat16*)(smem + stg * STAGE + PA * TILE_B);
        const __nv_bfloat16* TB1 = (const __nv_bfloat16*)(smem + stg * STAGE + (PA + 1) * TILE_B);

        #pragma unroll
        for (int kk = 0; kk < 32; kk += 16) {
            uint32_t a0[4][4], a1[4][4];
            uint32_t b0[16], b1[16];
            #pragma unroll
            for (int i = 0; i < 4; i++) {
                ldsm4(a0[i], smem_u32(TA0 + (wm + i * 16 + ar) * ROWS_H + kk + ac0));
                if (PA == 2)
                    ldsm4(a1[i], smem_u32(TA1 + (wm + i * 16 + ar) * ROWS_H + kk + ac0));
            }
            #pragma unroll
            for (int jj = 0; jj < 4; jj++) {
                ldsm4(&b0[4 * jj], smem_u32(TB0 + (wn + jj * 16 + br) * ROWS_H + kk + bc0));
                if (PB == 2)
                    ldsm4(&b1[4 * jj], smem_u32(TB1 + (wn + jj * 16 + br) * ROWS_H + kk + bc0));
            }
            #pragma unroll
            for (int i = 0; i < 4; i++)
                #pragma unroll
                for (int j = 0; j < 8; j++)
                    mma16816(acc[i][j], a0[i], &b0[2 * j]);
            if (PB == 2) {
                #pragma unroll
                for (int i = 0; i < 4; i++)
                    #pragma unroll
                    for (int j = 0; j < 8; j++)
                        mma16816(acc[i][j], a0[i], &b1[2 * j]);
            }
            if (PA == 2) {
                #pragma unroll
                for (int i = 0; i < 4; i++)
                    #pragma unroll
                    for (int j = 0; j < 8; j++)
                        mma16816(acc[i][j], a1[i], &b0[2 * j]);
            }
        }
    }

    const float* brp = bias_row ? bias_row + (size_t)bz * brs : nullptr;
    const float* bcp = bias_col ? bias_col + (size_t)bz * bcs : nullptr;
    const int g  = lane >> 2;
    const int t2 = (lane & 3) * 2;
    #pragma unroll
    for (int i = 0; i < 4; i++) {
        const int m = m0 + wm + i * 16 + g;
        const float br0 = brp ? brp[m] : 0.f;
        const float br1 = brp ? brp[m + 8] : 0.f;
        #pragma unroll
        for (int j = 0; j < 8; j++) {
            const int n = n0 + wn + j * 8 + t2;
            float bc0v = 0.f, bc1v = 0.f;
            if (bcp) { bc0v = bcp[n]; bc1v = bcp[n + 1]; }
            float v0 = acc[i][j][0] * alpha + br0 + bc0v;
            float v1 = acc[i][j][1] * alpha + br0 + bc1v;
            float v2 = acc[i][j][2] * alpha + br1 + bc0v;
            float v3 = acc[i][j][3] * alpha + br1 + bc1v;
            if (resid) {
                const float* rp = resid + (size_t)bz * sR;
                v0 += rp[(size_t)m * N + n];
                v1 += rp[(size_t)m * N + n + 1];
                v2 += rp[(size_t)(m + 8) * N + n];
                v3 += rp[(size_t)(m + 8) * N + n + 1];
            }
            if (OUTF32) {
                float* C = (float*)C0 + (size_t)bz * sC;
                float2 o0; o0.x = v0; o0.y = v1;
                float2 o1; o1.x = v2; o1.y = v3;
                *(float2*)&C[(size_t)m * N + n] = o0;
                *(float2*)&C[(size_t)(m + 8) * N + n] = o1;
            } else {
                __nv_bfloat16* Ch = (__nv_bfloat16*)C0 + (size_t)bz * sC;
                __nv_bfloat162 hh01, hh23;
                hh01.x = __float2bfloat16(v0); hh01.y = __float2bfloat16(v1);
                hh23.x = __float2bfloat16(v2); hh23.y = __float2bfloat16(v3);
                *(__nv_bfloat162*)&Ch[(size_t)m * N + n] = hh01;
                *(__nv_bfloat162*)&Ch[(size_t)(m + 8) * N + n] = hh23;
            }
        }
    }
}

// ---------------------------------------------------------------------------
// Launch
// ---------------------------------------------------------------------------
extern "C" void kernel_launch(void* const* d_in, const int* in_sizes, int n_in,
                              void* d_out, int out_size)
{
    (void)in_sizes; (void)n_in; (void)out_size;
    const float* x    = (const float*)d_in[0];
    const float* gn_w = (const float*)d_in[1];
    const float* gn_b = (const float*)d_in[2];
    const float* wq   = (const float*)d_in[3];
    const float* bq   = (const float*)d_in[4];
    const float* wk   = (const float*)d_in[5];
    const float* bk   = (const float*)d_in[6];
    const float* wv   = (const float*)d_in[7];
    const float* bv   = (const float*)d_in[8];
    const float* wp   = (const float*)d_in[9];
    const float* bp   = (const float*)d_in[10];
    float* out = (float*)d_out;

    __nv_bfloat16 *Hn, *Hc, *U, *G, *P, *Wah, *Wal, *Th, *Tl, *W2h, *W2l;
    float *S, *TW, *rq, *rk, *cvec;
    cudaGetSymbolAddress((void**)&Hn, g_Hn);
    cudaGetSymbolAddress((void**)&Hc, g_Hc);
    cudaGetSymbolAddress((void**)&U,  g_U);
    cudaGetSymbolAddress((void**)&G,  g_G);
    cudaGetSymbolAddress((void**)&P,  g_P);
    cudaGetSymbolAddress((void**)&S,  g_S);
    cudaGetSymbolAddress((void**)&Wah, g_Wah); cudaGetSymbolAddress((void**)&Wal, g_Wal);
    cudaGetSymbolAddress((void**)&Th, g_Th);   cudaGetSymbolAddress((void**)&Tl, g_Tl);
    cudaGetSymbolAddress((void**)&W2h, g_W2h); cudaGetSymbolAddress((void**)&W2l, g_W2l);
    cudaGetSymbolAddress((void**)&TW, g_TW);
    cudaGetSymbolAddress((void**)&rq, g_rq);   cudaGetSymbolAddress((void**)&rk, g_rk);
    cudaGetSymbolAddress((void**)&cvec, g_cvec);

    const int SMC2 = 2 * 2 * TILE_B;  // 40960 (config C, 2 planes)
    const int SMC3 = 2 * 3 * TILE_B;  // 61440 (config C, 3 planes)
    const int SM4  = 2 * 4 * TILE_B;  // 81920 (config A, 4 planes)
    static bool attr_done = false;
    if (!attr_done) {
        cudaFuncSetAttribute((const void*)mma_gemm<2, 2, true>,    cudaFuncAttributeMaxDynamicSharedMemorySize, SM4);
        cudaFuncSetAttribute((const void*)mma_gemm_c<1, 2, false>, cudaFuncAttributeMaxDynamicSharedMemorySize, SMC3);
        cudaFuncSetAttribute((const void*)mma_gemm_c<2, 1, true>,  cudaFuncAttributeMaxDynamicSharedMemorySize, SMC3);
        cudaFuncSetAttribute((const void*)mma_gemm_c<1, 1, true>,  cudaFuncAttributeMaxDynamicSharedMemorySize, SMC2);
        cudaFuncSetAttribute((const void*)mma_gemm_c<1, 1, false>, cudaFuncAttributeMaxDynamicSharedMemorySize, SMC2);
        attr_done = true;
    }

    const size_t sCN = (size_t)CH * NPIX;
    const size_t sNN = (size_t)NPIX * NPIX;
    const float scale = 0.044194173824159223f; // 512^-0.5

    // 0) pack weights + bias precomputes
    pack_weights_kernel<<<4096, 256>>>(wq, wk, wv, wp);
    vecs_kernel<<<192, 256>>>(wq, wk, bq, bk, wp, bv, bp);

    // 1) T | W2 in one launch: z=0: WqT.WkT^T ; z=1: Wp.WvT^T  (3-term)
    {
        dim3 grid(4, 4, 2);
        mma_gemm<2, 2, true><<<grid, 256, SM4>>>(Wah, Wal, Wah + 2 * WSZ, Wal + 2 * WSZ, TW,
            CH, CH, WSZ, WSZ, WSZ, 1.f);
    }
    split_tw_kernel<<<2048, 256>>>(scale);

    // 2) GroupNorm -> Hn, Hc
    gn_kernel<<<BATCH * NG, 256>>>(x, gn_w, gn_b);
    rqk_kernel<<<4096, 256>>>(scale);

    // 3) U[b][n][c1] = sum_c2 Hn(n,c2)*T(c1,c2)  (2-term, config C)
    {
        dim3 grid(CH / 128, NPIX / 128, BATCH);
        mma_gemm_c<1, 2, false><<<grid, 128, SMC3>>>(Hn, nullptr, Th, Tl, U,
            CH, CH, sCN, 0, sCN, nullptr, 0, nullptr, 0, nullptr, 0, 1.f);
    }
    // 4) S[b][q][k] = sum_c1 Hn(q,c1)*U(k,c1) + rq[q] + rk[k]  (config C)
    {
        dim3 grid(NPIX / 128, NPIX / 128, BATCH);
        mma_gemm_c<1, 1, true><<<grid, 128, SMC2>>>(Hn, nullptr, U, nullptr, S,
            NPIX, CH, sCN, sCN, sNN, rq, NPIX, rk, NPIX, nullptr, 0, 1.f);
    }
    // 5) softmax -> P bf16
    softmax_kernel<<<BATCH * NPIX, 256>>>(S, P);

    // 6) G[b][q][c] = sum_k P(q,k)*Hc(c,k)  (config C)
    {
        dim3 grid(CH / 128, NPIX / 128, BATCH);
        mma_gemm_c<1, 1, false><<<grid, 128, SMC2>>>(P, nullptr, Hc, nullptr, G,
            CH, NPIX, sNN, sCN, sCN, nullptr, 0, nullptr, 0, nullptr, 0, 1.f);
    }
    // 7) out[b][co][n] = sum_c W2(co,c)*G(n,c) + cvec[co] + x  (config C)
    {
        dim3 grid(NPIX / 128, CH / 128, BATCH);
        mma_gemm_c<2, 1, true><<<grid, 128, SMC3>>>(W2h, W2l, G, nullptr, out,
            NPIX, CH, 0, sCN, sCN, cvec, 0, nullptr, 0, x, sCN, 1.f);
    }
}

// round 12
// speedup vs baseline: 1.8484x; 1.0679x over previous
#include <cuda_runtime.h>
#include <cuda_bf16.h>
#include <cuda_fp16.h>
#include <cstdint>
#include <cstddef>

#define BATCH 32
#define CH    512
#define NPIX  1024
#define NG    32
#define CPG   16
#define EPS   1e-6f

#define SZ_CN ((size_t)BATCH * NPIX * CH)
#define SZ_NN ((size_t)BATCH * NPIX * NPIX)
#define WSZ   ((size_t)CH * CH)

// ---------------------------------------------------------------------------
// Scratch
// ---------------------------------------------------------------------------
__device__ __nv_bfloat16 g_Hn[SZ_CN];    // H [b][n][c]
__device__ __nv_bfloat16 g_Hc[SZ_CN];    // H [b][c][n]
__device__ __nv_bfloat16 g_U [SZ_CN];    // U = H.T^T [b][n][c1]
__device__ __nv_bfloat16 g_G [SZ_CN];    // G = P.H  [b][q][c]
__device__ __half        g_S [SZ_NN];    // logits fp16
__device__ __nv_bfloat16 g_P [SZ_NN];    // probs bf16
// packed weights: [0]=WqT, [1]=Wp(nat), [2]=WkT, [3]=WvT
__device__ __nv_bfloat16 g_Wah[4 * WSZ], g_Wal[4 * WSZ];
__device__ float g_TW[2 * WSZ];                     // Traw | W2raw (atomic acc)
__device__ __nv_bfloat16 g_Th[WSZ], g_Tl[WSZ];      // T = scale*Wq^T.Wk split
__device__ __nv_bfloat16 g_W2h[WSZ], g_W2l[WSZ];    // W2 = Wp.Wv split
__device__ float g_vv[2 * CH + 1];
__device__ float g_cvec[CH];
__device__ float g_rq[(size_t)BATCH * NPIX];
__device__ float g_rk[(size_t)BATCH * NPIX];

// ---------------------------------------------------------------------------
// Helpers
// ---------------------------------------------------------------------------
__device__ __forceinline__ uint32_t smem_u32(const void* p) {
    return (uint32_t)__cvta_generic_to_shared(p);
}
__device__ __forceinline__ void ldsm4(uint32_t r[4], uint32_t a) {
    asm volatile("ldmatrix.sync.aligned.m8n8.x4.shared.b16 {%0,%1,%2,%3}, [%4];"
        : "=r"(r[0]), "=r"(r[1]), "=r"(r[2]), "=r"(r[3]) : "r"(a));
}
__device__ __forceinline__ void mma16816(float d[4], const uint32_t a[4], const uint32_t* b) {
    asm volatile(
        "mma.sync.aligned.m16n8k16.row.col.f32.bf16.bf16.f32 "
        "{%0,%1,%2,%3}, {%4,%5,%6,%7}, {%8,%9}, {%0,%1,%2,%3};"
        : "+f"(d[0]), "+f"(d[1]), "+f"(d[2]), "+f"(d[3])
        : "r"(a[0]), "r"(a[1]), "r"(a[2]), "r"(a[3]), "r"(b[0]), "r"(b[1]));
}
__device__ __forceinline__ void cp16(uint32_t s, const void* g) {
    asm volatile("cp.async.cg.shared.global [%0], [%1], 16;" :: "r"(s), "l"(g));
}
__device__ __forceinline__ void cp_commit() {
    asm volatile("cp.async.commit_group;" ::: "memory");
}
template<int n>
__device__ __forceinline__ void cp_wait() {
    asm volatile("cp.async.wait_group %0;" :: "n"(n) : "memory");
}
__device__ __forceinline__ void splitf(float x, __nv_bfloat16& h, __nv_bfloat16& l) {
    h = __float2bfloat16(x);
    l = __float2bfloat16(x - __bfloat162float(h));
}

// ---------------------------------------------------------------------------
// Pack into unified layout: [0]=WqT, [1]=Wp natural, [2]=WkT, [3]=WvT
// ---------------------------------------------------------------------------
__global__ __launch_bounds__(256) void pack_weights_kernel(
    const float* __restrict__ wq, const float* __restrict__ wk,
    const float* __restrict__ wv, const float* __restrict__ wp)
{
    int i = blockIdx.x * 256 + threadIdx.x;
    int t = i >> 18;
    int j = i & (int)(WSZ - 1);
    float v;
    if (t == 1) {
        v = wp[j];
    } else {
        int c = j >> 9, co = j & 511;
        const float* src = (t == 0) ? wq : (t == 2) ? wk : wv;
        v = src[co * CH + c];
    }
    __nv_bfloat16 h, l;
    splitf(v, h, l);
    g_Wah[i] = h; g_Wal[i] = l;
}

// split fp32 TW -> bf16 hi/lo planes; T gets alpha=scale folded in
__global__ __launch_bounds__(256) void split_tw_kernel(float scale)
{
    int i = blockIdx.x * 256 + threadIdx.x;
    __nv_bfloat16 h, l;
    if (i < (int)WSZ) {
        splitf(g_TW[i] * scale, h, l);
        g_Th[i] = h; g_Tl[i] = l;
    } else {
        int j = i - (int)WSZ;
        splitf(g_TW[i], h, l);
        g_W2h[j] = h; g_W2l[j] = l;
    }
}

// warp-per-output: v1 = Wk^T.bq, v2 = Wq^T.bk, bq.bk ; cvec = Wp.bv + bp
__global__ __launch_bounds__(256) void vecs_kernel(
    const float* __restrict__ wq, const float* __restrict__ wk,
    const float* __restrict__ bq, const float* __restrict__ bk,
    const float* __restrict__ wp, const float* __restrict__ bv,
    const float* __restrict__ bp)
{
    const int gw = (blockIdx.x * 256 + threadIdx.x) >> 5;
    const int lane = threadIdx.x & 31;
    float s = 0.f;
    if (gw < CH) {
        const int c = gw;
        #pragma unroll
        for (int j = 0; j < 16; j++) {
            int co = lane + j * 32;
            s += wk[co * CH + c] * bq[co];
        }
        #pragma unroll
        for (int o = 16; o > 0; o >>= 1) s += __shfl_xor_sync(0xFFFFFFFF, s, o);
        if (lane == 0) g_vv[c] = s;
        if (gw == 0) {
            float sc = 0.f;
            #pragma unroll
            for (int j = 0; j < 16; j++) {
                int co = lane + j * 32;
                sc += bq[co] * bk[co];
            }
            #pragma unroll
            for (int o = 16; o > 0; o >>= 1) sc += __shfl_xor_sync(0xFFFFFFFF, sc, o);
            if (lane == 0) g_vv[2 * CH] = sc;
        }
    } else if (gw < 2 * CH) {
        const int c = gw - CH;
        #pragma unroll
        for (int j = 0; j < 16; j++) {
            int co = lane + j * 32;
            s += wq[co * CH + c] * bk[co];
        }
        #pragma unroll
        for (int o = 16; o > 0; o >>= 1) s += __shfl_xor_sync(0xFFFFFFFF, s, o);
        if (lane == 0) g_vv[CH + c] = s;
    } else {
        const int co = gw - 2 * CH;
        #pragma unroll
        for (int j = 0; j < 16; j++) {
            int cm = lane + j * 32;
            s += wp[co * CH + cm] * bv[cm];
        }
        #pragma unroll
        for (int o = 16; o > 0; o >>= 1) s += __shfl_xor_sync(0xFFFFFFFF, s, o);
        if (lane == 0) g_cvec[co] = s + bp[co];
    }
}

// rq[b][n] = scale*(v2.h + bqbk), rk[b][n] = scale*(v1.h)
__global__ __launch_bounds__(256) void rqk_kernel(float scale)
{
    const int row = blockIdx.x * 8 + (threadIdx.x >> 5);
    const int lane = threadIdx.x & 31;
    const __nv_bfloat16* h = g_Hn + (size_t)row * CH;
    float d1 = 0.f, d2 = 0.f;
    #pragma unroll
    for (int j = 0; j < 16; j++) {
        int c = lane + j * 32;
        float hv = __bfloat162float(h[c]);
        d1 += g_vv[c] * hv;
        d2 += g_vv[CH + c] * hv;
    }
    #pragma unroll
    for (int o = 16; o > 0; o >>= 1) {
        d1 += __shfl_xor_sync(0xFFFFFFFF, d1, o);
        d2 += __shfl_xor_sync(0xFFFFFFFF, d2, o);
    }
    if (lane == 0) {
        g_rq[row] = scale * (d2 + g_vv[2 * CH]);
        g_rk[row] = scale * d1;
    }
}

// ---------------------------------------------------------------------------
// GroupNorm -> Hn [b][n][c], Hc [b][c][n]
// ---------------------------------------------------------------------------
__global__ __launch_bounds__(256) void gn_kernel(
    const float* __restrict__ x, const float* __restrict__ w,
    const float* __restrict__ b)
{
    const int bg = blockIdx.x;
    const int batch = bg >> 5;
    const int g = bg & 31;
    const int tid = threadIdx.x;
    const float* xp = x + ((size_t)batch * CH + (size_t)g * CPG) * NPIX;

    float s = 0.f, ss = 0.f;
    for (int i = tid; i < CPG * NPIX; i += 256) {
        float v = xp[i];
        s += v; ss += v * v;
    }
    __shared__ float sh_s[256], sh_ss[256];
    sh_s[tid] = s; sh_ss[tid] = ss;
    __syncthreads();
    for (int st = 128; st > 0; st >>= 1) {
        if (tid < st) { sh_s[tid] += sh_s[tid + st]; sh_ss[tid] += sh_ss[tid + st]; }
        __syncthreads();
    }
    const float mean = sh_s[0] * (1.0f / (CPG * NPIX));
    const float var  = sh_ss[0] * (1.0f / (CPG * NPIX)) - mean * mean;
    const float inv  = rsqrtf(var + EPS);

    __shared__ float st[512][17];

    for (int half = 0; half < 2; half++) {
        for (int i = tid; i < CPG * 512; i += 256) {
            int c16 = i >> 9;
            int nl  = i & 511;
            int c   = g * CPG + c16;
            float v = (xp[c16 * NPIX + half * 512 + nl] - mean) * inv;
            v = v * w[c] + b[c];
            st[nl][c16] = v;
            g_Hc[((size_t)batch * CH + c) * NPIX + half * 512 + nl] = __float2bfloat16(v);
        }
        __syncthreads();
        size_t dst = ((size_t)batch * NPIX + half * 512) * CH + g * CPG;
        for (int i = tid; i < CPG * 512; i += 256) {
            int nl = i >> 4;
            int c16 = i & 15;
            g_Hn[dst + (size_t)nl * CH + c16] = __float2bfloat16(st[nl][c16]);
        }
        __syncthreads();
    }
}

// ---------------------------------------------------------------------------
// Row softmax fp16 logits -> bf16 probs
// ---------------------------------------------------------------------------
__global__ __launch_bounds__(256) void softmax_kernel(
    const __half* __restrict__ S, __nv_bfloat16* __restrict__ Sp)
{
    const uint2* p = (const uint2*)(S + (size_t)blockIdx.x * NPIX);
    uint2* po = (uint2*)(Sp + (size_t)blockIdx.x * NPIX);
    const int t = threadIdx.x;
    const int lane = t & 31;
    const int wid = t >> 5;

    uint2 raw = p[t];
    float2 f01 = __half22float2(*reinterpret_cast<__half2*>(&raw.x));
    float2 f23 = __half22float2(*reinterpret_cast<__half2*>(&raw.y));
    float4 v; v.x = f01.x; v.y = f01.y; v.z = f23.x; v.w = f23.y;

    float mx = fmaxf(fmaxf(v.x, v.y), fmaxf(v.z, v.w));
    #pragma unroll
    for (int o = 16; o > 0; o >>= 1)
        mx = fmaxf(mx, __shfl_xor_sync(0xFFFFFFFF, mx, o));
    __shared__ float red[8];
    if (lane == 0) red[wid] = mx;
    __syncthreads();
    mx = red[0];
    #pragma unroll
    for (int i = 1; i < 8; i++) mx = fmaxf(mx, red[i]);
    __syncthreads();

    v.x = __expf(v.x - mx); v.y = __expf(v.y - mx);
    v.z = __expf(v.z - mx); v.w = __expf(v.w - mx);
    float sum = v.x + v.y + v.z + v.w;
    #pragma unroll
    for (int o = 16; o > 0; o >>= 1)
        sum += __shfl_xor_sync(0xFFFFFFFF, sum, o);
    if (lane == 0) red[wid] = sum;
    __syncthreads();
    sum = 0.f;
    #pragma unroll
    for (int i = 0; i < 8; i++) sum += red[i];
    const float inv = 1.0f / sum;

    __nv_bfloat162 lo, hi;
    lo.x = __float2bfloat16(v.x * inv); lo.y = __float2bfloat16(v.y * inv);
    hi.x = __float2bfloat16(v.z * inv); hi.y = __float2bfloat16(v.w * inv);
    uint2 o;
    o.x = *reinterpret_cast<uint32_t*>(&lo);
    o.y = *reinterpret_cast<uint32_t*>(&hi);
    po[t] = o;
}

#define TILE_B   10240
#define ROWS_H   40

// ---------------------------------------------------------------------------
// T/W2 precompute GEMM: config A shape, split-K(x4), atomicAdd epilogue.
// grid (4,4,8): z>>2 = matrix (0:T, 1:W2), z&3 = K-slice of 128.
// A = Wa[mat], B = Wa[mat+2]; 3-term hi/lo.
// ---------------------------------------------------------------------------
__global__ __launch_bounds__(256, 2) void tw_gemm(
    const __nv_bfloat16* __restrict__ Wah, const __nv_bfloat16* __restrict__ Wal,
    float* __restrict__ TW)
{
    constexpr int STAGE = 4 * TILE_B;

    extern __shared__ __align__(1024) char smem[];
    const uint32_t sb = smem_u32(smem);

    const int tid  = threadIdx.x;
    const int lane = tid & 31;
    const int warp = tid >> 5;
    const int wm = (warp >> 2) * 64;
    const int wn = (warp & 3) * 32;
    const int m0 = blockIdx.y * 128;
    const int n0 = blockIdx.x * 128;
    const int mat = blockIdx.z >> 2;
    const int kbase = (blockIdx.z & 3) * 128;

    const __nv_bfloat16* gA[2] = { Wah + (size_t)mat * WSZ, Wal + (size_t)mat * WSZ };
    const __nv_bfloat16* gB[2] = { Wah + (size_t)(mat + 2) * WSZ, Wal + (size_t)(mat + 2) * WSZ };
    float* C = TW + (size_t)mat * WSZ;

    auto issue = [&](int c) {
        const int stg = c & 1;
        const int k0 = kbase + c * 32;
        const uint32_t sbase = sb + stg * STAGE;
        #pragma unroll
        for (int i = 0; i < 2; i++) {
            const int idx = tid + i * 256;
            const int r = idx >> 2;
            const int seg = idx & 3;
            const uint32_t soff = r * (ROWS_H * 2) + seg * 16;
            const size_t ga = (size_t)(m0 + r) * CH + k0 + seg * 8;
            const size_t gb = (size_t)(n0 + r) * CH + k0 + seg * 8;
            cp16(sbase + soff, gA[0] + ga);
            cp16(sbase + TILE_B + soff, gA[1] + ga);
            cp16(sbase + 2 * TILE_B + soff, gB[0] + gb);
            cp16(sbase + 3 * TILE_B + soff, gB[1] + gb);
        }
        cp_commit();
    };

    float acc[4][4][4] = {};

    issue(0);

    const int ar = lane & 15;
    const int ac0 = (lane >> 4) * 8;
    const int br = (lane & 7) + (lane >> 4) * 8;
    const int bc0 = ((lane >> 3) & 1) * 8;

    for (int c = 0; c < 4; c++) {
        cp_wait<0>();
        __syncthreads();
        if (c + 1 < 4) issue(c + 1);

        const int stg = c & 1;
        const __nv_bfloat16* TA0 = (const __nv_bfloat16*)(smem + stg * STAGE);
        const __nv_bfloat16* TA1 = (const __nv_bfloat16*)(smem + stg * STAGE + TILE_B);
        const __nv_bfloat16* TB0 = (const __nv_bfloat16*)(smem + stg * STAGE + 2 * TILE_B);
        const __nv_bfloat16* TB1 = (const __nv_bfloat16*)(smem + stg * STAGE + 3 * TILE_B);

        #pragma unroll
        for (int kk = 0; kk < 32; kk += 16) {
            uint32_t a0[4][4], a1[4][4];
            uint32_t b0[8], b1[8];
            #pragma unroll
            for (int i = 0; i < 4; i++) {
                ldsm4(a0[i], smem_u32(TA0 + (wm + i * 16 + ar) * ROWS_H + kk + ac0));
                ldsm4(a1[i], smem_u32(TA1 + (wm + i * 16 + ar) * ROWS_H + kk + ac0));
            }
            #pragma unroll
            for (int jj = 0; jj < 2; jj++) {
                ldsm4(&b0[4 * jj], smem_u32(TB0 + (wn + jj * 16 + br) * ROWS_H + kk + bc0));
                ldsm4(&b1[4 * jj], smem_u32(TB1 + (wn + jj * 16 + br) * ROWS_H + kk + bc0));
            }
            #pragma unroll
            for (int i = 0; i < 4; i++)
                #pragma unroll
                for (int j = 0; j < 4; j++)
                    mma16816(acc[i][j], a0[i], &b0[2 * j]);
            #pragma unroll
            for (int i = 0; i < 4; i++)
                #pragma unroll
                for (int j = 0; j < 4; j++)
                    mma16816(acc[i][j], a0[i], &b1[2 * j]);
            #pragma unroll
            for (int i = 0; i < 4; i++)
                #pragma unroll
                for (int j = 0; j < 4; j++)
                    mma16816(acc[i][j], a1[i], &b0[2 * j]);
        }
    }

    const int g  = lane >> 2;
    const int t2 = (lane & 3) * 2;
    #pragma unroll
    for (int i = 0; i < 4; i++) {
        const int m = m0 + wm + i * 16 + g;
        #pragma unroll
        for (int j = 0; j < 4; j++) {
            const int n = n0 + wn + j * 8 + t2;
            atomicAdd(&C[(size_t)m * CH + n],     acc[i][j][0]);
            atomicAdd(&C[(size_t)m * CH + n + 1], acc[i][j][1]);
            atomicAdd(&C[(size_t)(m + 8) * CH + n],     acc[i][j][2]);
            atomicAdd(&C[(size_t)(m + 8) * CH + n + 1], acc[i][j][3]);
        }
    }
}

// ---------------------------------------------------------------------------
// Config C GEMM (wide tiles): 4 warps (64x64 warp tiles), 128 threads,
// block 128x128, k-chunk 32, 3-stage cp.async pipeline, 2 CTAs/SM.
// PA/PB planes (<=2). Terms: a0b0 (+a0b1 if PB==2) (+a1b0 if PA==2).
// OM: 0 = fp32 out, 1 = bf16 out, 2 = fp16 out.
//   C[m][n] = alpha*sum_k A(m,k)B(n,k) + bias_row[m] + bias_col[n] (+resid)
// ---------------------------------------------------------------------------
template<int PA, int PB, int OM>
__global__ __launch_bounds__(128, 2) void mma_gemm_c(
    const __nv_bfloat16* __restrict__ Ah, const __nv_bfloat16* __restrict__ Al,
    const __nv_bfloat16* __restrict__ Bh, const __nv_bfloat16* __restrict__ Bl,
    void* __restrict__ C0,
    int N, int K,
    size_t sA, size_t sB, size_t sC,
    const float* __restrict__ bias_row, size_t brs,
    const float* __restrict__ bias_col, size_t bcs,
    const float* __restrict__ resid, size_t sR, float alpha)
{
    constexpr int NTILES = PA + PB;
    constexpr int STAGE = NTILES * TILE_B;

    extern __shared__ __align__(1024) char smem[];
    const uint32_t sb = smem_u32(smem);

    const int tid  = threadIdx.x;
    const int lane = tid & 31;
    const int warp = tid >> 5;
    const int wm = (warp >> 1) * 64;
    const int wn = (warp & 1) * 64;
    const int m0 = blockIdx.y * 128;
    const int n0 = blockIdx.x * 128;
    const int bz = blockIdx.z;

    const __nv_bfloat16* gA[2];
    gA[0] = Ah + (size_t)bz * sA;
    gA[1] = (PA == 2) ? (Al + (size_t)bz * sA) : nullptr;
    const __nv_bfloat16* gB[2];
    gB[0] = Bh + (size_t)bz * sB;
    gB[1] = (PB == 2) ? (Bl + (size_t)bz * sB) : nullptr;

    auto issue = [&](int c) {
        const int stg = c % 3;
        const int k0 = c * 32;
        const uint32_t sbase = sb + stg * STAGE;
        #pragma unroll
        for (int i = 0; i < 4; i++) {
            const int idx = tid + i * 128;
            const int r = idx >> 2;
            const int seg = idx & 3;
            const uint32_t soff = r * (ROWS_H * 2) + seg * 16;
            const size_t ga = (size_t)(m0 + r) * K + k0 + seg * 8;
            const size_t gb = (size_t)(n0 + r) * K + k0 + seg * 8;
            #pragma unroll
            for (int t = 0; t < PA; t++)
                cp16(sbase + t * TILE_B + soff, gA[t] + ga);
            #pragma unroll
            for (int t = 0; t < PB; t++)
                cp16(sbase + (PA + t) * TILE_B + soff, gB[t] + gb);
        }
        cp_commit();
    };

    float acc[4][8][4] = {};

    const int nc = K >> 5;
    issue(0);
    issue(1);

    const int ar = lane & 15;
    const int ac0 = (lane >> 4) * 8;
    const int br = (lane & 7) + (lane >> 4) * 8;
    const int bc0 = ((lane >> 3) & 1) * 8;

    for (int c = 0; c < nc; c++) {
        cp_wait<1>();
        __syncthreads();
        if (c + 2 < nc) issue(c + 2);

        const int stg = c % 3;
        const __nv_bfloat16* TA0 = (const __nv_bfloat16*)(smem + stg * STAGE);
        const __nv_bfloat16* TA1 = (const __nv_bfloat16*)(smem + stg * STAGE + TILE_B);
        const __nv_bfloat16* TB0 = (const __nv_bfloat16*)(smem + stg * STAGE + PA * TILE_B);
        const __nv_bfloat16* TB1 = (const __nv_bfloat16*)(smem + stg * STAGE + (PA + 1) * TILE_B);

        #pragma unroll
        for (int kk = 0; kk < 32; kk += 16) {
            uint32_t a0[4][4], a1[4][4];
            uint32_t b0[16], b1[16];
            #pragma unroll
            for (int i = 0; i < 4; i++) {
                ldsm4(a0[i], smem_u32(TA0 + (wm + i * 16 + ar) * ROWS_H + kk + ac0));
                if (PA == 2)
                    ldsm4(a1[i], smem_u32(TA1 + (wm + i * 16 + ar) * ROWS_H + kk + ac0));
            }
            #pragma unroll
            for (int jj = 0; jj < 4; jj++) {
                ldsm4(&b0[4 * jj], smem_u32(TB0 + (wn + jj * 16 + br) * ROWS_H + kk + bc0));
                if (PB == 2)
                    ldsm4(&b1[4 * jj], smem_u32(TB1 + (wn + jj * 16 + br) * ROWS_H + kk + bc0));
            }
            #pragma unroll
            for (int i = 0; i < 4; i++)
                #pragma unroll
                for (int j = 0; j < 8; j++)
                    mma16816(acc[i][j], a0[i], &b0[2 * j]);
            if (PB == 2) {
                #pragma unroll
                for (int i = 0; i < 4; i++)
                    #pragma unroll
                    for (int j = 0; j < 8; j++)
                        mma16816(acc[i][j], a0[i], &b1[2 * j]);
            }
            if (PA == 2) {
                #pragma unroll
                for (int i = 0; i < 4; i++)
                    #pragma unroll
                    for (int j = 0; j < 8; j++)
                        mma16816(acc[i][j], a1[i], &b0[2 * j]);
            }
        }
    }

    const float* brp = bias_row ? bias_row + (size_t)bz * brs : nullptr;
    const float* bcp = bias_col ? bias_col + (size_t)bz * bcs : nullptr;
    const int g  = lane >> 2;
    const int t2 = (lane & 3) * 2;
    #pragma unroll
    for (int i = 0; i < 4; i++) {
        const int m = m0 + wm + i * 16 + g;
        const float br0 = brp ? brp[m] : 0.f;
        const float br1 = brp ? brp[m + 8] : 0.f;
        #pragma unroll
        for (int j = 0; j < 8; j++) {
            const int n = n0 + wn + j * 8 + t2;
            float bc0v = 0.f, bc1v = 0.f;
            if (bcp) { bc0v = bcp[n]; bc1v = bcp[n + 1]; }
            float v0 = acc[i][j][0] * alpha + br0 + bc0v;
            float v1 = acc[i][j][1] * alpha + br0 + bc1v;
            float v2 = acc[i][j][2] * alpha + br1 + bc0v;
            float v3 = acc[i][j][3] * alpha + br1 + bc1v;
            if (resid) {
                const float* rp = resid + (size_t)bz * sR;
                v0 += rp[(size_t)m * N + n];
                v1 += rp[(size_t)m * N + n + 1];
                v2 += rp[(size_t)(m + 8) * N + n];
                v3 += rp[(size_t)(m + 8) * N + n + 1];
            }
            if (OM == 0) {
                float* C = (float*)C0 + (size_t)bz * sC;
                float2 o0; o0.x = v0; o0.y = v1;
                float2 o1; o1.x = v2; o1.y = v3;
                *(float2*)&C[(size_t)m * N + n] = o0;
                *(float2*)&C[(size_t)(m + 8) * N + n] = o1;
            } else if (OM == 1) {
                __nv_bfloat16* Ch = (__nv_bfloat16*)C0 + (size_t)bz * sC;
                __nv_bfloat162 hh01, hh23;
                hh01.x = __float2bfloat16(v0); hh01.y = __float2bfloat16(v1);
                hh23.x = __float2bfloat16(v2); hh23.y = __float2bfloat16(v3);
                *(__nv_bfloat162*)&Ch[(size_t)m * N + n] = hh01;
                *(__nv_bfloat162*)&Ch[(size_t)(m + 8) * N + n] = hh23;
            } else {
                __half* Ch = (__half*)C0 + (size_t)bz * sC;
                __half2 h01 = __floats2half2_rn(v0, v1);
                __half2 h23 = __floats2half2_rn(v2, v3);
                *(__half2*)&Ch[(size_t)m * N + n] = h01;
                *(__half2*)&Ch[(size_t)(m + 8) * N + n] = h23;
            }
        }
    }
}

// ---------------------------------------------------------------------------
// Launch
// ---------------------------------------------------------------------------
extern "C" void kernel_launch(void* const* d_in, const int* in_sizes, int n_in,
                              void* d_out, int out_size)
{
    (void)in_sizes; (void)n_in; (void)out_size;
    const float* x    = (const float*)d_in[0];
    const float* gn_w = (const float*)d_in[1];
    const float* gn_b = (const float*)d_in[2];
    const float* wq   = (const float*)d_in[3];
    const float* bq   = (const float*)d_in[4];
    const float* wk   = (const float*)d_in[5];
    const float* bk   = (const float*)d_in[6];
    const float* wv   = (const float*)d_in[7];
    const float* bv   = (const float*)d_in[8];
    const float* wp   = (const float*)d_in[9];
    const float* bp   = (const float*)d_in[10];
    float* out = (float*)d_out;

    __nv_bfloat16 *Hn, *Hc, *U, *G, *P, *Wah, *Wal, *Th, *Tl, *W2h, *W2l;
    __half* S;
    float *TW, *rq, *rk, *cvec;
    cudaGetSymbolAddress((void**)&Hn, g_Hn);
    cudaGetSymbolAddress((void**)&Hc, g_Hc);
    cudaGetSymbolAddress((void**)&U,  g_U);
    cudaGetSymbolAddress((void**)&G,  g_G);
    cudaGetSymbolAddress((void**)&P,  g_P);
    cudaGetSymbolAddress((void**)&S,  g_S);
    cudaGetSymbolAddress((void**)&Wah, g_Wah); cudaGetSymbolAddress((void**)&Wal, g_Wal);
    cudaGetSymbolAddress((void**)&Th, g_Th);   cudaGetSymbolAddress((void**)&Tl, g_Tl);
    cudaGetSymbolAddress((void**)&W2h, g_W2h); cudaGetSymbolAddress((void**)&W2l, g_W2l);
    cudaGetSymbolAddress((void**)&TW, g_TW);
    cudaGetSymbolAddress((void**)&rq, g_rq);   cudaGetSymbolAddress((void**)&rk, g_rk);
    cudaGetSymbolAddress((void**)&cvec, g_cvec);

    const int SMC2 = 3 * 2 * TILE_B;  // 61440  (config C, 2 planes, 3 stages)
    const int SMC3 = 3 * 3 * TILE_B;  // 92160  (config C, 3 planes, 3 stages)
    const int SMTW = 2 * 4 * TILE_B;  // 81920  (tw_gemm)
    static bool attr_done = false;
    if (!attr_done) {
        cudaFuncSetAttribute((const void*)tw_gemm,                cudaFuncAttributeMaxDynamicSharedMemorySize, SMTW);
        cudaFuncSetAttribute((const void*)mma_gemm_c<1, 2, 1>,    cudaFuncAttributeMaxDynamicSharedMemorySize, SMC3);
        cudaFuncSetAttribute((const void*)mma_gemm_c<2, 1, 0>,    cudaFuncAttributeMaxDynamicSharedMemorySize, SMC3);
        cudaFuncSetAttribute((const void*)mma_gemm_c<1, 1, 2>,    cudaFuncAttributeMaxDynamicSharedMemorySize, SMC2);
        cudaFuncSetAttribute((const void*)mma_gemm_c<1, 1, 1>,    cudaFuncAttributeMaxDynamicSharedMemorySize, SMC2);
        attr_done = true;
    }

    const size_t sCN = (size_t)CH * NPIX;
    const size_t sNN = (size_t)NPIX * NPIX;
    const float scale = 0.044194173824159223f; // 512^-0.5

    // 0) pack weights + bias precomputes; zero TW accumulators
    pack_weights_kernel<<<4096, 256>>>(wq, wk, wv, wp);
    vecs_kernel<<<192, 256>>>(wq, wk, bq, bk, wp, bv, bp);
    cudaMemsetAsync(TW, 0, 2 * WSZ * sizeof(float));

    // 1) T | W2: split-K(x4) atomic GEMM, grid (4,4,8)
    {
        dim3 grid(4, 4, 8);
        tw_gemm<<<grid, 256, SMTW>>>(Wah, Wal, TW);
    }
    split_tw_kernel<<<2048, 256>>>(scale);

    // 2) GroupNorm -> Hn, Hc
    gn_kernel<<<BATCH * NG, 256>>>(x, gn_w, gn_b);
    rqk_kernel<<<4096, 256>>>(scale);

    // 3) U[b][n][c1] = sum_c2 Hn(n,c2)*T(c1,c2)  (2-term)
    {
        dim3 grid(CH / 128, NPIX / 128, BATCH);
        mma_gemm_c<1, 2, 1><<<grid, 128, SMC3>>>(Hn, nullptr, Th, Tl, U,
            CH, CH, sCN, 0, sCN, nullptr, 0, nullptr, 0, nullptr, 0, 1.f);
    }
    // 4) S[b][q][k] = sum_c1 Hn(q,c1)*U(k,c1) + rq[q] + rk[k]  -> fp16
    {
        dim3 grid(NPIX / 128, NPIX / 128, BATCH);
        mma_gemm_c<1, 1, 2><<<grid, 128, SMC2>>>(Hn, nullptr, U, nullptr, S,
            NPIX, CH, sCN, sCN, sNN, rq, NPIX, rk, NPIX, nullptr, 0, 1.f);
    }
    // 5) softmax fp16 -> P bf16
    softmax_kernel<<<BATCH * NPIX, 256>>>(S, P);

    // 6) G[b][q][c] = sum_k P(q,k)*Hc(c,k)
    {
        dim3 grid(CH / 128, NPIX / 128, BATCH);
        mma_gemm_c<1, 1, 1><<<grid, 128, SMC2>>>(P, nullptr, Hc, nullptr, G,
            CH, NPIX, sNN, sCN, sCN, nullptr, 0, nullptr, 0, nullptr, 0, 1.f);
    }
    // 7) out[b][co][n] = sum_c W2(co,c)*G(n,c) + cvec[co] + x
    {
        dim3 grid(NPIX / 128, CH / 128, BATCH);
        mma_gemm_c<2, 1, 0><<<grid, 128, SMC3>>>(W2h, W2l, G, nullptr, out,
            NPIX, CH, 0, sCN, sCN, cvec, 0, nullptr, 0, x, sCN, 1.f);
    }
}

// round 13
// speedup vs baseline: 2.0885x; 1.1299x over previous
#include <cuda_runtime.h>
#include <cuda_fp16.h>
#include <cstdint>
#include <cstddef>

#define BATCH 32
#define CH    512
#define NPIX  1024
#define NG    32
#define CPG   16
#define EPS   1e-6f

#define SZ_CN ((size_t)BATCH * NPIX * CH)
#define SZ_NN ((size_t)BATCH * NPIX * NPIX)
#define WSZ   ((size_t)CH * CH)

// ---------------------------------------------------------------------------
// Scratch (all activations fp16)
// ---------------------------------------------------------------------------
__device__ __half g_Hn[SZ_CN];    // H [b][n][c]
__device__ __half g_Hc[SZ_CN];    // H [b][c][n]
__device__ __half g_U [SZ_CN];    // U = H.T^T [b][n][c1]
__device__ __half g_G [SZ_CN];    // G = P.H  [b][q][c]
__device__ __half g_S [SZ_NN];    // logits fp16
__device__ __half g_P [SZ_NN];    // probs fp16
// packed weights fp16 hi/lo: [0]=WqT, [1]=Wp(nat), [2]=WkT, [3]=WvT
__device__ __half g_Wah[4 * WSZ], g_Wal[4 * WSZ];
__device__ float g_TW[2 * WSZ];                     // Traw | W2raw (atomic acc)
__device__ __half g_Th[WSZ];                        // T = scale*Wq^T.Wk (fp16)
__device__ __half g_W2h[WSZ];                       // W2 = Wp.Wv (fp16)
__device__ float g_vv[2 * CH + 1];
__device__ float g_cvec[CH];
__device__ float g_rq[(size_t)BATCH * NPIX];
__device__ float g_rk[(size_t)BATCH * NPIX];

// ---------------------------------------------------------------------------
// Helpers
// ---------------------------------------------------------------------------
__device__ __forceinline__ uint32_t smem_u32(const void* p) {
    return (uint32_t)__cvta_generic_to_shared(p);
}
__device__ __forceinline__ void ldsm4(uint32_t r[4], uint32_t a) {
    asm volatile("ldmatrix.sync.aligned.m8n8.x4.shared.b16 {%0,%1,%2,%3}, [%4];"
        : "=r"(r[0]), "=r"(r[1]), "=r"(r[2]), "=r"(r[3]) : "r"(a));
}
__device__ __forceinline__ void mma16816(float d[4], const uint32_t a[4], const uint32_t* b) {
    asm volatile(
        "mma.sync.aligned.m16n8k16.row.col.f32.f16.f16.f32 "
        "{%0,%1,%2,%3}, {%4,%5,%6,%7}, {%8,%9}, {%0,%1,%2,%3};"
        : "+f"(d[0]), "+f"(d[1]), "+f"(d[2]), "+f"(d[3])
        : "r"(a[0]), "r"(a[1]), "r"(a[2]), "r"(a[3]), "r"(b[0]), "r"(b[1]));
}
__device__ __forceinline__ void cp16(uint32_t s, const void* g) {
    asm volatile("cp.async.cg.shared.global [%0], [%1], 16;" :: "r"(s), "l"(g));
}
__device__ __forceinline__ void cp_commit() {
    asm volatile("cp.async.commit_group;" ::: "memory");
}
template<int n>
__device__ __forceinline__ void cp_wait() {
    asm volatile("cp.async.wait_group %0;" :: "n"(n) : "memory");
}
__device__ __forceinline__ void splitf(float x, __half& h, __half& l) {
    h = __float2half(x);
    l = __float2half(x - __half2float(h));
}

// ---------------------------------------------------------------------------
// Pack into unified layout: [0]=WqT, [1]=Wp natural, [2]=WkT, [3]=WvT
// ---------------------------------------------------------------------------
__global__ __launch_bounds__(256) void pack_weights_kernel(
    const float* __restrict__ wq, const float* __restrict__ wk,
    const float* __restrict__ wv, const float* __restrict__ wp)
{
    int i = blockIdx.x * 256 + threadIdx.x;
    int t = i >> 18;
    int j = i & (int)(WSZ - 1);
    float v;
    if (t == 1) {
        v = wp[j];
    } else {
        int c = j >> 9, co = j & 511;
        const float* src = (t == 0) ? wq : (t == 2) ? wk : wv;
        v = src[co * CH + c];
    }
    __half h, l;
    splitf(v, h, l);
    g_Wah[i] = h; g_Wal[i] = l;
}

// convert fp32 TW -> single fp16 planes; T gets alpha=scale folded in
__global__ __launch_bounds__(256) void split_tw_kernel(float scale)
{
    int i = blockIdx.x * 256 + threadIdx.x;
    if (i < (int)WSZ) {
        g_Th[i] = __float2half(g_TW[i] * scale);
    } else {
        g_W2h[i - (int)WSZ] = __float2half(g_TW[i]);
    }
}

// warp-per-output: v1 = Wk^T.bq, v2 = Wq^T.bk, bq.bk ; cvec = Wp.bv + bp
__global__ __launch_bounds__(256) void vecs_kernel(
    const float* __restrict__ wq, const float* __restrict__ wk,
    const float* __restrict__ bq, const float* __restrict__ bk,
    const float* __restrict__ wp, const float* __restrict__ bv,
    const float* __restrict__ bp)
{
    const int gw = (blockIdx.x * 256 + threadIdx.x) >> 5;
    const int lane = threadIdx.x & 31;
    float s = 0.f;
    if (gw < CH) {
        const int c = gw;
        #pragma unroll
        for (int j = 0; j < 16; j++) {
            int co = lane + j * 32;
            s += wk[co * CH + c] * bq[co];
        }
        #pragma unroll
        for (int o = 16; o > 0; o >>= 1) s += __shfl_xor_sync(0xFFFFFFFF, s, o);
        if (lane == 0) g_vv[c] = s;
        if (gw == 0) {
            float sc = 0.f;
            #pragma unroll
            for (int j = 0; j < 16; j++) {
                int co = lane + j * 32;
                sc += bq[co] * bk[co];
            }
            #pragma unroll
            for (int o = 16; o > 0; o >>= 1) sc += __shfl_xor_sync(0xFFFFFFFF, sc, o);
            if (lane == 0) g_vv[2 * CH] = sc;
        }
    } else if (gw < 2 * CH) {
        const int c = gw - CH;
        #pragma unroll
        for (int j = 0; j < 16; j++) {
            int co = lane + j * 32;
            s += wq[co * CH + c] * bk[co];
        }
        #pragma unroll
        for (int o = 16; o > 0; o >>= 1) s += __shfl_xor_sync(0xFFFFFFFF, s, o);
        if (lane == 0) g_vv[CH + c] = s;
    } else {
        const int co = gw - 2 * CH;
        #pragma unroll
        for (int j = 0; j < 16; j++) {
            int cm = lane + j * 32;
            s += wp[co * CH + cm] * bv[cm];
        }
        #pragma unroll
        for (int o = 16; o > 0; o >>= 1) s += __shfl_xor_sync(0xFFFFFFFF, s, o);
        if (lane == 0) g_cvec[co] = s + bp[co];
    }
}

// rq[b][n] = scale*(v2.h + bqbk), rk[b][n] = scale*(v1.h)
__global__ __launch_bounds__(256) void rqk_kernel(float scale)
{
    const int row = blockIdx.x * 8 + (threadIdx.x >> 5);
    const int lane = threadIdx.x & 31;
    const __half* h = g_Hn + (size_t)row * CH;
    float d1 = 0.f, d2 = 0.f;
    #pragma unroll
    for (int j = 0; j < 16; j++) {
        int c = lane + j * 32;
        float hv = __half2float(h[c]);
        d1 += g_vv[c] * hv;
        d2 += g_vv[CH + c] * hv;
    }
    #pragma unroll
    for (int o = 16; o > 0; o >>= 1) {
        d1 += __shfl_xor_sync(0xFFFFFFFF, d1, o);
        d2 += __shfl_xor_sync(0xFFFFFFFF, d2, o);
    }
    if (lane == 0) {
        g_rq[row] = scale * (d2 + g_vv[2 * CH]);
        g_rk[row] = scale * d1;
    }
}

// ---------------------------------------------------------------------------
// GroupNorm -> Hn [b][n][c], Hc [b][c][n]  (fp16)
// ---------------------------------------------------------------------------
__global__ __launch_bounds__(256) void gn_kernel(
    const float* __restrict__ x, const float* __restrict__ w,
    const float* __restrict__ b)
{
    const int bg = blockIdx.x;
    const int batch = bg >> 5;
    const int g = bg & 31;
    const int tid = threadIdx.x;
    const float* xp = x + ((size_t)batch * CH + (size_t)g * CPG) * NPIX;

    float s = 0.f, ss = 0.f;
    for (int i = tid; i < CPG * NPIX; i += 256) {
        float v = xp[i];
        s += v; ss += v * v;
    }
    __shared__ float sh_s[256], sh_ss[256];
    sh_s[tid] = s; sh_ss[tid] = ss;
    __syncthreads();
    for (int st = 128; st > 0; st >>= 1) {
        if (tid < st) { sh_s[tid] += sh_s[tid + st]; sh_ss[tid] += sh_ss[tid + st]; }
        __syncthreads();
    }
    const float mean = sh_s[0] * (1.0f / (CPG * NPIX));
    const float var  = sh_ss[0] * (1.0f / (CPG * NPIX)) - mean * mean;
    const float inv  = rsqrtf(var + EPS);

    __shared__ float st[512][17];

    for (int half = 0; half < 2; half++) {
        for (int i = tid; i < CPG * 512; i += 256) {
            int c16 = i >> 9;
            int nl  = i & 511;
            int c   = g * CPG + c16;
            float v = (xp[c16 * NPIX + half * 512 + nl] - mean) * inv;
            v = v * w[c] + b[c];
            st[nl][c16] = v;
            g_Hc[((size_t)batch * CH + c) * NPIX + half * 512 + nl] = __float2half(v);
        }
        __syncthreads();
        size_t dst = ((size_t)batch * NPIX + half * 512) * CH + g * CPG;
        for (int i = tid; i < CPG * 512; i += 256) {
            int nl = i >> 4;
            int c16 = i & 15;
            g_Hn[dst + (size_t)nl * CH + c16] = __float2half(st[nl][c16]);
        }
        __syncthreads();
    }
}

// ---------------------------------------------------------------------------
// Row softmax fp16 logits -> fp16 probs
// ---------------------------------------------------------------------------
__global__ __launch_bounds__(256) void softmax_kernel(
    const __half* __restrict__ S, __half* __restrict__ Sp)
{
    const uint2* p = (const uint2*)(S + (size_t)blockIdx.x * NPIX);
    uint2* po = (uint2*)(Sp + (size_t)blockIdx.x * NPIX);
    const int t = threadIdx.x;
    const int lane = t & 31;
    const int wid = t >> 5;

    uint2 raw = p[t];
    float2 f01 = __half22float2(*reinterpret_cast<__half2*>(&raw.x));
    float2 f23 = __half22float2(*reinterpret_cast<__half2*>(&raw.y));
    float4 v; v.x = f01.x; v.y = f01.y; v.z = f23.x; v.w = f23.y;

    float mx = fmaxf(fmaxf(v.x, v.y), fmaxf(v.z, v.w));
    #pragma unroll
    for (int o = 16; o > 0; o >>= 1)
        mx = fmaxf(mx, __shfl_xor_sync(0xFFFFFFFF, mx, o));
    __shared__ float red[8];
    if (lane == 0) red[wid] = mx;
    __syncthreads();
    mx = red[0];
    #pragma unroll
    for (int i = 1; i < 8; i++) mx = fmaxf(mx, red[i]);
    __syncthreads();

    v.x = __expf(v.x - mx); v.y = __expf(v.y - mx);
    v.z = __expf(v.z - mx); v.w = __expf(v.w - mx);
    float sum = v.x + v.y + v.z + v.w;
    #pragma unroll
    for (int o = 16; o > 0; o >>= 1)
        sum += __shfl_xor_sync(0xFFFFFFFF, sum, o);
    if (lane == 0) red[wid] = sum;
    __syncthreads();
    sum = 0.f;
    #pragma unroll
    for (int i = 0; i < 8; i++) sum += red[i];
    const float inv = 1.0f / sum;

    __half2 lo = __floats2half2_rn(v.x * inv, v.y * inv);
    __half2 hi = __floats2half2_rn(v.z * inv, v.w * inv);
    uint2 o;
    o.x = *reinterpret_cast<uint32_t*>(&lo);
    o.y = *reinterpret_cast<uint32_t*>(&hi);
    po[t] = o;
}

#define TILE_B   10240
#define ROWS_H   40

// ---------------------------------------------------------------------------
// T/W2 precompute GEMM: split-K(x4), atomicAdd epilogue, fp16 hi/lo 3-term.
// grid (4,4,8): z>>2 = matrix (0:T, 1:W2), z&3 = K-slice of 128.
// ---------------------------------------------------------------------------
__global__ __launch_bounds__(256, 2) void tw_gemm(
    const __half* __restrict__ Wah, const __half* __restrict__ Wal,
    float* __restrict__ TW)
{
    constexpr int STAGE = 4 * TILE_B;

    extern __shared__ __align__(1024) char smem[];
    const uint32_t sb = smem_u32(smem);

    const int tid  = threadIdx.x;
    const int lane = tid & 31;
    const int warp = tid >> 5;
    const int wm = (warp >> 2) * 64;
    const int wn = (warp & 3) * 32;
    const int m0 = blockIdx.y * 128;
    const int n0 = blockIdx.x * 128;
    const int mat = blockIdx.z >> 2;
    const int kbase = (blockIdx.z & 3) * 128;

    const __half* gA[2] = { Wah + (size_t)mat * WSZ, Wal + (size_t)mat * WSZ };
    const __half* gB[2] = { Wah + (size_t)(mat + 2) * WSZ, Wal + (size_t)(mat + 2) * WSZ };
    float* C = TW + (size_t)mat * WSZ;

    auto issue = [&](int c) {
        const int stg = c & 1;
        const int k0 = kbase + c * 32;
        const uint32_t sbase = sb + stg * STAGE;
        #pragma unroll
        for (int i = 0; i < 2; i++) {
            const int idx = tid + i * 256;
            const int r = idx >> 2;
            const int seg = idx & 3;
            const uint32_t soff = r * (ROWS_H * 2) + seg * 16;
            const size_t ga = (size_t)(m0 + r) * CH + k0 + seg * 8;
            const size_t gb = (size_t)(n0 + r) * CH + k0 + seg * 8;
            cp16(sbase + soff, gA[0] + ga);
            cp16(sbase + TILE_B + soff, gA[1] + ga);
            cp16(sbase + 2 * TILE_B + soff, gB[0] + gb);
            cp16(sbase + 3 * TILE_B + soff, gB[1] + gb);
        }
        cp_commit();
    };

    float acc[4][4][4] = {};

    issue(0);

    const int ar = lane & 15;
    const int ac0 = (lane >> 4) * 8;
    const int br = (lane & 7) + (lane >> 4) * 8;
    const int bc0 = ((lane >> 3) & 1) * 8;

    for (int c = 0; c < 4; c++) {
        cp_wait<0>();
        __syncthreads();
        if (c + 1 < 4) issue(c + 1);

        const int stg = c & 1;
        const __half* TA0 = (const __half*)(smem + stg * STAGE);
        const __half* TA1 = (const __half*)(smem + stg * STAGE + TILE_B);
        const __half* TB0 = (const __half*)(smem + stg * STAGE + 2 * TILE_B);
        const __half* TB1 = (const __half*)(smem + stg * STAGE + 3 * TILE_B);

        #pragma unroll
        for (int kk = 0; kk < 32; kk += 16) {
            uint32_t a0[4][4], a1[4][4];
            uint32_t b0[8], b1[8];
            #pragma unroll
            for (int i = 0; i < 4; i++) {
                ldsm4(a0[i], smem_u32(TA0 + (wm + i * 16 + ar) * ROWS_H + kk + ac0));
                ldsm4(a1[i], smem_u32(TA1 + (wm + i * 16 + ar) * ROWS_H + kk + ac0));
            }
            #pragma unroll
            for (int jj = 0; jj < 2; jj++) {
                ldsm4(&b0[4 * jj], smem_u32(TB0 + (wn + jj * 16 + br) * ROWS_H + kk + bc0));
                ldsm4(&b1[4 * jj], smem_u32(TB1 + (wn + jj * 16 + br) * ROWS_H + kk + bc0));
            }
            #pragma unroll
            for (int i = 0; i < 4; i++)
                #pragma unroll
                for (int j = 0; j < 4; j++)
                    mma16816(acc[i][j], a0[i], &b0[2 * j]);
            #pragma unroll
            for (int i = 0; i < 4; i++)
                #pragma unroll
                for (int j = 0; j < 4; j++)
                    mma16816(acc[i][j], a0[i], &b1[2 * j]);
            #pragma unroll
            for (int i = 0; i < 4; i++)
                #pragma unroll
                for (int j = 0; j < 4; j++)
                    mma16816(acc[i][j], a1[i], &b0[2 * j]);
        }
    }

    const int g  = lane >> 2;
    const int t2 = (lane & 3) * 2;
    #pragma unroll
    for (int i = 0; i < 4; i++) {
        const int m = m0 + wm + i * 16 + g;
        #pragma unroll
        for (int j = 0; j < 4; j++) {
            const int n = n0 + wn + j * 8 + t2;
            atomicAdd(&C[(size_t)m * CH + n],     acc[i][j][0]);
            atomicAdd(&C[(size_t)m * CH + n + 1], acc[i][j][1]);
            atomicAdd(&C[(size_t)(m + 8) * CH + n],     acc[i][j][2]);
            atomicAdd(&C[(size_t)(m + 8) * CH + n + 1], acc[i][j][3]);
        }
    }
}

// ---------------------------------------------------------------------------
// Config C GEMM (wide tiles): 4 warps (64x64 warp tiles), 128 threads,
// block 128x128, k-chunk 32, 3-stage cp.async, 2 CTAs/SM. 1-term fp16.
// OM: 0 = fp32 out, 2 = fp16 out.
//   C[m][n] = alpha*sum_k A(m,k)B(n,k) + bias_row[m] + bias_col[n] (+resid)
// ---------------------------------------------------------------------------
template<int OM>
__global__ __launch_bounds__(128, 2) void mma_gemm_c(
    const __half* __restrict__ Ah, const __half* __restrict__ Bh,
    void* __restrict__ C0,
    int N, int K,
    size_t sA, size_t sB, size_t sC,
    const float* __restrict__ bias_row, size_t brs,
    const float* __restrict__ bias_col, size_t bcs,
    const float* __restrict__ resid, size_t sR, float alpha)
{
    constexpr int STAGE = 2 * TILE_B;

    extern __shared__ __align__(1024) char smem[];
    const uint32_t sb = smem_u32(smem);

    const int tid  = threadIdx.x;
    const int lane = tid & 31;
    const int warp = tid >> 5;
    const int wm = (warp >> 1) * 64;
    const int wn = (warp & 1) * 64;
    const int m0 = blockIdx.y * 128;
    const int n0 = blockIdx.x * 128;
    const int bz = blockIdx.z;

    const __half* gA = Ah + (size_t)bz * sA;
    const __half* gB = Bh + (size_t)bz * sB;

    auto issue = [&](int c) {
        const int stg = c % 3;
        const int k0 = c * 32;
        const uint32_t sbase = sb + stg * STAGE;
        #pragma unroll
        for (int i = 0; i < 4; i++) {
            const int idx = tid + i * 128;
            const int r = idx >> 2;
            const int seg = idx & 3;
            const uint32_t soff = r * (ROWS_H * 2) + seg * 16;
            cp16(sbase + soff, gA + (size_t)(m0 + r) * K + k0 + seg * 8);
            cp16(sbase + TILE_B + soff, gB + (size_t)(n0 + r) * K + k0 + seg * 8);
        }
        cp_commit();
    };

    float acc[4][8][4] = {};

    const int nc = K >> 5;
    issue(0);
    issue(1);

    const int ar = lane & 15;
    const int ac0 = (lane >> 4) * 8;
    const int br = (lane & 7) + (lane >> 4) * 8;
    const int bc0 = ((lane >> 3) & 1) * 8;

    for (int c = 0; c < nc; c++) {
        cp_wait<1>();
        __syncthreads();
        if (c + 2 < nc) issue(c + 2);

        const int stg = c % 3;
        const __half* TA = (const __half*)(smem + stg * STAGE);
        const __half* TB = (const __half*)(smem + stg * STAGE + TILE_B);

        #pragma unroll
        for (int kk = 0; kk < 32; kk += 16) {
            uint32_t a0[4][4];
            uint32_t b0[16];
            #pragma unroll
            for (int i = 0; i < 4; i++)
                ldsm4(a0[i], smem_u32(TA + (wm + i * 16 + ar) * ROWS_H + kk + ac0));
            #pragma unroll
            for (int jj = 0; jj < 4; jj++)
                ldsm4(&b0[4 * jj], smem_u32(TB + (wn + jj * 16 + br) * ROWS_H + kk + bc0));
            #pragma unroll
            for (int i = 0; i < 4; i++)
                #pragma unroll
                for (int j = 0; j < 8; j++)
                    mma16816(acc[i][j], a0[i], &b0[2 * j]);
        }
    }

    const float* brp = bias_row ? bias_row + (size_t)bz * brs : nullptr;
    const float* bcp = bias_col ? bias_col + (size_t)bz * bcs : nullptr;
    const int g  = lane >> 2;
    const int t2 = (lane & 3) * 2;
    #pragma unroll
    for (int i = 0; i < 4; i++) {
        const int m = m0 + wm + i * 16 + g;
        const float br0 = brp ? brp[m] : 0.f;
        const float br1 = brp ? brp[m + 8] : 0.f;
        #pragma unroll
        for (int j = 0; j < 8; j++) {
            const int n = n0 + wn + j * 8 + t2;
            float bc0v = 0.f, bc1v = 0.f;
            if (bcp) { bc0v = bcp[n]; bc1v = bcp[n + 1]; }
            float v0 = acc[i][j][0] * alpha + br0 + bc0v;
            float v1 = acc[i][j][1] * alpha + br0 + bc1v;
            float v2 = acc[i][j][2] * alpha + br1 + bc0v;
            float v3 = acc[i][j][3] * alpha + br1 + bc1v;
            if (resid) {
                const float* rp = resid + (size_t)bz * sR;
                v0 += rp[(size_t)m * N + n];
                v1 += rp[(size_t)m * N + n + 1];
                v2 += rp[(size_t)(m + 8) * N + n];
                v3 += rp[(size_t)(m + 8) * N + n + 1];
            }
            if (OM == 0) {
                float* C = (float*)C0 + (size_t)bz * sC;
                float2 o0; o0.x = v0; o0.y = v1;
                float2 o1; o1.x = v2; o1.y = v3;
                *(float2*)&C[(size_t)m * N + n] = o0;
                *(float2*)&C[(size_t)(m + 8) * N + n] = o1;
            } else {
                __half* Ch = (__half*)C0 + (size_t)bz * sC;
                __half2 h01 = __floats2half2_rn(v0, v1);
                __half2 h23 = __floats2half2_rn(v2, v3);
                *(__half2*)&Ch[(size_t)m * N + n] = h01;
                *(__half2*)&Ch[(size_t)(m + 8) * N + n] = h23;
            }
        }
    }
}

// ---------------------------------------------------------------------------
// Launch
// ---------------------------------------------------------------------------
extern "C" void kernel_launch(void* const* d_in, const int* in_sizes, int n_in,
                              void* d_out, int out_size)
{
    (void)in_sizes; (void)n_in; (void)out_size;
    const float* x    = (const float*)d_in[0];
    const float* gn_w = (const float*)d_in[1];
    const float* gn_b = (const float*)d_in[2];
    const float* wq   = (const float*)d_in[3];
    const float* bq   = (const float*)d_in[4];
    const float* wk   = (const float*)d_in[5];
    const float* bk   = (const float*)d_in[6];
    const float* wv   = (const float*)d_in[7];
    const float* bv   = (const float*)d_in[8];
    const float* wp   = (const float*)d_in[9];
    const float* bp   = (const float*)d_in[10];
    float* out = (float*)d_out;

    __half *Hn, *Hc, *U, *G, *P, *S, *Wah, *Wal, *Th, *W2h;
    float *TW, *rq, *rk, *cvec;
    cudaGetSymbolAddress((void**)&Hn, g_Hn);
    cudaGetSymbolAddress((void**)&Hc, g_Hc);
    cudaGetSymbolAddress((void**)&U,  g_U);
    cudaGetSymbolAddress((void**)&G,  g_G);
    cudaGetSymbolAddress((void**)&P,  g_P);
    cudaGetSymbolAddress((void**)&S,  g_S);
    cudaGetSymbolAddress((void**)&Wah, g_Wah); cudaGetSymbolAddress((void**)&Wal, g_Wal);
    cudaGetSymbolAddress((void**)&Th, g_Th);   cudaGetSymbolAddress((void**)&W2h, g_W2h);
    cudaGetSymbolAddress((void**)&TW, g_TW);
    cudaGetSymbolAddress((void**)&rq, g_rq);   cudaGetSymbolAddress((void**)&rk, g_rk);
    cudaGetSymbolAddress((void**)&cvec, g_cvec);

    const int SMC2 = 3 * 2 * TILE_B;  // 61440  (config C, 3-stage)
    const int SMTW = 2 * 4 * TILE_B;  // 81920  (tw_gemm)
    static bool attr_done = false;
    if (!attr_done) {
        cudaFuncSetAttribute((const void*)tw_gemm,        cudaFuncAttributeMaxDynamicSharedMemorySize, SMTW);
        cudaFuncSetAttribute((const void*)mma_gemm_c<0>,  cudaFuncAttributeMaxDynamicSharedMemorySize, SMC2);
        cudaFuncSetAttribute((const void*)mma_gemm_c<2>,  cudaFuncAttributeMaxDynamicSharedMemorySize, SMC2);
        attr_done = true;
    }

    const size_t sCN = (size_t)CH * NPIX;
    const size_t sNN = (size_t)NPIX * NPIX;
    const float scale = 0.044194173824159223f; // 512^-0.5

    // 0) pack weights + bias precomputes; zero TW accumulators
    pack_weights_kernel<<<4096, 256>>>(wq, wk, wv, wp);
    vecs_kernel<<<192, 256>>>(wq, wk, bq, bk, wp, bv, bp);
    cudaMemsetAsync(TW, 0, 2 * WSZ * sizeof(float));

    // 1) T | W2: split-K(x4) atomic GEMM, fp16 hi/lo 3-term
    {
        dim3 grid(4, 4, 8);
        tw_gemm<<<grid, 256, SMTW>>>(Wah, Wal, TW);
    }
    split_tw_kernel<<<2048, 256>>>(scale);

    // 2) GroupNorm -> Hn, Hc (fp16)
    gn_kernel<<<BATCH * NG, 256>>>(x, gn_w, gn_b);
    rqk_kernel<<<4096, 256>>>(scale);

    // 3) U[b][n][c1] = sum_c2 Hn(n,c2)*T(c1,c2)  (1-term fp16)
    {
        dim3 grid(CH / 128, NPIX / 128, BATCH);
        mma_gemm_c<2><<<grid, 128, SMC2>>>(Hn, Th, U,
            CH, CH, sCN, 0, sCN, nullptr, 0, nullptr, 0, nullptr, 0, 1.f);
    }
    // 4) S[b][q][k] = sum_c1 Hn(q,c1)*U(k,c1) + rq[q] + rk[k] -> fp16
    {
        dim3 grid(NPIX / 128, NPIX / 128, BATCH);
        mma_gemm_c<2><<<grid, 128, SMC2>>>(Hn, U, S,
            NPIX, CH, sCN, sCN, sNN, rq, NPIX, rk, NPIX, nullptr, 0, 1.f);
    }
    // 5) softmax fp16 -> P fp16
    softmax_kernel<<<BATCH * NPIX, 256>>>(S, P);

    // 6) G[b][q][c] = sum_k P(q,k)*Hc(c,k)  (1-term fp16)
    {
        dim3 grid(CH / 128, NPIX / 128, BATCH);
        mma_gemm_c<2><<<grid, 128, SMC2>>>(P, Hc, G,
            CH, NPIX, sNN, sCN, sCN, nullptr, 0, nullptr, 0, nullptr, 0, 1.f);
    }
    // 7) out[b][co][n] = sum_c W2(co,c)*G(n,c) + cvec[co] + x  (1-term fp16)
    {
        dim3 grid(NPIX / 128, CH / 128, BATCH);
        mma_gemm_c<0><<<grid, 128, SMC2>>>(W2h, G, out,
            NPIX, CH, 0, sCN, sCN, cvec, 0, nullptr, 0, x, sCN, 1.f);
    }
}

// round 14
// speedup vs baseline: 2.2645x; 1.0843x over previous
#include <cuda_runtime.h>
#include <cuda_fp16.h>
#include <cstdint>
#include <cstddef>

#define BATCH 32
#define CH    512
#define NPIX  1024
#define NG    32
#define CPG   16
#define EPS   1e-6f

#define SZ_CN ((size_t)BATCH * NPIX * CH)
#define SZ_NN ((size_t)BATCH * NPIX * NPIX)
#define WSZ   ((size_t)CH * CH)

// ---------------------------------------------------------------------------
// Scratch (all activations fp16)
// ---------------------------------------------------------------------------
__device__ __half g_Hn[SZ_CN];    // H [b][n][c]
__device__ __half g_Hc[SZ_CN];    // H [b][c][n]
__device__ __half g_U [SZ_CN];    // U = H.T^T [b][n][c1]
__device__ __half g_G [SZ_CN];    // G = P.H  [b][q][c]
__device__ __half g_S [SZ_NN];    // logits fp16
__device__ __half g_P [SZ_NN];    // probs fp16
// packed weights fp16 hi/lo: [0]=WqT, [1]=Wp(nat), [2]=WkT, [3]=WvT
__device__ __half g_Wah[4 * WSZ], g_Wal[4 * WSZ];
__device__ float g_TW[2 * WSZ];                     // Traw | W2raw (atomic acc)
__device__ __half g_Th[WSZ];                        // T = scale*Wq^T.Wk (fp16)
__device__ __half g_W2h[WSZ];                       // W2 = Wp.Wv (fp16)
__device__ float g_vv[2 * CH + 1];
__device__ float g_cvec[CH];
__device__ float g_rq[(size_t)BATCH * NPIX];
__device__ float g_rk[(size_t)BATCH * NPIX];

// ---------------------------------------------------------------------------
// Helpers
// ---------------------------------------------------------------------------
__device__ __forceinline__ uint32_t smem_u32(const void* p) {
    return (uint32_t)__cvta_generic_to_shared(p);
}
__device__ __forceinline__ void ldsm4(uint32_t r[4], uint32_t a) {
    asm volatile("ldmatrix.sync.aligned.m8n8.x4.shared.b16 {%0,%1,%2,%3}, [%4];"
        : "=r"(r[0]), "=r"(r[1]), "=r"(r[2]), "=r"(r[3]) : "r"(a));
}
__device__ __forceinline__ void mma16816(float d[4], const uint32_t a[4], const uint32_t* b) {
    asm volatile(
        "mma.sync.aligned.m16n8k16.row.col.f32.f16.f16.f32 "
        "{%0,%1,%2,%3}, {%4,%5,%6,%7}, {%8,%9}, {%0,%1,%2,%3};"
        : "+f"(d[0]), "+f"(d[1]), "+f"(d[2]), "+f"(d[3])
        : "r"(a[0]), "r"(a[1]), "r"(a[2]), "r"(a[3]), "r"(b[0]), "r"(b[1]));
}
__device__ __forceinline__ void cp16(uint32_t s, const void* g) {
    asm volatile("cp.async.cg.shared.global [%0], [%1], 16;" :: "r"(s), "l"(g));
}
__device__ __forceinline__ void cp_commit() {
    asm volatile("cp.async.commit_group;" ::: "memory");
}
template<int n>
__device__ __forceinline__ void cp_wait() {
    asm volatile("cp.async.wait_group %0;" :: "n"(n) : "memory");
}
__device__ __forceinline__ void splitf(float x, __half& h, __half& l) {
    h = __float2half(x);
    l = __float2half(x - __half2float(h));
}

// ---------------------------------------------------------------------------
// Pack into unified layout: [0]=WqT, [1]=Wp natural, [2]=WkT, [3]=WvT
// Also zeros the TW accumulators (first 2*WSZ threads).
// ---------------------------------------------------------------------------
__global__ __launch_bounds__(256) void pack_weights_kernel(
    const float* __restrict__ wq, const float* __restrict__ wk,
    const float* __restrict__ wv, const float* __restrict__ wp)
{
    int i = blockIdx.x * 256 + threadIdx.x;
    if (i < (int)(2 * WSZ)) g_TW[i] = 0.f;
    int t = i >> 18;
    int j = i & (int)(WSZ - 1);
    float v;
    if (t == 1) {
        v = wp[j];
    } else {
        int c = j >> 9, co = j & 511;
        const float* src = (t == 0) ? wq : (t == 2) ? wk : wv;
        v = src[co * CH + c];
    }
    __half h, l;
    splitf(v, h, l);
    g_Wah[i] = h; g_Wal[i] = l;
}

// convert fp32 TW -> single fp16 planes; T gets alpha=scale folded in
__global__ __launch_bounds__(256) void split_tw_kernel(float scale)
{
    int i = blockIdx.x * 256 + threadIdx.x;
    if (i < (int)WSZ) {
        g_Th[i] = __float2half(g_TW[i] * scale);
    } else {
        g_W2h[i - (int)WSZ] = __float2half(g_TW[i]);
    }
}

// warp-per-output: v1 = Wk^T.bq, v2 = Wq^T.bk, bq.bk ; cvec = Wp.bv + bp
__global__ __launch_bounds__(256) void vecs_kernel(
    const float* __restrict__ wq, const float* __restrict__ wk,
    const float* __restrict__ bq, const float* __restrict__ bk,
    const float* __restrict__ wp, const float* __restrict__ bv,
    const float* __restrict__ bp)
{
    const int gw = (blockIdx.x * 256 + threadIdx.x) >> 5;
    const int lane = threadIdx.x & 31;
    float s = 0.f;
    if (gw < CH) {
        const int c = gw;
        #pragma unroll
        for (int j = 0; j < 16; j++) {
            int co = lane + j * 32;
            s += wk[co * CH + c] * bq[co];
        }
        #pragma unroll
        for (int o = 16; o > 0; o >>= 1) s += __shfl_xor_sync(0xFFFFFFFF, s, o);
        if (lane == 0) g_vv[c] = s;
        if (gw == 0) {
            float sc = 0.f;
            #pragma unroll
            for (int j = 0; j < 16; j++) {
                int co = lane + j * 32;
                sc += bq[co] * bk[co];
            }
            #pragma unroll
            for (int o = 16; o > 0; o >>= 1) sc += __shfl_xor_sync(0xFFFFFFFF, sc, o);
            if (lane == 0) g_vv[2 * CH] = sc;
        }
    } else if (gw < 2 * CH) {
        const int c = gw - CH;
        #pragma unroll
        for (int j = 0; j < 16; j++) {
            int co = lane + j * 32;
            s += wq[co * CH + c] * bk[co];
        }
        #pragma unroll
        for (int o = 16; o > 0; o >>= 1) s += __shfl_xor_sync(0xFFFFFFFF, s, o);
        if (lane == 0) g_vv[CH + c] = s;
    } else {
        const int co = gw - 2 * CH;
        #pragma unroll
        for (int j = 0; j < 16; j++) {
            int cm = lane + j * 32;
            s += wp[co * CH + cm] * bv[cm];
        }
        #pragma unroll
        for (int o = 16; o > 0; o >>= 1) s += __shfl_xor_sync(0xFFFFFFFF, s, o);
        if (lane == 0) g_cvec[co] = s + bp[co];
    }
}

// rq[b][n] = scale*(v2.h + bqbk), rk[b][n] = scale*(v1.h)
__global__ __launch_bounds__(256) void rqk_kernel(float scale)
{
    const int row = blockIdx.x * 8 + (threadIdx.x >> 5);
    const int lane = threadIdx.x & 31;
    const __half* h = g_Hn + (size_t)row * CH;
    float d1 = 0.f, d2 = 0.f;
    #pragma unroll
    for (int j = 0; j < 16; j++) {
        int c = lane + j * 32;
        float hv = __half2float(h[c]);
        d1 += g_vv[c] * hv;
        d2 += g_vv[CH + c] * hv;
    }
    #pragma unroll
    for (int o = 16; o > 0; o >>= 1) {
        d1 += __shfl_xor_sync(0xFFFFFFFF, d1, o);
        d2 += __shfl_xor_sync(0xFFFFFFFF, d2, o);
    }
    if (lane == 0) {
        g_rq[row] = scale * (d2 + g_vv[2 * CH]);
        g_rk[row] = scale * d1;
    }
}

// ---------------------------------------------------------------------------
// GroupNorm -> Hn [b][n][c], Hc [b][c][n]  (fp16, float4-vectorized)
// ---------------------------------------------------------------------------
__global__ __launch_bounds__(256) void gn_kernel(
    const float* __restrict__ x, const float* __restrict__ w,
    const float* __restrict__ b)
{
    const int bg = blockIdx.x;
    const int batch = bg >> 5;
    const int g = bg & 31;
    const int tid = threadIdx.x;
    const float* xp = x + ((size_t)batch * CH + (size_t)g * CPG) * NPIX;
    const float4* xp4 = (const float4*)xp;

    float s = 0.f, ss = 0.f;
    #pragma unroll
    for (int i = 0; i < 16; i++) {
        float4 v = xp4[tid + i * 256];
        s  += v.x + v.y + v.z + v.w;
        ss += v.x * v.x + v.y * v.y + v.z * v.z + v.w * v.w;
    }
    __shared__ float sh_s[256], sh_ss[256];
    sh_s[tid] = s; sh_ss[tid] = ss;
    __syncthreads();
    for (int st = 128; st > 0; st >>= 1) {
        if (tid < st) { sh_s[tid] += sh_s[tid + st]; sh_ss[tid] += sh_ss[tid + st]; }
        __syncthreads();
    }
    const float mean = sh_s[0] * (1.0f / (CPG * NPIX));
    const float var  = sh_ss[0] * (1.0f / (CPG * NPIX)) - mean * mean;
    const float inv  = rsqrtf(var + EPS);

    __shared__ float st[512][17];

    for (int half = 0; half < 2; half++) {
        #pragma unroll
        for (int it = 0; it < 8; it++) {
            int i = tid + it * 256;            // 0..2047 float4 slots
            int c16 = i >> 7;                  // 0..15
            int q   = i & 127;                 // float4 index within half-channel
            int p4  = q << 2;                  // 0..508
            int c   = g * CPG + c16;
            const float wc = w[c] * inv;
            const float bc = b[c] - mean * wc;
            float4 xv = xp4[c16 * 256 + half * 128 + q];
            float n0 = xv.x * wc + bc;
            float n1 = xv.y * wc + bc;
            float n2 = xv.z * wc + bc;
            float n3 = xv.w * wc + bc;
            st[p4][c16] = n0; st[p4 + 1][c16] = n1;
            st[p4 + 2][c16] = n2; st[p4 + 3][c16] = n3;
            __half2 h01 = __floats2half2_rn(n0, n1);
            __half2 h23 = __floats2half2_rn(n2, n3);
            uint2 o;
            o.x = *reinterpret_cast<uint32_t*>(&h01);
            o.y = *reinterpret_cast<uint32_t*>(&h23);
            *(uint2*)&g_Hc[((size_t)batch * CH + c) * NPIX + half * 512 + p4] = o;
        }
        __syncthreads();
        size_t dst = ((size_t)batch * NPIX + half * 512) * CH + g * CPG;
        #pragma unroll
        for (int it = 0; it < 2; it++) {
            int nl = tid + it * 256;           // 0..511
            __half buf[16];
            #pragma unroll
            for (int c16 = 0; c16 < 16; c16++)
                buf[c16] = __float2half(st[nl][c16]);
            uint4* dp = (uint4*)&g_Hn[dst + (size_t)nl * CH];
            dp[0] = *(uint4*)&buf[0];
            dp[1] = *(uint4*)&buf[8];
        }
        __syncthreads();
    }
}

// ---------------------------------------------------------------------------
// Warp-per-row softmax: fp16 logits -> fp16 probs. 8 rows/block, grid 4096.
// ---------------------------------------------------------------------------
__global__ __launch_bounds__(256) void softmax_kernel(
    const __half* __restrict__ S, __half* __restrict__ Sp)
{
    const int row = blockIdx.x * 8 + (threadIdx.x >> 5);
    const int lane = threadIdx.x & 31;
    const uint4* p = (const uint4*)(S + (size_t)row * NPIX);
    uint4* po = (uint4*)(Sp + (size_t)row * NPIX);

    uint4 raw[4];
    float v[32];
    #pragma unroll
    for (int j = 0; j < 4; j++) raw[j] = p[lane + j * 32];
    #pragma unroll
    for (int j = 0; j < 4; j++) {
        const __half2* h2 = (const __half2*)&raw[j];
        #pragma unroll
        for (int k = 0; k < 4; k++) {
            float2 f = __half22float2(h2[k]);
            v[j * 8 + k * 2]     = f.x;
            v[j * 8 + k * 2 + 1] = f.y;
        }
    }
    float mx = -1e30f;
    #pragma unroll
    for (int i = 0; i < 32; i++) mx = fmaxf(mx, v[i]);
    #pragma unroll
    for (int o = 16; o > 0; o >>= 1)
        mx = fmaxf(mx, __shfl_xor_sync(0xFFFFFFFF, mx, o));

    float sum = 0.f;
    #pragma unroll
    for (int i = 0; i < 32; i++) {
        v[i] = __expf(v[i] - mx);
        sum += v[i];
    }
    #pragma unroll
    for (int o = 16; o > 0; o >>= 1)
        sum += __shfl_xor_sync(0xFFFFFFFF, sum, o);
    const float inv = 1.0f / sum;

    #pragma unroll
    for (int j = 0; j < 4; j++) {
        __half2* h2 = (__half2*)&raw[j];
        #pragma unroll
        for (int k = 0; k < 4; k++)
            h2[k] = __floats2half2_rn(v[j * 8 + k * 2] * inv, v[j * 8 + k * 2 + 1] * inv);
        po[lane + j * 32] = raw[j];
    }
}

#define TILE_B   10240
#define ROWS_H   40

// ---------------------------------------------------------------------------
// T/W2 precompute GEMM: split-K(x4), atomicAdd epilogue, fp16 hi/lo 3-term.
// grid (4,4,8): z>>2 = matrix (0:T, 1:W2), z&3 = K-slice of 128.
// ---------------------------------------------------------------------------
__global__ __launch_bounds__(256, 2) void tw_gemm(
    const __half* __restrict__ Wah, const __half* __restrict__ Wal,
    float* __restrict__ TW)
{
    constexpr int STAGE = 4 * TILE_B;

    extern __shared__ __align__(1024) char smem[];
    const uint32_t sb = smem_u32(smem);

    const int tid  = threadIdx.x;
    const int lane = tid & 31;
    const int warp = tid >> 5;
    const int wm = (warp >> 2) * 64;
    const int wn = (warp & 3) * 32;
    const int m0 = blockIdx.y * 128;
    const int n0 = blockIdx.x * 128;
    const int mat = blockIdx.z >> 2;
    const int kbase = (blockIdx.z & 3) * 128;

    const __half* gA[2] = { Wah + (size_t)mat * WSZ, Wal + (size_t)mat * WSZ };
    const __half* gB[2] = { Wah + (size_t)(mat + 2) * WSZ, Wal + (size_t)(mat + 2) * WSZ };
    float* C = TW + (size_t)mat * WSZ;

    auto issue = [&](int c) {
        const int stg = c & 1;
        const int k0 = kbase + c * 32;
        const uint32_t sbase = sb + stg * STAGE;
        #pragma unroll
        for (int i = 0; i < 2; i++) {
            const int idx = tid + i * 256;
            const int r = idx >> 2;
            const int seg = idx & 3;
            const uint32_t soff = r * (ROWS_H * 2) + seg * 16;
            const size_t ga = (size_t)(m0 + r) * CH + k0 + seg * 8;
            const size_t gb = (size_t)(n0 + r) * CH + k0 + seg * 8;
            cp16(sbase + soff, gA[0] + ga);
            cp16(sbase + TILE_B + soff, gA[1] + ga);
            cp16(sbase + 2 * TILE_B + soff, gB[0] + gb);
            cp16(sbase + 3 * TILE_B + soff, gB[1] + gb);
        }
        cp_commit();
    };

    float acc[4][4][4] = {};

    issue(0);

    const int ar = lane & 15;
    const int ac0 = (lane >> 4) * 8;
    const int br = (lane & 7) + (lane >> 4) * 8;
    const int bc0 = ((lane >> 3) & 1) * 8;

    for (int c = 0; c < 4; c++) {
        cp_wait<0>();
        __syncthreads();
        if (c + 1 < 4) issue(c + 1);

        const int stg = c & 1;
        const __half* TA0 = (const __half*)(smem + stg * STAGE);
        const __half* TA1 = (const __half*)(smem + stg * STAGE + TILE_B);
        const __half* TB0 = (const __half*)(smem + stg * STAGE + 2 * TILE_B);
        const __half* TB1 = (const __half*)(smem + stg * STAGE + 3 * TILE_B);

        #pragma unroll
        for (int kk = 0; kk < 32; kk += 16) {
            uint32_t a0[4][4], a1[4][4];
            uint32_t b0[8], b1[8];
            #pragma unroll
            for (int i = 0; i < 4; i++) {
                ldsm4(a0[i], smem_u32(TA0 + (wm + i * 16 + ar) * ROWS_H + kk + ac0));
                ldsm4(a1[i], smem_u32(TA1 + (wm + i * 16 + ar) * ROWS_H + kk + ac0));
            }
            #pragma unroll
            for (int jj = 0; jj < 2; jj++) {
                ldsm4(&b0[4 * jj], smem_u32(TB0 + (wn + jj * 16 + br) * ROWS_H + kk + bc0));
                ldsm4(&b1[4 * jj], smem_u32(TB1 + (wn + jj * 16 + br) * ROWS_H + kk + bc0));
            }
            #pragma unroll
            for (int i = 0; i < 4; i++)
                #pragma unroll
                for (int j = 0; j < 4; j++)
                    mma16816(acc[i][j], a0[i], &b0[2 * j]);
            #pragma unroll
            for (int i = 0; i < 4; i++)
                #pragma unroll
                for (int j = 0; j < 4; j++)
                    mma16816(acc[i][j], a0[i], &b1[2 * j]);
            #pragma unroll
            for (int i = 0; i < 4; i++)
                #pragma unroll
                for (int j = 0; j < 4; j++)
                    mma16816(acc[i][j], a1[i], &b0[2 * j]);
        }
    }

    const int g  = lane >> 2;
    const int t2 = (lane & 3) * 2;
    #pragma unroll
    for (int i = 0; i < 4; i++) {
        const int m = m0 + wm + i * 16 + g;
        #pragma unroll
        for (int j = 0; j < 4; j++) {
            const int n = n0 + wn + j * 8 + t2;
            atomicAdd(&C[(size_t)m * CH + n],     acc[i][j][0]);
            atomicAdd(&C[(size_t)m * CH + n + 1], acc[i][j][1]);
            atomicAdd(&C[(size_t)(m + 8) * CH + n],     acc[i][j][2]);
            atomicAdd(&C[(size_t)(m + 8) * CH + n + 1], acc[i][j][3]);
        }
    }
}

// ---------------------------------------------------------------------------
// Config C GEMM (wide tiles): 4 warps (64x64 warp tiles), 128 threads,
// block 128x128, k-chunk 32, 3-stage cp.async, 2 CTAs/SM. 1-term fp16.
// OM: 0 = fp32 out, 2 = fp16 out.
//   C[m][n] = alpha*sum_k A(m,k)B(n,k) + bias_row[m] + bias_col[n] (+resid)
// ---------------------------------------------------------------------------
template<int OM>
__global__ __launch_bounds__(128, 2) void mma_gemm_c(
    const __half* __restrict__ Ah, const __half* __restrict__ Bh,
    void* __restrict__ C0,
    int N, int K,
    size_t sA, size_t sB, size_t sC,
    const float* __restrict__ bias_row, size_t brs,
    const float* __restrict__ bias_col, size_t bcs,
    const float* __restrict__ resid, size_t sR, float alpha)
{
    constexpr int STAGE = 2 * TILE_B;

    extern __shared__ __align__(1024) char smem[];
    const uint32_t sb = smem_u32(smem);

    const int tid  = threadIdx.x;
    const int lane = tid & 31;
    const int warp = tid >> 5;
    const int wm = (warp >> 1) * 64;
    const int wn = (warp & 1) * 64;
    const int m0 = blockIdx.y * 128;
    const int n0 = blockIdx.x * 128;
    const int bz = blockIdx.z;

    const __half* gA = Ah + (size_t)bz * sA;
    const __half* gB = Bh + (size_t)bz * sB;

    auto issue = [&](int c) {
        const int stg = c % 3;
        const int k0 = c * 32;
        const uint32_t sbase = sb + stg * STAGE;
        #pragma unroll
        for (int i = 0; i < 4; i++) {
            const int idx = tid + i * 128;
            const int r = idx >> 2;
            const int seg = idx & 3;
            const uint32_t soff = r * (ROWS_H * 2) + seg * 16;
            cp16(sbase + soff, gA + (size_t)(m0 + r) * K + k0 + seg * 8);
            cp16(sbase + TILE_B + soff, gB + (size_t)(n0 + r) * K + k0 + seg * 8);
        }
        cp_commit();
    };

    float acc[4][8][4] = {};

    const int nc = K >> 5;
    issue(0);
    issue(1);

    const int ar = lane & 15;
    const int ac0 = (lane >> 4) * 8;
    const int br = (lane & 7) + (lane >> 4) * 8;
    const int bc0 = ((lane >> 3) & 1) * 8;

    for (int c = 0; c < nc; c++) {
        cp_wait<1>();
        __syncthreads();
        if (c + 2 < nc) issue(c + 2);

        const int stg = c % 3;
        const __half* TA = (const __half*)(smem + stg * STAGE);
        const __half* TB = (const __half*)(smem + stg * STAGE + TILE_B);

        #pragma unroll
        for (int kk = 0; kk < 32; kk += 16) {
            uint32_t a0[4][4];
            uint32_t b0[16];
            #pragma unroll
            for (int i = 0; i < 4; i++)
                ldsm4(a0[i], smem_u32(TA + (wm + i * 16 + ar) * ROWS_H + kk + ac0));
            #pragma unroll
            for (int jj = 0; jj < 4; jj++)
                ldsm4(&b0[4 * jj], smem_u32(TB + (wn + jj * 16 + br) * ROWS_H + kk + bc0));
            #pragma unroll
            for (int i = 0; i < 4; i++)
                #pragma unroll
                for (int j = 0; j < 8; j++)
                    mma16816(acc[i][j], a0[i], &b0[2 * j]);
        }
    }

    const float* brp = bias_row ? bias_row + (size_t)bz * brs : nullptr;
    const float* bcp = bias_col ? bias_col + (size_t)bz * bcs : nullptr;
    const int g  = lane >> 2;
    const int t2 = (lane & 3) * 2;
    #pragma unroll
    for (int i = 0; i < 4; i++) {
        const int m = m0 + wm + i * 16 + g;
        const float br0 = brp ? brp[m] : 0.f;
        const float br1 = brp ? brp[m + 8] : 0.f;
        #pragma unroll
        for (int j = 0; j < 8; j++) {
            const int n = n0 + wn + j * 8 + t2;
            float bc0v = 0.f, bc1v = 0.f;
            if (bcp) { bc0v = bcp[n]; bc1v = bcp[n + 1]; }
            float v0 = acc[i][j][0] * alpha + br0 + bc0v;
            float v1 = acc[i][j][1] * alpha + br0 + bc1v;
            float v2 = acc[i][j][2] * alpha + br1 + bc0v;
            float v3 = acc[i][j][3] * alpha + br1 + bc1v;
            if (resid) {
                const float* rp = resid + (size_t)bz * sR;
                v0 += rp[(size_t)m * N + n];
                v1 += rp[(size_t)m * N + n + 1];
                v2 += rp[(size_t)(m + 8) * N + n];
                v3 += rp[(size_t)(m + 8) * N + n + 1];
            }
            if (OM == 0) {
                float* C = (float*)C0 + (size_t)bz * sC;
                float2 o0; o0.x = v0; o0.y = v1;
                float2 o1; o1.x = v2; o1.y = v3;
                *(float2*)&C[(size_t)m * N + n] = o0;
                *(float2*)&C[(size_t)(m + 8) * N + n] = o1;
            } else {
                __half* Ch = (__half*)C0 + (size_t)bz * sC;
                __half2 h01 = __floats2half2_rn(v0, v1);
                __half2 h23 = __floats2half2_rn(v2, v3);
                *(__half2*)&Ch[(size_t)m * N + n] = h01;
                *(__half2*)&Ch[(size_t)(m + 8) * N + n] = h23;
            }
        }
    }
}

// ---------------------------------------------------------------------------
// Launch (fork/join stream capture: weight-prep chain overlaps GN chain)
// ---------------------------------------------------------------------------
extern "C" void kernel_launch(void* const* d_in, const int* in_sizes, int n_in,
                              void* d_out, int out_size)
{
    (void)in_sizes; (void)n_in; (void)out_size;
    const float* x    = (const float*)d_in[0];
    const float* gn_w = (const float*)d_in[1];
    const float* gn_b = (const float*)d_in[2];
    const float* wq   = (const float*)d_in[3];
    const float* bq   = (const float*)d_in[4];
    const float* wk   = (const float*)d_in[5];
    const float* bk   = (const float*)d_in[6];
    const float* wv   = (const float*)d_in[7];
    const float* bv   = (const float*)d_in[8];
    const float* wp   = (const float*)d_in[9];
    const float* bp   = (const float*)d_in[10];
    float* out = (float*)d_out;

    __half *Hn, *Hc, *U, *G, *P, *S, *Wah, *Wal, *Th, *W2h;
    float *TW, *rq, *rk, *cvec;
    cudaGetSymbolAddress((void**)&Hn, g_Hn);
    cudaGetSymbolAddress((void**)&Hc, g_Hc);
    cudaGetSymbolAddress((void**)&U,  g_U);
    cudaGetSymbolAddress((void**)&G,  g_G);
    cudaGetSymbolAddress((void**)&P,  g_P);
    cudaGetSymbolAddress((void**)&S,  g_S);
    cudaGetSymbolAddress((void**)&Wah, g_Wah); cudaGetSymbolAddress((void**)&Wal, g_Wal);
    cudaGetSymbolAddress((void**)&Th, g_Th);   cudaGetSymbolAddress((void**)&W2h, g_W2h);
    cudaGetSymbolAddress((void**)&TW, g_TW);
    cudaGetSymbolAddress((void**)&rq, g_rq);   cudaGetSymbolAddress((void**)&rk, g_rk);
    cudaGetSymbolAddress((void**)&cvec, g_cvec);

    const int SMC2 = 3 * 2 * TILE_B;  // 61440
    const int SMTW = 2 * 4 * TILE_B;  // 81920
    static bool init_done = false;
    static cudaStream_t s2;
    static cudaEvent_t e0, eV, e1;
    if (!init_done) {
        cudaFuncSetAttribute((const void*)tw_gemm,        cudaFuncAttributeMaxDynamicSharedMemorySize, SMTW);
        cudaFuncSetAttribute((const void*)mma_gemm_c<0>,  cudaFuncAttributeMaxDynamicSharedMemorySize, SMC2);
        cudaFuncSetAttribute((const void*)mma_gemm_c<2>,  cudaFuncAttributeMaxDynamicSharedMemorySize, SMC2);
        cudaStreamCreateWithFlags(&s2, cudaStreamNonBlocking);
        cudaEventCreateWithFlags(&e0, cudaEventDisableTiming);
        cudaEventCreateWithFlags(&eV, cudaEventDisableTiming);
        cudaEventCreateWithFlags(&e1, cudaEventDisableTiming);
        init_done = true;
    }

    const size_t sCN = (size_t)CH * NPIX;
    const size_t sNN = (size_t)NPIX * NPIX;
    const float scale = 0.044194173824159223f; // 512^-0.5

    // ---- fork: weight-prep chain on s2 ----
    cudaEventRecord(e0, 0);
    cudaStreamWaitEvent(s2, e0, 0);
    vecs_kernel<<<192, 256, 0, s2>>>(wq, wk, bq, bk, wp, bv, bp);
    cudaEventRecord(eV, s2);
    pack_weights_kernel<<<4096, 256, 0, s2>>>(wq, wk, wv, wp);  // also zeros TW
    {
        dim3 grid(4, 4, 8);
        tw_gemm<<<grid, 256, SMTW, s2>>>(Wah, Wal, TW);
    }
    split_tw_kernel<<<2048, 256, 0, s2>>>(scale);
    cudaEventRecord(e1, s2);

    // ---- main chain on default stream ----
    gn_kernel<<<BATCH * NG, 256>>>(x, gn_w, gn_b);
    cudaStreamWaitEvent(0, eV, 0);
    rqk_kernel<<<4096, 256>>>(scale);
    cudaStreamWaitEvent(0, e1, 0);    // join weight chain

    // U[b][n][c1] = sum_c2 Hn(n,c2)*T(c1,c2)
    {
        dim3 grid(CH / 128, NPIX / 128, BATCH);
        mma_gemm_c<2><<<grid, 128, SMC2>>>(Hn, Th, U,
            CH, CH, sCN, 0, sCN, nullptr, 0, nullptr, 0, nullptr, 0, 1.f);
    }
    // S[b][q][k] = sum_c1 Hn(q,c1)*U(k,c1) + rq[q] + rk[k] -> fp16
    {
        dim3 grid(NPIX / 128, NPIX / 128, BATCH);
        mma_gemm_c<2><<<grid, 128, SMC2>>>(Hn, U, S,
            NPIX, CH, sCN, sCN, sNN, rq, NPIX, rk, NPIX, nullptr, 0, 1.f);
    }
    // softmax
    softmax_kernel<<<BATCH * NPIX / 8, 256>>>(S, P);

    // G[b][q][c] = sum_k P(q,k)*Hc(c,k)
    {
        dim3 grid(CH / 128, NPIX / 128, BATCH);
        mma_gemm_c<2><<<grid, 128, SMC2>>>(P, Hc, G,
            CH, NPIX, sNN, sCN, sCN, nullptr, 0, nullptr, 0, nullptr, 0, 1.f);
    }
    // out[b][co][n] = sum_c W2(co,c)*G(n,c) + cvec[co] + x
    {
        dim3 grid(NPIX / 128, CH / 128, BATCH);
        mma_gemm_c<0><<<grid, 128, SMC2>>>(W2h, G, out,
            NPIX, CH, 0, sCN, sCN, cvec, 0, nullptr, 0, x, sCN, 1.f);
    }
}

// round 15
// speedup vs baseline: 2.3860x; 1.0537x over previous
#include <cuda_runtime.h>
#include <cuda_fp16.h>
#include <cstdint>
#include <cstddef>

#define BATCH 32
#define CH    512
#define NPIX  1024
#define NG    32
#define CPG   16
#define EPS   1e-6f

#define SZ_CN ((size_t)BATCH * NPIX * CH)
#define SZ_NN ((size_t)BATCH * NPIX * NPIX)
#define WSZ   ((size_t)CH * CH)

// ---------------------------------------------------------------------------
// Scratch (all activations fp16)
// ---------------------------------------------------------------------------
__device__ __half g_Hn[SZ_CN];    // H [b][n][c]
__device__ __half g_Hc[SZ_CN];    // H [b][c][n]
__device__ __half g_U [SZ_CN];    // U = H.T^T [b][n][c1]
__device__ __half g_G [SZ_CN];    // G = P.H  [b][q][c]
__device__ __half g_S [SZ_NN];    // logits fp16
__device__ __half g_P [SZ_NN];    // probs fp16
// packed weights fp16 hi/lo: [0]=WqT, [1]=Wp(nat), [2]=WkT, [3]=WvT
__device__ __half g_Wah[4 * WSZ], g_Wal[4 * WSZ];
__device__ float g_TW[2 * WSZ];                     // Traw | W2raw (atomic acc)
__device__ __half g_Th[WSZ];                        // T = scale*Wq^T.Wk (fp16)
__device__ __half g_W2h[WSZ];                       // W2 = Wp.Wv (fp16)
__device__ float g_vv[2 * CH + 1];
__device__ float g_cvec[CH];
__device__ float g_rq[(size_t)BATCH * NPIX];
__device__ float g_rk[(size_t)BATCH * NPIX];

// ---------------------------------------------------------------------------
// Helpers
// ---------------------------------------------------------------------------
__device__ __forceinline__ uint32_t smem_u32(const void* p) {
    return (uint32_t)__cvta_generic_to_shared(p);
}
__device__ __forceinline__ void ldsm4(uint32_t r[4], uint32_t a) {
    asm volatile("ldmatrix.sync.aligned.m8n8.x4.shared.b16 {%0,%1,%2,%3}, [%4];"
        : "=r"(r[0]), "=r"(r[1]), "=r"(r[2]), "=r"(r[3]) : "r"(a));
}
__device__ __forceinline__ void mma16816(float d[4], const uint32_t a[4], const uint32_t* b) {
    asm volatile(
        "mma.sync.aligned.m16n8k16.row.col.f32.f16.f16.f32 "
        "{%0,%1,%2,%3}, {%4,%5,%6,%7}, {%8,%9}, {%0,%1,%2,%3};"
        : "+f"(d[0]), "+f"(d[1]), "+f"(d[2]), "+f"(d[3])
        : "r"(a[0]), "r"(a[1]), "r"(a[2]), "r"(a[3]), "r"(b[0]), "r"(b[1]));
}
__device__ __forceinline__ void cp16(uint32_t s, const void* g) {
    asm volatile("cp.async.cg.shared.global [%0], [%1], 16;" :: "r"(s), "l"(g));
}
__device__ __forceinline__ void cp_commit() {
    asm volatile("cp.async.commit_group;" ::: "memory");
}
template<int n>
__device__ __forceinline__ void cp_wait() {
    asm volatile("cp.async.wait_group %0;" :: "n"(n) : "memory");
}
__device__ __forceinline__ void splitf(float x, __half& h, __half& l) {
    h = __float2half(x);
    l = __float2half(x - __half2float(h));
}

// ---------------------------------------------------------------------------
// Pack into unified layout: [0]=WqT, [1]=Wp natural, [2]=WkT, [3]=WvT
// Also zeros the TW accumulators.
// ---------------------------------------------------------------------------
__global__ __launch_bounds__(256) void pack_weights_kernel(
    const float* __restrict__ wq, const float* __restrict__ wk,
    const float* __restrict__ wv, const float* __restrict__ wp)
{
    int i = blockIdx.x * 256 + threadIdx.x;
    if (i < (int)(2 * WSZ)) g_TW[i] = 0.f;
    int t = i >> 18;
    int j = i & (int)(WSZ - 1);
    float v;
    if (t == 1) {
        v = wp[j];
    } else {
        int c = j >> 9, co = j & 511;
        const float* src = (t == 0) ? wq : (t == 2) ? wk : wv;
        v = src[co * CH + c];
    }
    __half h, l;
    splitf(v, h, l);
    g_Wah[i] = h; g_Wal[i] = l;
}

// convert fp32 TW -> single fp16 planes; T gets alpha=scale folded in
__global__ __launch_bounds__(256) void split_tw_kernel(float scale)
{
    int i = blockIdx.x * 256 + threadIdx.x;
    if (i < (int)WSZ) {
        g_Th[i] = __float2half(g_TW[i] * scale);
    } else {
        g_W2h[i - (int)WSZ] = __float2half(g_TW[i]);
    }
}

// warp-per-output: v1 = Wk^T.bq, v2 = Wq^T.bk, bq.bk ; cvec = Wp.bv + bp
__global__ __launch_bounds__(256) void vecs_kernel(
    const float* __restrict__ wq, const float* __restrict__ wk,
    const float* __restrict__ bq, const float* __restrict__ bk,
    const float* __restrict__ wp, const float* __restrict__ bv,
    const float* __restrict__ bp)
{
    const int gw = (blockIdx.x * 256 + threadIdx.x) >> 5;
    const int lane = threadIdx.x & 31;
    float s = 0.f;
    if (gw < CH) {
        const int c = gw;
        #pragma unroll
        for (int j = 0; j < 16; j++) {
            int co = lane + j * 32;
            s += wk[co * CH + c] * bq[co];
        }
        #pragma unroll
        for (int o = 16; o > 0; o >>= 1) s += __shfl_xor_sync(0xFFFFFFFF, s, o);
        if (lane == 0) g_vv[c] = s;
        if (gw == 0) {
            float sc = 0.f;
            #pragma unroll
            for (int j = 0; j < 16; j++) {
                int co = lane + j * 32;
                sc += bq[co] * bk[co];
            }
            #pragma unroll
            for (int o = 16; o > 0; o >>= 1) sc += __shfl_xor_sync(0xFFFFFFFF, sc, o);
            if (lane == 0) g_vv[2 * CH] = sc;
        }
    } else if (gw < 2 * CH) {
        const int c = gw - CH;
        #pragma unroll
        for (int j = 0; j < 16; j++) {
            int co = lane + j * 32;
            s += wq[co * CH + c] * bk[co];
        }
        #pragma unroll
        for (int o = 16; o > 0; o >>= 1) s += __shfl_xor_sync(0xFFFFFFFF, s, o);
        if (lane == 0) g_vv[CH + c] = s;
    } else {
        const int co = gw - 2 * CH;
        #pragma unroll
        for (int j = 0; j < 16; j++) {
            int cm = lane + j * 32;
            s += wp[co * CH + cm] * bv[cm];
        }
        #pragma unroll
        for (int o = 16; o > 0; o >>= 1) s += __shfl_xor_sync(0xFFFFFFFF, s, o);
        if (lane == 0) g_cvec[co] = s + bp[co];
    }
}

// rq[b][n] = scale*(v2.h + bqbk), rk[b][n] = scale*(v1.h)
__global__ __launch_bounds__(256) void rqk_kernel(float scale, int ofs)
{
    const int row = ofs * NPIX + blockIdx.x * 8 + (threadIdx.x >> 5);
    const int lane = threadIdx.x & 31;
    const __half* h = g_Hn + (size_t)row * CH;
    float d1 = 0.f, d2 = 0.f;
    #pragma unroll
    for (int j = 0; j < 16; j++) {
        int c = lane + j * 32;
        float hv = __half2float(h[c]);
        d1 += g_vv[c] * hv;
        d2 += g_vv[CH + c] * hv;
    }
    #pragma unroll
    for (int o = 16; o > 0; o >>= 1) {
        d1 += __shfl_xor_sync(0xFFFFFFFF, d1, o);
        d2 += __shfl_xor_sync(0xFFFFFFFF, d2, o);
    }
    if (lane == 0) {
        g_rq[row] = scale * (d2 + g_vv[2 * CH]);
        g_rk[row] = scale * d1;
    }
}

// ---------------------------------------------------------------------------
// GroupNorm -> Hn [b][n][c], Hc [b][c][n]  (fp16, float4-vectorized)
// grid.x covers 16 batches starting at batch ofs
// ---------------------------------------------------------------------------
__global__ __launch_bounds__(256) void gn_kernel(
    const float* __restrict__ x, const float* __restrict__ w,
    const float* __restrict__ b, int ofs)
{
    const int bg = blockIdx.x;
    const int batch = ofs + (bg >> 5);
    const int g = bg & 31;
    const int tid = threadIdx.x;
    const float* xp = x + ((size_t)batch * CH + (size_t)g * CPG) * NPIX;
    const float4* xp4 = (const float4*)xp;

    float s = 0.f, ss = 0.f;
    #pragma unroll
    for (int i = 0; i < 16; i++) {
        float4 v = xp4[tid + i * 256];
        s  += v.x + v.y + v.z + v.w;
        ss += v.x * v.x + v.y * v.y + v.z * v.z + v.w * v.w;
    }
    __shared__ float sh_s[256], sh_ss[256];
    sh_s[tid] = s; sh_ss[tid] = ss;
    __syncthreads();
    for (int st = 128; st > 0; st >>= 1) {
        if (tid < st) { sh_s[tid] += sh_s[tid + st]; sh_ss[tid] += sh_ss[tid + st]; }
        __syncthreads();
    }
    const float mean = sh_s[0] * (1.0f / (CPG * NPIX));
    const float var  = sh_ss[0] * (1.0f / (CPG * NPIX)) - mean * mean;
    const float inv  = rsqrtf(var + EPS);

    __shared__ float st[512][17];

    for (int half = 0; half < 2; half++) {
        #pragma unroll
        for (int it = 0; it < 8; it++) {
            int i = tid + it * 256;
            int c16 = i >> 7;
            int q   = i & 127;
            int p4  = q << 2;
            int c   = g * CPG + c16;
            const float wc = w[c] * inv;
            const float bc = b[c] - mean * wc;
            float4 xv = xp4[c16 * 256 + half * 128 + q];
            float n0 = xv.x * wc + bc;
            float n1 = xv.y * wc + bc;
            float n2 = xv.z * wc + bc;
            float n3 = xv.w * wc + bc;
            st[p4][c16] = n0; st[p4 + 1][c16] = n1;
            st[p4 + 2][c16] = n2; st[p4 + 3][c16] = n3;
            __half2 h01 = __floats2half2_rn(n0, n1);
            __half2 h23 = __floats2half2_rn(n2, n3);
            uint2 o;
            o.x = *reinterpret_cast<uint32_t*>(&h01);
            o.y = *reinterpret_cast<uint32_t*>(&h23);
            *(uint2*)&g_Hc[((size_t)batch * CH + c) * NPIX + half * 512 + p4] = o;
        }
        __syncthreads();
        size_t dst = ((size_t)batch * NPIX + half * 512) * CH + g * CPG;
        #pragma unroll
        for (int it = 0; it < 2; it++) {
            int nl = tid + it * 256;
            __half buf[16];
            #pragma unroll
            for (int c16 = 0; c16 < 16; c16++)
                buf[c16] = __float2half(st[nl][c16]);
            uint4* dp = (uint4*)&g_Hn[dst + (size_t)nl * CH];
            dp[0] = *(uint4*)&buf[0];
            dp[1] = *(uint4*)&buf[8];
        }
        __syncthreads();
    }
}

// ---------------------------------------------------------------------------
// Warp-per-row softmax: fp16 logits -> fp16 probs. 8 rows/block.
// ---------------------------------------------------------------------------
__global__ __launch_bounds__(256) void softmax_kernel(
    const __half* __restrict__ S, __half* __restrict__ Sp)
{
    const int row = blockIdx.x * 8 + (threadIdx.x >> 5);
    const int lane = threadIdx.x & 31;
    const uint4* p = (const uint4*)(S + (size_t)row * NPIX);
    uint4* po = (uint4*)(Sp + (size_t)row * NPIX);

    uint4 raw[4];
    float v[32];
    #pragma unroll
    for (int j = 0; j < 4; j++) raw[j] = p[lane + j * 32];
    #pragma unroll
    for (int j = 0; j < 4; j++) {
        const __half2* h2 = (const __half2*)&raw[j];
        #pragma unroll
        for (int k = 0; k < 4; k++) {
            float2 f = __half22float2(h2[k]);
            v[j * 8 + k * 2]     = f.x;
            v[j * 8 + k * 2 + 1] = f.y;
        }
    }
    float mx = -1e30f;
    #pragma unroll
    for (int i = 0; i < 32; i++) mx = fmaxf(mx, v[i]);
    #pragma unroll
    for (int o = 16; o > 0; o >>= 1)
        mx = fmaxf(mx, __shfl_xor_sync(0xFFFFFFFF, mx, o));

    float sum = 0.f;
    #pragma unroll
    for (int i = 0; i < 32; i++) {
        v[i] = __expf(v[i] - mx);
        sum += v[i];
    }
    #pragma unroll
    for (int o = 16; o > 0; o >>= 1)
        sum += __shfl_xor_sync(0xFFFFFFFF, sum, o);
    const float inv = 1.0f / sum;

    #pragma unroll
    for (int j = 0; j < 4; j++) {
        __half2* h2 = (__half2*)&raw[j];
        #pragma unroll
        for (int k = 0; k < 4; k++)
            h2[k] = __floats2half2_rn(v[j * 8 + k * 2] * inv, v[j * 8 + k * 2 + 1] * inv);
        po[lane + j * 32] = raw[j];
    }
}

#define TILE_B   10240
#define ROWS_H   40

// ---------------------------------------------------------------------------
// T/W2 precompute GEMM: split-K(x4), atomicAdd epilogue, fp16 hi/lo 3-term.
// ---------------------------------------------------------------------------
__global__ __launch_bounds__(256, 2) void tw_gemm(
    const __half* __restrict__ Wah, const __half* __restrict__ Wal,
    float* __restrict__ TW)
{
    constexpr int STAGE = 4 * TILE_B;

    extern __shared__ __align__(1024) char smem[];
    const uint32_t sb = smem_u32(smem);

    const int tid  = threadIdx.x;
    const int lane = tid & 31;
    const int warp = tid >> 5;
    const int wm = (warp >> 2) * 64;
    const int wn = (warp & 3) * 32;
    const int m0 = blockIdx.y * 128;
    const int n0 = blockIdx.x * 128;
    const int mat = blockIdx.z >> 2;
    const int kbase = (blockIdx.z & 3) * 128;

    const __half* gA[2] = { Wah + (size_t)mat * WSZ, Wal + (size_t)mat * WSZ };
    const __half* gB[2] = { Wah + (size_t)(mat + 2) * WSZ, Wal + (size_t)(mat + 2) * WSZ };
    float* C = TW + (size_t)mat * WSZ;

    auto issue = [&](int c) {
        const int stg = c & 1;
        const int k0 = kbase + c * 32;
        const uint32_t sbase = sb + stg * STAGE;
        #pragma unroll
        for (int i = 0; i < 2; i++) {
            const int idx = tid + i * 256;
            const int r = idx >> 2;
            const int seg = idx & 3;
            const uint32_t soff = r * (ROWS_H * 2) + seg * 16;
            const size_t ga = (size_t)(m0 + r) * CH + k0 + seg * 8;
            const size_t gb = (size_t)(n0 + r) * CH + k0 + seg * 8;
            cp16(sbase + soff, gA[0] + ga);
            cp16(sbase + TILE_B + soff, gA[1] + ga);
            cp16(sbase + 2 * TILE_B + soff, gB[0] + gb);
            cp16(sbase + 3 * TILE_B + soff, gB[1] + gb);
        }
        cp_commit();
    };

    float acc[4][4][4] = {};

    issue(0);

    const int ar = lane & 15;
    const int ac0 = (lane >> 4) * 8;
    const int br = (lane & 7) + (lane >> 4) * 8;
    const int bc0 = ((lane >> 3) & 1) * 8;

    for (int c = 0; c < 4; c++) {
        cp_wait<0>();
        __syncthreads();
        if (c + 1 < 4) issue(c + 1);

        const int stg = c & 1;
        const __half* TA0 = (const __half*)(smem + stg * STAGE);
        const __half* TA1 = (const __half*)(smem + stg * STAGE + TILE_B);
        const __half* TB0 = (const __half*)(smem + stg * STAGE + 2 * TILE_B);
        const __half* TB1 = (const __half*)(smem + stg * STAGE + 3 * TILE_B);

        #pragma unroll
        for (int kk = 0; kk < 32; kk += 16) {
            uint32_t a0[4][4], a1[4][4];
            uint32_t b0[8], b1[8];
            #pragma unroll
            for (int i = 0; i < 4; i++) {
                ldsm4(a0[i], smem_u32(TA0 + (wm + i * 16 + ar) * ROWS_H + kk + ac0));
                ldsm4(a1[i], smem_u32(TA1 + (wm + i * 16 + ar) * ROWS_H + kk + ac0));
            }
            #pragma unroll
            for (int jj = 0; jj < 2; jj++) {
                ldsm4(&b0[4 * jj], smem_u32(TB0 + (wn + jj * 16 + br) * ROWS_H + kk + bc0));
                ldsm4(&b1[4 * jj], smem_u32(TB1 + (wn + jj * 16 + br) * ROWS_H + kk + bc0));
            }
            #pragma unroll
            for (int i = 0; i < 4; i++)
                #pragma unroll
                for (int j = 0; j < 4; j++)
                    mma16816(acc[i][j], a0[i], &b0[2 * j]);
            #pragma unroll
            for (int i = 0; i < 4; i++)
                #pragma unroll
                for (int j = 0; j < 4; j++)
                    mma16816(acc[i][j], a0[i], &b1[2 * j]);
            #pragma unroll
            for (int i = 0; i < 4; i++)
                #pragma unroll
                for (int j = 0; j < 4; j++)
                    mma16816(acc[i][j], a1[i], &b0[2 * j]);
        }
    }

    const int g  = lane >> 2;
    const int t2 = (lane & 3) * 2;
    #pragma unroll
    for (int i = 0; i < 4; i++) {
        const int m = m0 + wm + i * 16 + g;
        #pragma unroll
        for (int j = 0; j < 4; j++) {
            const int n = n0 + wn + j * 8 + t2;
            atomicAdd(&C[(size_t)m * CH + n],     acc[i][j][0]);
            atomicAdd(&C[(size_t)m * CH + n + 1], acc[i][j][1]);
            atomicAdd(&C[(size_t)(m + 8) * CH + n],     acc[i][j][2]);
            atomicAdd(&C[(size_t)(m + 8) * CH + n + 1], acc[i][j][3]);
        }
    }
}

// ---------------------------------------------------------------------------
// Config C GEMM (wide tiles): 4 warps (64x64 warp tiles), 128 threads,
// block 128x128, k-chunk 32, 3-stage cp.async, 2 CTAs/SM. 1-term fp16.
// OM: 0 = fp32 out, 2 = fp16 out.
// ---------------------------------------------------------------------------
template<int OM>
__global__ __launch_bounds__(128, 2) void mma_gemm_c(
    const __half* __restrict__ Ah, const __half* __restrict__ Bh,
    void* __restrict__ C0,
    int N, int K,
    size_t sA, size_t sB, size_t sC,
    const float* __restrict__ bias_row, size_t brs,
    const float* __restrict__ bias_col, size_t bcs,
    const float* __restrict__ resid, size_t sR, float alpha)
{
    constexpr int STAGE = 2 * TILE_B;

    extern __shared__ __align__(1024) char smem[];
    const uint32_t sb = smem_u32(smem);

    const int tid  = threadIdx.x;
    const int lane = tid & 31;
    const int warp = tid >> 5;
    const int wm = (warp >> 1) * 64;
    const int wn = (warp & 1) * 64;
    const int m0 = blockIdx.y * 128;
    const int n0 = blockIdx.x * 128;
    const int bz = blockIdx.z;

    const __half* gA = Ah + (size_t)bz * sA;
    const __half* gB = Bh + (size_t)bz * sB;

    auto issue = [&](int c) {
        const int stg = c % 3;
        const int k0 = c * 32;
        const uint32_t sbase = sb + stg * STAGE;
        #pragma unroll
        for (int i = 0; i < 4; i++) {
            const int idx = tid + i * 128;
            const int r = idx >> 2;
            const int seg = idx & 3;
            const uint32_t soff = r * (ROWS_H * 2) + seg * 16;
            cp16(sbase + soff, gA + (size_t)(m0 + r) * K + k0 + seg * 8);
            cp16(sbase + TILE_B + soff, gB + (size_t)(n0 + r) * K + k0 + seg * 8);
        }
        cp_commit();
    };

    float acc[4][8][4] = {};

    const int nc = K >> 5;
    issue(0);
    issue(1);

    const int ar = lane & 15;
    const int ac0 = (lane >> 4) * 8;
    const int br = (lane & 7) + (lane >> 4) * 8;
    const int bc0 = ((lane >> 3) & 1) * 8;

    for (int c = 0; c < nc; c++) {
        cp_wait<1>();
        __syncthreads();
        if (c + 2 < nc) issue(c + 2);

        const int stg = c % 3;
        const __half* TA = (const __half*)(smem + stg * STAGE);
        const __half* TB = (const __half*)(smem + stg * STAGE + TILE_B);

        #pragma unroll
        for (int kk = 0; kk < 32; kk += 16) {
            uint32_t a0[4][4];
            uint32_t b0[16];
            #pragma unroll
            for (int i = 0; i < 4; i++)
                ldsm4(a0[i], smem_u32(TA + (wm + i * 16 + ar) * ROWS_H + kk + ac0));
            #pragma unroll
            for (int jj = 0; jj < 4; jj++)
                ldsm4(&b0[4 * jj], smem_u32(TB + (wn + jj * 16 + br) * ROWS_H + kk + bc0));
            #pragma unroll
            for (int i = 0; i < 4; i++)
                #pragma unroll
                for (int j = 0; j < 8; j++)
                    mma16816(acc[i][j], a0[i], &b0[2 * j]);
        }
    }

    const float* brp = bias_row ? bias_row + (size_t)bz * brs : nullptr;
    const float* bcp = bias_col ? bias_col + (size_t)bz * bcs : nullptr;
    const int g  = lane >> 2;
    const int t2 = (lane & 3) * 2;
    #pragma unroll
    for (int i = 0; i < 4; i++) {
        const int m = m0 + wm + i * 16 + g;
        const float br0 = brp ? brp[m] : 0.f;
        const float br1 = brp ? brp[m + 8] : 0.f;
        #pragma unroll
        for (int j = 0; j < 8; j++) {
            const int n = n0 + wn + j * 8 + t2;
            float bc0v = 0.f, bc1v = 0.f;
            if (bcp) { bc0v = bcp[n]; bc1v = bcp[n + 1]; }
            float v0 = acc[i][j][0] * alpha + br0 + bc0v;
            float v1 = acc[i][j][1] * alpha + br0 + bc1v;
            float v2 = acc[i][j][2] * alpha + br1 + bc0v;
            float v3 = acc[i][j][3] * alpha + br1 + bc1v;
            if (resid) {
                const float* rp = resid + (size_t)bz * sR;
                v0 += rp[(size_t)m * N + n];
                v1 += rp[(size_t)m * N + n + 1];
                v2 += rp[(size_t)(m + 8) * N + n];
                v3 += rp[(size_t)(m + 8) * N + n + 1];
            }
            if (OM == 0) {
                float* C = (float*)C0 + (size_t)bz * sC;
                float2 o0; o0.x = v0; o0.y = v1;
                float2 o1; o1.x = v2; o1.y = v3;
                *(float2*)&C[(size_t)m * N + n] = o0;
                *(float2*)&C[(size_t)(m + 8) * N + n] = o1;
            } else {
                __half* Ch = (__half*)C0 + (size_t)bz * sC;
                __half2 h01 = __floats2half2_rn(v0, v1);
                __half2 h23 = __floats2half2_rn(v2, v3);
                *(__half2*)&Ch[(size_t)m * N + n] = h01;
                *(__half2*)&Ch[(size_t)(m + 8) * N + n] = h23;
            }
        }
    }
}

// ---------------------------------------------------------------------------
// Launch: weight-prep fork + dual batch-split chains (A: b0-15, B: b16-31)
// ---------------------------------------------------------------------------
extern "C" void kernel_launch(void* const* d_in, const int* in_sizes, int n_in,
                              void* d_out, int out_size)
{
    (void)in_sizes; (void)n_in; (void)out_size;
    const float* x    = (const float*)d_in[0];
    const float* gn_w = (const float*)d_in[1];
    const float* gn_b = (const float*)d_in[2];
    const float* wq   = (const float*)d_in[3];
    const float* bq   = (const float*)d_in[4];
    const float* wk   = (const float*)d_in[5];
    const float* bk   = (const float*)d_in[6];
    const float* wv   = (const float*)d_in[7];
    const float* bv   = (const float*)d_in[8];
    const float* wp   = (const float*)d_in[9];
    const float* bp   = (const float*)d_in[10];
    float* out = (float*)d_out;

    __half *Hn, *Hc, *U, *G, *P, *S, *Wah, *Wal, *Th, *W2h;
    float *TW, *rq, *rk, *cvec;
    cudaGetSymbolAddress((void**)&Hn, g_Hn);
    cudaGetSymbolAddress((void**)&Hc, g_Hc);
    cudaGetSymbolAddress((void**)&U,  g_U);
    cudaGetSymbolAddress((void**)&G,  g_G);
    cudaGetSymbolAddress((void**)&P,  g_P);
    cudaGetSymbolAddress((void**)&S,  g_S);
    cudaGetSymbolAddress((void**)&Wah, g_Wah); cudaGetSymbolAddress((void**)&Wal, g_Wal);
    cudaGetSymbolAddress((void**)&Th, g_Th);   cudaGetSymbolAddress((void**)&W2h, g_W2h);
    cudaGetSymbolAddress((void**)&TW, g_TW);
    cudaGetSymbolAddress((void**)&rq, g_rq);   cudaGetSymbolAddress((void**)&rk, g_rk);
    cudaGetSymbolAddress((void**)&cvec, g_cvec);

    const int SMC2 = 3 * 2 * TILE_B;  // 61440
    const int SMTW = 2 * 4 * TILE_B;  // 81920
    static bool init_done = false;
    static cudaStream_t s2, s3;
    static cudaEvent_t e0, eV, e1, eGB, eB;
    if (!init_done) {
        cudaFuncSetAttribute((const void*)tw_gemm,        cudaFuncAttributeMaxDynamicSharedMemorySize, SMTW);
        cudaFuncSetAttribute((const void*)mma_gemm_c<0>,  cudaFuncAttributeMaxDynamicSharedMemorySize, SMC2);
        cudaFuncSetAttribute((const void*)mma_gemm_c<2>,  cudaFuncAttributeMaxDynamicSharedMemorySize, SMC2);
        cudaStreamCreateWithFlags(&s2, cudaStreamNonBlocking);
        cudaStreamCreateWithFlags(&s3, cudaStreamNonBlocking);
        cudaEventCreateWithFlags(&e0, cudaEventDisableTiming);
        cudaEventCreateWithFlags(&eV, cudaEventDisableTiming);
        cudaEventCreateWithFlags(&e1, cudaEventDisableTiming);
        cudaEventCreateWithFlags(&eGB, cudaEventDisableTiming);
        cudaEventCreateWithFlags(&eB, cudaEventDisableTiming);
        init_done = true;
    }

    const size_t sCN = (size_t)CH * NPIX;
    const size_t sNN = (size_t)NPIX * NPIX;
    const float scale = 0.044194173824159223f; // 512^-0.5
    const int HB = BATCH / 2;                   // 16

    // ---- fork: weight-prep chain on s2 ----
    cudaEventRecord(e0, 0);
    cudaStreamWaitEvent(s2, e0, 0);
    cudaStreamWaitEvent(s3, e0, 0);
    vecs_kernel<<<192, 256, 0, s2>>>(wq, wk, bq, bk, wp, bv, bp);
    cudaEventRecord(eV, s2);
    pack_weights_kernel<<<4096, 256, 0, s2>>>(wq, wk, wv, wp);  // also zeros TW
    {
        dim3 grid(4, 4, 8);
        tw_gemm<<<grid, 256, SMTW, s2>>>(Wah, Wal, TW);
    }
    split_tw_kernel<<<2048, 256, 0, s2>>>(scale);
    cudaEventRecord(e1, s2);

    // ---- chain B prologue on s3: GN for batches 16-31 ----
    gn_kernel<<<HB * NG, 256, 0, s3>>>(x, gn_w, gn_b, HB);
    cudaStreamWaitEvent(s3, eV, 0);
    rqk_kernel<<<HB * NPIX / 8, 256, 0, s3>>>(scale, HB);
    cudaEventRecord(eGB, s3);

    // ---- chain A on default stream: GN for batches 0-15 ----
    gn_kernel<<<HB * NG, 256>>>(x, gn_w, gn_b, 0);
    cudaStreamWaitEvent(0, eV, 0);
    rqk_kernel<<<HB * NPIX / 8, 256>>>(scale, 0);
    cudaStreamWaitEvent(0, e1, 0);     // weights ready
    cudaStreamWaitEvent(s3, e1, 0);

    // helper offsets for half B
    const size_t oCN = (size_t)HB * sCN;
    const size_t oNN = (size_t)HB * sNN;

    // ---- chain A (batches 0-15) on stream 0 ----
    {
        dim3 gU(CH / 128, NPIX / 128, HB);
        mma_gemm_c<2><<<gU, 128, SMC2>>>(Hn, Th, U,
            CH, CH, sCN, 0, sCN, nullptr, 0, nullptr, 0, nullptr, 0, 1.f);
        dim3 gS(NPIX / 128, NPIX / 128, HB);
        mma_gemm_c<2><<<gS, 128, SMC2>>>(Hn, U, S,
            NPIX, CH, sCN, sCN, sNN, rq, NPIX, rk, NPIX, nullptr, 0, 1.f);
        softmax_kernel<<<HB * NPIX / 8, 256>>>(S, P);
        dim3 gG(CH / 128, NPIX / 128, HB);
        mma_gemm_c<2><<<gG, 128, SMC2>>>(P, Hc, G,
            CH, NPIX, sNN, sCN, sCN, nullptr, 0, nullptr, 0, nullptr, 0, 1.f);
        dim3 gO(NPIX / 128, CH / 128, HB);
        mma_gemm_c<0><<<gO, 128, SMC2>>>(W2h, G, out,
            NPIX, CH, 0, sCN, sCN, cvec, 0, nullptr, 0, x, sCN, 1.f);
    }

    // ---- chain B (batches 16-31) on s3 ----
    {
        dim3 gU(CH / 128, NPIX / 128, HB);
        mma_gemm_c<2><<<gU, 128, SMC2, s3>>>(Hn + oCN, Th, U + oCN,
            CH, CH, sCN, 0, sCN, nullptr, 0, nullptr, 0, nullptr, 0, 1.f);
        dim3 gS(NPIX / 128, NPIX / 128, HB);
        mma_gemm_c<2><<<gS, 128, SMC2, s3>>>(Hn + oCN, U + oCN, S + oNN,
            NPIX, CH, sCN, sCN, sNN, rq + (size_t)HB * NPIX, NPIX,
            rk + (size_t)HB * NPIX, NPIX, nullptr, 0, 1.f);
        softmax_kernel<<<HB * NPIX / 8, 256, 0, s3>>>(S + oNN, P + oNN);
        dim3 gG(CH / 128, NPIX / 128, HB);
        mma_gemm_c<2><<<gG, 128, SMC2, s3>>>(P + oNN, Hc + oCN, G + oCN,
            CH, NPIX, sNN, sCN, sCN, nullptr, 0, nullptr, 0, nullptr, 0, 1.f);
        dim3 gO(NPIX / 128, CH / 128, HB);
        mma_gemm_c<0><<<gO, 128, SMC2, s3>>>(W2h, G + oCN, out + (size_t)HB * sCN,
            NPIX, CH, 0, sCN, sCN, cvec, 0, nullptr, 0, x + (size_t)HB * sCN, sCN, 1.f);
        cudaEventRecord(eB, s3);
    }

    // join: graph output complete only when both chains finish
    cudaStreamWaitEvent(0, eB, 0);
}